// round 6
// baseline (speedup 1.0000x reference)
#include <cuda_runtime.h>
#include <cuda_bf16.h>
#include <math.h>

#define BATCH 4
#define HW    30976            // 176*176
#define PTOT  123904           // BATCH*HW
#define NWIN  1936             // 44*44
#define PB    3964928ULL       // per-batch plane = 128*30976

// uint-unit offsets into the single scratch buffer
#define OFF_AQ    0ULL          // tiled bf16x2, K=128 (8 stages/blk)
#define OFF_AKV   7929856ULL    // tiled bf16x2, K=128
#define OFF_AO    15859712ULL   // fp32 merged-layout attention out
#define OFF_Q     31719424ULL   // packed bf16x2 [p][64]
#define OFF_KV    47579136ULL   // packed bf16x2 [p][128] (K | V)
#define OFF_X1    79298560ULL   // fp32 NCHW residual
#define OFF_X1LN  95158272ULL   // tiled bf16x2, K=128
#define OFF_YIN   103088128ULL  // packed bf16x2 [p][512]
#define OFF_YG    166526976ULL  // packed bf16x2 [p][256]
#define OFF_WB    198246400ULL
#define TOT_U     198369280ULL

__device__ unsigned g_u[TOT_U];

// ---------------------------------------------------------------------------
// helpers
// ---------------------------------------------------------------------------
__device__ __forceinline__ unsigned pk(float lo, float hi) {
    unsigned r;
    asm("cvt.rn.bf16x2.f32 %0, %1, %2;" : "=r"(r) : "f"(hi), "f"(lo));
    return r;
}
__device__ __forceinline__ float2 bf2f(unsigned u) {
    __nv_bfloat162 h = *reinterpret_cast<__nv_bfloat162*>(&u);
    return __bfloat1622float2(h);
}
__device__ __forceinline__ void mma16(float* d, const unsigned* a, const unsigned* b) {
    asm volatile(
        "mma.sync.aligned.m16n8k16.row.col.f32.bf16.bf16.f32 "
        "{%0,%1,%2,%3},{%4,%5,%6,%7},{%8,%9},{%0,%1,%2,%3};"
        : "+f"(d[0]), "+f"(d[1]), "+f"(d[2]), "+f"(d[3])
        : "r"(a[0]), "r"(a[1]), "r"(a[2]), "r"(a[3]), "r"(b[0]), "r"(b[1]));
}
__device__ __forceinline__ void ldsm4(unsigned& r0, unsigned& r1, unsigned& r2, unsigned& r3, unsigned a) {
    asm volatile("ldmatrix.sync.aligned.m8n8.x4.shared.b16 {%0,%1,%2,%3}, [%4];"
        : "=r"(r0), "=r"(r1), "=r"(r2), "=r"(r3) : "r"(a));
}
__device__ __forceinline__ void cpa16(unsigned d, const void* s) {
    asm volatile("cp.async.cg.shared.global [%0], [%1], 16;" :: "r"(d), "l"(s));
}
#define CP_COMMIT() asm volatile("cp.async.commit_group;" ::: "memory")
#define CP_WAIT2()  asm volatile("cp.async.wait_group 2;" ::: "memory")

// ---------------------------------------------------------------------------
// K0: weight prep -> packed bf16x2 in GEMM-tiled layout.
// WB: WqP[8192] | WKVP[16384] | WinP[65536] | WoutP[32768]
// ---------------------------------------------------------------------------
__global__ void k_wprep(const float* __restrict__ Wq, const float* __restrict__ Wk,
                        const float* __restrict__ Wv, const float* __restrict__ win,
                        const float* __restrict__ wout)
{
    int idx = blockIdx.x * 256 + threadIdx.x;
    if (idx >= 122880) return;
    unsigned* WB = g_u + OFF_WB;
    if (idx < 8192) {
        int n = idx >> 6, kp = idx & 63;
        WB[(kp >> 3) * 1024 + n * 8 + (kp & 7)] = pk(Wq[n * 128 + 2 * kp], Wq[n * 128 + 2 * kp + 1]);
    } else if (idx < 24576) {
        int j = idx - 8192; int n2 = j >> 6, kp = j & 63;
        const float* W = (n2 < 128) ? Wk : Wv;
        int n = n2 & 127;
        WB[8192 + (n2 >> 7) * 8192 + (kp >> 3) * 1024 + n * 8 + (kp & 7)]
            = pk(W[n * 128 + 2 * kp], W[n * 128 + 2 * kp + 1]);
    } else if (idx < 90112) {
        int j = idx - 24576; int n = j >> 6, kp = j & 63;
        WB[24576 + (n >> 7) * 8192 + (kp >> 3) * 1024 + (n & 127) * 8 + (kp & 7)]
            = pk(win[n * 128 + 2 * kp], win[n * 128 + 2 * kp + 1]);
    } else {
        int j = idx - 90112; int n = j >> 8, kp = j & 255;
        WB[90112 + (kp >> 3) * 1024 + n * 8 + (kp & 7)]
            = pk(wout[n * 512 + 2 * kp], wout[n * 512 + 2 * kp + 1]);
    }
}

// ---------------------------------------------------------------------------
// K1: LN1(x), bilinear mask/edge upsample -> tiled Aq / Akv (uint4 stores).
// ---------------------------------------------------------------------------
__global__ void __launch_bounds__(256) k_prep(
    const float* __restrict__ x, const float* __restrict__ mask,
    const float* __restrict__ edge, const float* __restrict__ ln1w,
    const float* __restrict__ ln1b)
{
    __shared__ float xs[128 * 33];
    __shared__ float red[264], red2[264];
    __shared__ float ms[32], mu_s[32], rs_s[32];
    __shared__ int   cy0[32], cy1[32], cx0[32], cx1[32];
    __shared__ float cwy[32], cwx[32];
    __shared__ float w1s[128], b1s[128];

    int p0 = blockIdx.x * 32;
    int b = p0 / HW, hw0 = p0 % HW;
    const float* xb = x + (size_t)b * PB;
    if (threadIdx.x < 128) { w1s[threadIdx.x] = ln1w[threadIdx.x]; b1s[threadIdx.x] = ln1b[threadIdx.x]; }

    for (int e = threadIdx.x; e < 4096; e += 256) {
        int c = e >> 5, px = e & 31;
        xs[c * 33 + px] = xb[(size_t)c * HW + hw0 + px];
    }
    if (threadIdx.x < 32) {
        int px = threadIdx.x;
        int hw = hw0 + px;
        int h2 = hw / 176, w2 = hw % 176;
        float fy = 0.25f * h2 - 0.375f; int iy = (int)floorf(fy); float ty = fy - iy;
        float fx = 0.25f * w2 - 0.375f; int ix = (int)floorf(fx); float tx = fx - ix;
        int y0 = iy < 0 ? 0 : iy, y1 = (iy + 1 > 43) ? 43 : iy + 1;
        int x0 = ix < 0 ? 0 : ix, x1 = (ix + 1 > 43) ? 43 : ix + 1;
        cy0[px] = y0; cy1[px] = y1; cx0[px] = x0; cx1[px] = x1;
        cwy[px] = ty; cwx[px] = tx;
        const float* mb = mask + b * NWIN;
        ms[px] = (1.f - ty) * ((1.f - tx) * mb[y0 * 44 + x0] + tx * mb[y0 * 44 + x1])
               +        ty  * ((1.f - tx) * mb[y1 * 44 + x0] + tx * mb[y1 * 44 + x1]);
    }
    __syncthreads();
    {
        int px = threadIdx.x & 31, j = threadIdx.x >> 5;
        float s = 0.f, s2 = 0.f;
        #pragma unroll
        for (int i = 0; i < 16; i++) {
            float v = xs[(j * 16 + i) * 33 + px];
            s += v; s2 += v * v;
        }
        red[j * 33 + px] = s; red2[j * 33 + px] = s2;
    }
    __syncthreads();
    if (threadIdx.x < 32) {
        int px = threadIdx.x; float s = 0.f, s2 = 0.f;
        #pragma unroll
        for (int j = 0; j < 8; j++) { s += red[j * 33 + px]; s2 += red2[j * 33 + px]; }
        float mu = s * (1.f / 128.f);
        float var = s2 * (1.f / 128.f) - mu * mu;
        mu_s[px] = mu; rs_s[px] = rsqrtf(var + 1e-5f);
    }
    __syncthreads();

    int px = threadIdx.x & 31, j = threadIdx.x >> 5;   // j = stage 0..7
    int p = p0 + px;
    size_t tbase = (size_t)(p >> 7) * 8192 + (size_t)j * 1024 + (size_t)(p & 127) * 8;
    {
        float mu = mu_s[px], rs = rs_s[px], m = ms[px];
        unsigned q[8];
        #pragma unroll
        for (int ii = 0; ii < 8; ii++) {
            int c = j * 16 + 2 * ii;
            float v0 = ((xs[c * 33 + px] - mu) * rs * w1s[c] + b1s[c]) * m;
            float v1 = ((xs[(c + 1) * 33 + px] - mu) * rs * w1s[c + 1] + b1s[c + 1]) * m;
            q[ii] = pk(v0, v1);
        }
        uint4* dst = (uint4*)(g_u + OFF_AKV + tbase);
        dst[0] = make_uint4(q[0], q[1], q[2], q[3]);
        dst[1] = make_uint4(q[4], q[5], q[6], q[7]);
    }
    __syncthreads();
    for (int e = threadIdx.x; e < 4096; e += 256) {
        int c = e >> 5, px2 = e & 31;
        const float* eb = edge + ((size_t)b * 128 + c) * NWIN;
        float ty = cwy[px2], tx = cwx[px2];
        float v = (1.f - ty) * ((1.f - tx) * eb[cy0[px2] * 44 + cx0[px2]] + tx * eb[cy0[px2] * 44 + cx1[px2]])
                +        ty  * ((1.f - tx) * eb[cy1[px2] * 44 + cx0[px2]] + tx * eb[cy1[px2] * 44 + cx1[px2]]);
        xs[c * 33 + px2] = v;
    }
    __syncthreads();
    {
        unsigned q[8];
        #pragma unroll
        for (int ii = 0; ii < 8; ii++) {
            int c = j * 16 + 2 * ii;
            q[ii] = pk(xs[c * 33 + px], xs[(c + 1) * 33 + px]);
        }
        uint4* dst = (uint4*)(g_u + OFF_AQ + tbase);
        dst[0] = make_uint4(q[0], q[1], q[2], q[3]);
        dst[1] = make_uint4(q[4], q[5], q[6], q[7]);
    }
}

// ---------------------------------------------------------------------------
// K2: bf16 MMA GEMM, cp.async 4-deep pipeline + ldmatrix + internal NY loop.
// A cycles every NSTAGE stages (L1/L2 reuse); B streams contiguously.
// ASRC=0: A tiled.  ASRC=1: A rows [m][256] (K=512).
// EPI=1: packed bf16x2 C [M][Nd/2].  EPI=2: fp32 + residual -> NCHW outp.
// ---------------------------------------------------------------------------
template<int NSTAGE, int NY, int ASRC, int EPI>
__global__ void __launch_bounds__(256, 2) k_mma_t(
    const unsigned* __restrict__ At, const unsigned* __restrict__ Bt,
    unsigned* __restrict__ Cu, int Nd, float* __restrict__ outp)
{
    const int NT = NSTAGE * NY;
    __shared__ unsigned sm[4 * 2048];
    int tid = threadIdx.x, lane = tid & 31, warp = tid >> 5;
    int wm = warp >> 2, wn = warp & 3, t = lane & 3, g = lane >> 2;
    const unsigned* Ab;
    if (ASRC == 0) Ab = At + (size_t)blockIdx.x * (NSTAGE * 1024) + tid * 4;
    else           Ab = At + ((size_t)blockIdx.x * 128 + (tid >> 1)) * 256 + (tid & 1) * 4;
    const unsigned* Bb = Bt + tid * 4;
    unsigned smb = (unsigned)__cvta_generic_to_shared(sm);

    // cp.async dst (swizzled 16B rows)
    int m_ = tid >> 1, q = tid & 1;
    unsigned dA = smb + (unsigned)(2 * m_ + (q ^ ((m_ >> 2) & 1))) * 16;
    unsigned dB = dA + 4096;

    // ldmatrix fragment addresses (stage-buffer relative)
    int itemA = wm * 64 + (lane & 15);
    int khA = lane >> 4;
    unsigned aAddr = smb + (unsigned)(2 * itemA + (khA ^ ((itemA >> 2) & 1))) * 16;
    int itemB = wn * 32 + lane;
    int bbit = (itemB >> 2) & 1;
    unsigned bAddr0 = smb + 4096u + (unsigned)(2 * itemB + bbit) * 16;
    unsigned bAddr1 = smb + 4096u + (unsigned)(2 * itemB + (1 ^ bbit)) * 16;

    float acc[4][4][4];
    #pragma unroll
    for (int i = 0; i < 4; i++)
        #pragma unroll
        for (int j = 0; j < 4; j++)
            #pragma unroll
            for (int k = 0; k < 4; k++) acc[i][j][k] = 0.f;

    #pragma unroll
    for (int s = 0; s < 3; s++) {
        unsigned off = s * 8192u;
        cpa16(dA + off, Ab + (ASRC == 0 ? (s & (NSTAGE - 1)) * 1024 : s * 8));
        cpa16(dB + off, Bb + s * 1024);
        CP_COMMIT();
    }

    #pragma unroll 8
    for (int s = 0; s < NT; s++) {
        CP_WAIT2();
        __syncthreads();
        unsigned buf = (unsigned)(s & 3) * 8192u;
        unsigned af[4][4], bf[4][2];
        ldsm4(bf[0][0], bf[1][0], bf[2][0], bf[3][0], bAddr0 + buf);
        ldsm4(bf[0][1], bf[1][1], bf[2][1], bf[3][1], bAddr1 + buf);
        #pragma unroll
        for (int tm = 0; tm < 4; tm++)
            ldsm4(af[tm][0], af[tm][1], af[tm][2], af[tm][3], aAddr + buf + tm * 512u);
        #pragma unroll
        for (int tm = 0; tm < 4; tm++)
            #pragma unroll
            for (int tn = 0; tn < 4; tn++)
                mma16(acc[tm][tn], af[tm], bf[tn]);
        if (s + 3 < NT) {
            unsigned off = (unsigned)((s + 3) & 3) * 8192u;
            cpa16(dA + off, Ab + (ASRC == 0 ? ((s + 3) & (NSTAGE - 1)) * 1024 : (s + 3) * 8));
            cpa16(dB + off, Bb + (s + 3) * 1024);
            CP_COMMIT();
        }
        if ((s & (NSTAGE - 1)) == NSTAGE - 1) {
            int ny = s / NSTAGE;
            int m0 = blockIdx.x * 128;
            int n0 = (NY > 1 ? ny : (int)blockIdx.y) * 128;
            if (EPI == 1) {
                int np = Nd >> 1;
                #pragma unroll
                for (int tm = 0; tm < 4; tm++)
                    #pragma unroll
                    for (int tn = 0; tn < 4; tn++) {
                        int m = m0 + wm * 64 + tm * 16 + g;
                        int n = n0 + wn * 32 + tn * 8 + 2 * t;
                        Cu[(size_t)m * np + (n >> 1)] = pk(acc[tm][tn][0], acc[tm][tn][1]);
                        Cu[(size_t)(m + 8) * np + (n >> 1)] = pk(acc[tm][tn][2], acc[tm][tn][3]);
                    }
            } else {
                const float* x1 = (const float*)(g_u + OFF_X1);
                int b = m0 / HW, hw0 = m0 % HW;
                #pragma unroll
                for (int tm = 0; tm < 4; tm++)
                    #pragma unroll
                    for (int tn = 0; tn < 4; tn++) {
                        int mrow = wm * 64 + tm * 16 + g;
                        int n = wn * 32 + tn * 8 + 2 * t;
                        size_t a0 = ((size_t)b * 128 + n) * HW + hw0 + mrow;
                        outp[a0]          = x1[a0] + acc[tm][tn][0];
                        outp[a0 + HW]     = x1[a0 + HW] + acc[tm][tn][1];
                        outp[a0 + 8]      = x1[a0 + 8] + acc[tm][tn][2];
                        outp[a0 + HW + 8] = x1[a0 + HW + 8] + acc[tm][tn][3];
                    }
            }
            if (s + 1 < NT) {
                #pragma unroll
                for (int i = 0; i < 4; i++)
                    #pragma unroll
                    for (int j = 0; j < 4; j++)
                        #pragma unroll
                        for (int k = 0; k < 4; k++) acc[i][j][k] = 0.f;
            }
        }
    }
}

// ---------------------------------------------------------------------------
// K3: per-(window,token) channel attention. Q/KV packed bf16 -> AO fp32.
// ---------------------------------------------------------------------------
__global__ void __launch_bounds__(256) k_attn()
{
    __shared__ float outs[32 * 129];
    __shared__ float buf[8 * 640];
    int bid = blockIdx.x;
    int chunk = bid % 61;
    int n = (bid / 61) % 16;
    int b = bid / (61 * 16);
    int ihw0 = chunk * 32;
    const unsigned* Qp  = g_u + OFF_Q;
    const unsigned* KVp = g_u + OFF_KV;
    float* AO = (float*)(g_u + OFF_AO);
    int warp = threadIdx.x >> 5, lane = threadIdx.x & 31;
    float* qs = buf + warp * 640;
    float* ks = qs + 128;
    float* vs = qs + 256;
    float* ds = qs + 384;

    for (int it = 0; it < 4; it++) {
        int g = it * 8 + warp;
        int ihw = ihw0 + g;
        if (ihw < NWIN) {
            int ih = ihw / 44, iw = ihw % 44;
            int h2 = ih * 4 + (n >> 2), w2 = iw * 4 + (n & 3);
            size_t p = (size_t)b * HW + (size_t)h2 * 176 + w2;
            {
                int i = lane;
                float2 vq = bf2f(Qp[p * 64 + i]);
                qs[2 * i] = vq.x; qs[2 * i + 1] = vq.y;
                float2 vq2 = bf2f(Qp[p * 64 + 32 + i]);
                qs[64 + 2 * i] = vq2.x; qs[65 + 2 * i] = vq2.y;
                float2 k1 = bf2f(KVp[p * 128 + i]);
                ks[2 * i] = k1.x; ks[2 * i + 1] = k1.y;
                float2 k2 = bf2f(KVp[p * 128 + 32 + i]);
                ks[64 + 2 * i] = k2.x; ks[65 + 2 * i] = k2.y;
                float2 v1 = bf2f(KVp[p * 128 + 64 + i]);
                vs[2 * i] = v1.x; vs[2 * i + 1] = v1.y;
                float2 v2 = bf2f(KVp[p * 128 + 96 + i]);
                vs[64 + 2 * i] = v2.x; vs[65 + 2 * i] = v2.y;
            }
            __syncwarp();
            for (int e = lane; e < 256; e += 32) {
                int j = e >> 4, kk = e & 15;
                float s = 0.f;
                #pragma unroll
                for (int i = 0; i < 8; i++) s += qs[i * 16 + j] * ks[i * 16 + kk];
                ds[e] = s * 0.25f;
            }
            __syncwarp();
            if (lane < 16) {
                float mx = -1e30f;
                #pragma unroll
                for (int kk = 0; kk < 16; kk++) mx = fmaxf(mx, ds[lane * 16 + kk]);
                float sm = 0.f;
                #pragma unroll
                for (int kk = 0; kk < 16; kk++) {
                    float ev = __expf(ds[lane * 16 + kk] - mx);
                    ds[lane * 16 + kk] = ev; sm += ev;
                }
                float inv = 1.f / sm;
                #pragma unroll
                for (int kk = 0; kk < 16; kk++) ds[lane * 16 + kk] *= inv;
            }
            __syncwarp();
            for (int ch = lane; ch < 128; ch += 32) {
                int i = ch >> 4, j = ch & 15;
                float s = 0.f;
                #pragma unroll
                for (int kk = 0; kk < 16; kk++) s += ds[j * 16 + kk] * vs[i * 16 + kk];
                outs[g * 129 + ch] = s;
            }
        }
    }
    __syncthreads();
    size_t base = ((size_t)b * 2048 + (size_t)n * 128) * 1936 + ihw0;
    for (int e = threadIdx.x; e < 4096; e += 256) {
        int ch = e >> 5, g = e & 31;
        if (ihw0 + g < NWIN)
            AO[base + (size_t)ch * 1936 + g] = outs[g * 129 + ch];
    }
}

// ---------------------------------------------------------------------------
// K4: x1 = x + AO (fp32) + LN2 applied & packed -> tiled X1LN (uint4 stores).
// ---------------------------------------------------------------------------
__global__ void __launch_bounds__(256) k_merge2(
    const float* __restrict__ x, const float* __restrict__ ln2w,
    const float* __restrict__ ln2b)
{
    __shared__ float red[264], red2[264], mu_s[32], rs_s[32];
    __shared__ float w2s[128], b2s[128];
    int p0 = blockIdx.x * 32;
    int b = p0 / HW, hw0 = p0 % HW;
    int px = threadIdx.x & 31, j = threadIdx.x >> 5;
    if (threadIdx.x < 128) { w2s[threadIdx.x] = ln2w[threadIdx.x]; b2s[threadIdx.x] = ln2b[threadIdx.x]; }
    const float* AO = (const float*)(g_u + OFF_AO);
    float* x1 = (float*)(g_u + OFF_X1);
    size_t base = (size_t)b * PB + hw0 + px;
    float v[16];
    float s = 0.f, s2 = 0.f;
    #pragma unroll
    for (int i = 0; i < 16; i++) {
        int c = j * 16 + i;
        size_t idx = base + (size_t)c * HW;
        float val = x[idx] + AO[idx];
        x1[idx] = val; v[i] = val; s += val; s2 += val * val;
    }
    red[j * 33 + px] = s; red2[j * 33 + px] = s2;
    __syncthreads();
    if (threadIdx.x < 32) {
        float ss = 0.f, ss2 = 0.f;
        #pragma unroll
        for (int j2 = 0; j2 < 8; j2++) { ss += red[j2 * 33 + threadIdx.x]; ss2 += red2[j2 * 33 + threadIdx.x]; }
        float mu = ss * (1.f / 128.f);
        float var = ss2 * (1.f / 128.f) - mu * mu;
        mu_s[threadIdx.x] = mu; rs_s[threadIdx.x] = rsqrtf(var + 1e-5f);
    }
    __syncthreads();
    float mu = mu_s[px], rs = rs_s[px];
    int p = p0 + px;
    unsigned qv[8];
    #pragma unroll
    for (int ii = 0; ii < 8; ii++) {
        int c = j * 16 + 2 * ii;
        float a = (v[2 * ii] - mu) * rs * w2s[c] + b2s[c];
        float bb = (v[2 * ii + 1] - mu) * rs * w2s[c + 1] + b2s[c + 1];
        qv[ii] = pk(a, bb);
    }
    uint4* dst = (uint4*)(g_u + OFF_X1LN + (size_t)(p >> 7) * 8192 + (size_t)j * 1024 + (size_t)(p & 127) * 8);
    dst[0] = make_uint4(qv[0], qv[1], qv[2], qv[3]);
    dst[1] = make_uint4(qv[4], qv[5], qv[6], qv[7]);
}

// ---------------------------------------------------------------------------
// K6: depthwise 3x3 + exact GELU gate, h-split x2 for occupancy.
// y_in packed [p][512] -> y_g packed [p][256].
// ---------------------------------------------------------------------------
__device__ __forceinline__ void dw_loadrow(
    const unsigned* __restrict__ yin, int b, int h, int w, int cp,
    float2* a, float2* bb)
{
    #pragma unroll
    for (int dw = 0; dw < 3; dw++) { a[dw] = make_float2(0.f, 0.f); bb[dw] = make_float2(0.f, 0.f); }
    if (h < 0 || h >= 176) return;
    #pragma unroll
    for (int dw = 0; dw < 3; dw++) {
        int ww = w + dw - 1;
        if (ww < 0 || ww >= 176) continue;
        size_t base = ((size_t)b * HW + (size_t)h * 176 + ww) * 512;
        a[dw]  = bf2f(yin[base + cp]);
        bb[dw] = bf2f(yin[base + 256 + cp]);
    }
}

__global__ void __launch_bounds__(256) k_dwconv(const float* __restrict__ wdw)
{
    int cp = threadIdx.x;
    int r = blockIdx.x;
    int hs = r & 1;
    int w = (r >> 1) % 176, b = (r >> 1) / 176;
    int h0 = hs * 88;
    const unsigned* yin = g_u + OFF_YIN;
    unsigned* yg = g_u + OFF_YG;
    int c0 = 2 * cp;
    float wa0[9], wa1[9], wb0[9], wb1[9];
    #pragma unroll
    for (int t = 0; t < 9; t++) {
        wa0[t] = __ldg(&wdw[c0 * 9 + t]);
        wa1[t] = __ldg(&wdw[(c0 + 1) * 9 + t]);
        wb0[t] = __ldg(&wdw[(512 + c0) * 9 + t]);
        wb1[t] = __ldg(&wdw[(513 + c0) * 9 + t]);
    }
    float2 A[3][3], B2[3][3];
    dw_loadrow(yin, b, h0 - 1, w, cp, A[0], B2[0]);
    dw_loadrow(yin, b, h0, w, cp, A[1], B2[1]);
    dw_loadrow(yin, b, h0 + 1, w, cp, A[2], B2[2]);

    for (int h = h0; h < h0 + 88; h++) {
        float a0 = 0.f, a1 = 0.f, g0 = 0.f, g1 = 0.f;
        #pragma unroll
        for (int rr = 0; rr < 3; rr++)
            #pragma unroll
            for (int cc = 0; cc < 3; cc++) {
                int t = rr * 3 + cc;
                a0 += A[rr][cc].x * wa0[t];
                a1 += A[rr][cc].y * wa1[t];
                g0 += B2[rr][cc].x * wb0[t];
                g1 += B2[rr][cc].y * wb1[t];
            }
        float e0 = 0.5f * a0 * (1.f + erff(a0 * 0.70710678118654752f));
        float e1 = 0.5f * a1 * (1.f + erff(a1 * 0.70710678118654752f));
        yg[((size_t)b * HW + (size_t)h * 176 + w) * 256 + cp] = pk(e0 * g0, e1 * g1);
        #pragma unroll
        for (int cc = 0; cc < 3; cc++) {
            A[0][cc] = A[1][cc]; A[1][cc] = A[2][cc];
            B2[0][cc] = B2[1][cc]; B2[1][cc] = B2[2][cc];
        }
        dw_loadrow(yin, b, h + 2, w, cp, A[2], B2[2]);
    }
}

// ---------------------------------------------------------------------------
extern "C" void kernel_launch(void* const* d_in, const int* in_sizes, int n_in,
                              void* d_out, int out_size)
{
    const float* x    = (const float*)d_in[0];
    const float* mask = (const float*)d_in[1];
    const float* edge = (const float*)d_in[2];
    const float* ln1w = (const float*)d_in[3];
    const float* ln1b = (const float*)d_in[4];
    const float* Wq   = (const float*)d_in[5];
    const float* Wk   = (const float*)d_in[6];
    const float* Wv   = (const float*)d_in[7];
    const float* ln2w = (const float*)d_in[8];
    const float* ln2b = (const float*)d_in[9];
    const float* w_in = (const float*)d_in[10];
    const float* w_dw = (const float*)d_in[11];
    const float* w_out= (const float*)d_in[12];
    float* outp = (float*)d_out;

    unsigned* G = nullptr;
    cudaGetSymbolAddress((void**)&G, g_u);

    // K0: weights -> tiled packed bf16x2
    k_wprep<<<(122880 + 255) / 256, 256>>>(Wq, Wk, Wv, w_in, w_out);

    // K1: LN1 + resize -> tiled Aq/Akv
    k_prep<<<PTOT / 32, 256>>>(x, mask, edge, ln1w, ln1b);

    // K2: Q GEMM (NY=1), fused KV GEMM (NY=2, internal loop)
    k_mma_t<8, 1, 0, 1><<<PTOT / 128, 256>>>(G + OFF_AQ,  G + OFF_WB,        G + OFF_Q,  128, nullptr);
    k_mma_t<8, 2, 0, 1><<<PTOT / 128, 256>>>(G + OFF_AKV, G + OFF_WB + 8192, G + OFF_KV, 256, nullptr);

    // K3: channel attention -> AO (merged layout, fp32)
    k_attn<<<4 * 16 * 61, 256>>>();

    // K4: x1 = x + AO, LN2 applied & packed -> tiled X1LN
    k_merge2<<<PTOT / 32, 256>>>(x, ln2w, ln2b);

    // K5: conv1x1 128->1024, NY=8 internal loop (A read once) -> y_in
    k_mma_t<8, 8, 0, 1><<<PTOT / 128, 256>>>(G + OFF_X1LN, G + OFF_WB + 24576, G + OFF_YIN, 1024, nullptr);

    // K6: depthwise 3x3 + GELU gate -> y_g packed rows (h-split x2)
    k_dwconv<<<BATCH * 176 * 2, 256>>>(w_dw);

    // K7: conv1x1 512->128 + residual -> d_out (NCHW), A from rows
    k_mma_t<32, 1, 1, 2><<<PTOT / 128, 256>>>(G + OFF_YG, G + OFF_WB + 90112, nullptr, 128, outp);
}

// round 7
// speedup vs baseline: 1.0421x; 1.0421x over previous
#include <cuda_runtime.h>
#include <cuda_bf16.h>
#include <math.h>

#define BATCH 4
#define HW    30976            // 176*176
#define PTOT  123904           // BATCH*HW
#define NWIN  1936             // 44*44
#define PB    3964928ULL       // per-batch plane = 128*30976

// uint-unit offsets into the single scratch buffer
#define OFF_AQ    0ULL          // tiled bf16x2, K=128 (8 stages/blk)
#define OFF_AKV   7929856ULL    // tiled bf16x2, K=128
#define OFF_AO    15859712ULL   // fp32 merged-layout attention out
#define OFF_Q     31719424ULL   // packed bf16x2 [p][64]
#define OFF_KV    47579136ULL   // packed bf16x2 [p][128] (K | V)
#define OFF_X1    79298560ULL   // fp32 NCHW residual
#define OFF_X1LN  95158272ULL   // tiled bf16x2, K=128
#define OFF_YIN   103088128ULL  // packed bf16x2 [p][512]
#define OFF_YG    166526976ULL  // packed bf16x2 [p][256]
#define OFF_WB    198246400ULL
#define TOT_U     198369280ULL

__device__ unsigned g_u[TOT_U];

// ---------------------------------------------------------------------------
// helpers
// ---------------------------------------------------------------------------
__device__ __forceinline__ unsigned pk(float lo, float hi) {
    unsigned r;
    asm("cvt.rn.bf16x2.f32 %0, %1, %2;" : "=r"(r) : "f"(hi), "f"(lo));
    return r;
}
__device__ __forceinline__ float2 bf2f(unsigned u) {
    __nv_bfloat162 h = *reinterpret_cast<__nv_bfloat162*>(&u);
    return __bfloat1622float2(h);
}
__device__ __forceinline__ void mma16(float* d, const unsigned* a, const unsigned* b) {
    asm volatile(
        "mma.sync.aligned.m16n8k16.row.col.f32.bf16.bf16.f32 "
        "{%0,%1,%2,%3},{%4,%5,%6,%7},{%8,%9},{%0,%1,%2,%3};"
        : "+f"(d[0]), "+f"(d[1]), "+f"(d[2]), "+f"(d[3])
        : "r"(a[0]), "r"(a[1]), "r"(a[2]), "r"(a[3]), "r"(b[0]), "r"(b[1]));
}
__device__ __forceinline__ void ldsm4(unsigned& r0, unsigned& r1, unsigned& r2, unsigned& r3, unsigned a) {
    asm volatile("ldmatrix.sync.aligned.m8n8.x4.shared.b16 {%0,%1,%2,%3}, [%4];"
        : "=r"(r0), "=r"(r1), "=r"(r2), "=r"(r3) : "r"(a));
}
__device__ __forceinline__ void cpa16(unsigned d, const void* s) {
    asm volatile("cp.async.cg.shared.global [%0], [%1], 16;" :: "r"(d), "l"(s));
}
#define CP_COMMIT() asm volatile("cp.async.commit_group;" ::: "memory")
#define CP_WAIT1()  asm volatile("cp.async.wait_group 1;" ::: "memory")
#define CP_WAIT0()  asm volatile("cp.async.wait_group 0;" ::: "memory")

// ---------------------------------------------------------------------------
// K0: weight prep -> packed bf16x2 in GEMM-tiled layout.
// WB: WqP[8192] | WKVP[16384] | WinP[65536] | WoutP[32768]
// ---------------------------------------------------------------------------
__global__ void k_wprep(const float* __restrict__ Wq, const float* __restrict__ Wk,
                        const float* __restrict__ Wv, const float* __restrict__ win,
                        const float* __restrict__ wout)
{
    int idx = blockIdx.x * 256 + threadIdx.x;
    if (idx >= 122880) return;
    unsigned* WB = g_u + OFF_WB;
    if (idx < 8192) {
        int n = idx >> 6, kp = idx & 63;
        WB[(kp >> 3) * 1024 + n * 8 + (kp & 7)] = pk(Wq[n * 128 + 2 * kp], Wq[n * 128 + 2 * kp + 1]);
    } else if (idx < 24576) {
        int j = idx - 8192; int n2 = j >> 6, kp = j & 63;
        const float* W = (n2 < 128) ? Wk : Wv;
        int n = n2 & 127;
        WB[8192 + (n2 >> 7) * 8192 + (kp >> 3) * 1024 + n * 8 + (kp & 7)]
            = pk(W[n * 128 + 2 * kp], W[n * 128 + 2 * kp + 1]);
    } else if (idx < 90112) {
        int j = idx - 24576; int n = j >> 6, kp = j & 63;
        WB[24576 + (n >> 7) * 8192 + (kp >> 3) * 1024 + (n & 127) * 8 + (kp & 7)]
            = pk(win[n * 128 + 2 * kp], win[n * 128 + 2 * kp + 1]);
    } else {
        int j = idx - 90112; int n = j >> 8, kp = j & 255;
        WB[90112 + (kp >> 3) * 1024 + n * 8 + (kp & 7)]
            = pk(wout[n * 512 + 2 * kp], wout[n * 512 + 2 * kp + 1]);
    }
}

// ---------------------------------------------------------------------------
// K1: LN1(x), bilinear mask/edge upsample -> tiled Aq / Akv (uint4 stores).
// ---------------------------------------------------------------------------
__global__ void __launch_bounds__(256) k_prep(
    const float* __restrict__ x, const float* __restrict__ mask,
    const float* __restrict__ edge, const float* __restrict__ ln1w,
    const float* __restrict__ ln1b)
{
    __shared__ float xs[128 * 33];
    __shared__ float red[264], red2[264];
    __shared__ float ms[32], mu_s[32], rs_s[32];
    __shared__ int   cy0[32], cy1[32], cx0[32], cx1[32];
    __shared__ float cwy[32], cwx[32];
    __shared__ float w1s[128], b1s[128];

    int p0 = blockIdx.x * 32;
    int b = p0 / HW, hw0 = p0 % HW;
    const float* xb = x + (size_t)b * PB;
    if (threadIdx.x < 128) { w1s[threadIdx.x] = ln1w[threadIdx.x]; b1s[threadIdx.x] = ln1b[threadIdx.x]; }

    for (int e = threadIdx.x; e < 4096; e += 256) {
        int c = e >> 5, px = e & 31;
        xs[c * 33 + px] = xb[(size_t)c * HW + hw0 + px];
    }
    if (threadIdx.x < 32) {
        int px = threadIdx.x;
        int hw = hw0 + px;
        int h2 = hw / 176, w2 = hw % 176;
        float fy = 0.25f * h2 - 0.375f; int iy = (int)floorf(fy); float ty = fy - iy;
        float fx = 0.25f * w2 - 0.375f; int ix = (int)floorf(fx); float tx = fx - ix;
        int y0 = iy < 0 ? 0 : iy, y1 = (iy + 1 > 43) ? 43 : iy + 1;
        int x0 = ix < 0 ? 0 : ix, x1 = (ix + 1 > 43) ? 43 : ix + 1;
        cy0[px] = y0; cy1[px] = y1; cx0[px] = x0; cx1[px] = x1;
        cwy[px] = ty; cwx[px] = tx;
        const float* mb = mask + b * NWIN;
        ms[px] = (1.f - ty) * ((1.f - tx) * mb[y0 * 44 + x0] + tx * mb[y0 * 44 + x1])
               +        ty  * ((1.f - tx) * mb[y1 * 44 + x0] + tx * mb[y1 * 44 + x1]);
    }
    __syncthreads();
    {
        int px = threadIdx.x & 31, j = threadIdx.x >> 5;
        float s = 0.f, s2 = 0.f;
        #pragma unroll
        for (int i = 0; i < 16; i++) {
            float v = xs[(j * 16 + i) * 33 + px];
            s += v; s2 += v * v;
        }
        red[j * 33 + px] = s; red2[j * 33 + px] = s2;
    }
    __syncthreads();
    if (threadIdx.x < 32) {
        int px = threadIdx.x; float s = 0.f, s2 = 0.f;
        #pragma unroll
        for (int j = 0; j < 8; j++) { s += red[j * 33 + px]; s2 += red2[j * 33 + px]; }
        float mu = s * (1.f / 128.f);
        float var = s2 * (1.f / 128.f) - mu * mu;
        mu_s[px] = mu; rs_s[px] = rsqrtf(var + 1e-5f);
    }
    __syncthreads();

    int px = threadIdx.x & 31, j = threadIdx.x >> 5;   // j = stage 0..7
    int p = p0 + px;
    size_t tbase = (size_t)(p >> 7) * 8192 + (size_t)j * 1024 + (size_t)(p & 127) * 8;
    {
        float mu = mu_s[px], rs = rs_s[px], m = ms[px];
        unsigned q[8];
        #pragma unroll
        for (int ii = 0; ii < 8; ii++) {
            int c = j * 16 + 2 * ii;
            float v0 = ((xs[c * 33 + px] - mu) * rs * w1s[c] + b1s[c]) * m;
            float v1 = ((xs[(c + 1) * 33 + px] - mu) * rs * w1s[c + 1] + b1s[c + 1]) * m;
            q[ii] = pk(v0, v1);
        }
        uint4* dst = (uint4*)(g_u + OFF_AKV + tbase);
        dst[0] = make_uint4(q[0], q[1], q[2], q[3]);
        dst[1] = make_uint4(q[4], q[5], q[6], q[7]);
    }
    __syncthreads();
    for (int e = threadIdx.x; e < 4096; e += 256) {
        int c = e >> 5, px2 = e & 31;
        const float* eb = edge + ((size_t)b * 128 + c) * NWIN;
        float ty = cwy[px2], tx = cwx[px2];
        float v = (1.f - ty) * ((1.f - tx) * eb[cy0[px2] * 44 + cx0[px2]] + tx * eb[cy0[px2] * 44 + cx1[px2]])
                +        ty  * ((1.f - tx) * eb[cy1[px2] * 44 + cx0[px2]] + tx * eb[cy1[px2] * 44 + cx1[px2]]);
        xs[c * 33 + px2] = v;
    }
    __syncthreads();
    {
        unsigned q[8];
        #pragma unroll
        for (int ii = 0; ii < 8; ii++) {
            int c = j * 16 + 2 * ii;
            q[ii] = pk(xs[c * 33 + px], xs[(c + 1) * 33 + px]);
        }
        uint4* dst = (uint4*)(g_u + OFF_AQ + tbase);
        dst[0] = make_uint4(q[0], q[1], q[2], q[3]);
        dst[1] = make_uint4(q[4], q[5], q[6], q[7]);
    }
}

// ---------------------------------------------------------------------------
// K2: bf16 MMA GEMM, cp.async 3-stage pipeline + ldmatrix (R5-proven core).
// SWAP=1: m-block = blockIdx.y, n-block = blockIdx.x (launch-order A reuse).
// ASRC=0: A tiled.  ASRC=1: A rows [m][256] (K=512).
// EPI=1: packed bf16x2 C [M][Nd/2].  EPI=2: fp32 + residual -> NCHW outp.
// ---------------------------------------------------------------------------
template<int NSTAGE, int ASRC, int EPI, int SWAP>
__global__ void __launch_bounds__(256, 2) k_mma_t(
    const unsigned* __restrict__ At, const unsigned* __restrict__ Bt,
    unsigned* __restrict__ Cu, int Nd, float* __restrict__ outp)
{
    __shared__ unsigned sm[3 * 2048];
    int tid = threadIdx.x, lane = tid & 31, warp = tid >> 5;
    int wm = warp >> 2, wn = warp & 3, t = lane & 3, g = lane >> 2;
    int mb = SWAP ? blockIdx.y : blockIdx.x;
    int nb = SWAP ? blockIdx.x : blockIdx.y;
    const unsigned* Ab;
    if (ASRC == 0) Ab = At + (size_t)mb * (NSTAGE * 1024) + tid * 4;
    else           Ab = At + ((size_t)mb * 128 + (tid >> 1)) * 256 + (tid & 1) * 4;
    const unsigned* Bb = Bt + (size_t)nb * (NSTAGE * 1024) + tid * 4;
    unsigned smb = (unsigned)__cvta_generic_to_shared(sm);

    // cp.async dst (swizzled 16B rows)
    int m_ = tid >> 1, q = tid & 1;
    unsigned dA = smb + (unsigned)(2 * m_ + (q ^ ((m_ >> 2) & 1))) * 16;
    unsigned dB = dA + 4096;

    // ldmatrix fragment addresses (stage-buffer relative)
    int itemA = wm * 64 + (lane & 15);
    int khA = lane >> 4;
    unsigned aAddr = smb + (unsigned)(2 * itemA + (khA ^ ((itemA >> 2) & 1))) * 16;
    int itemB = wn * 32 + lane;
    int bbit = (itemB >> 2) & 1;
    unsigned bAddr0 = smb + 4096u + (unsigned)(2 * itemB + bbit) * 16;
    unsigned bAddr1 = smb + 4096u + (unsigned)(2 * itemB + (1 ^ bbit)) * 16;

    float acc[4][4][4];
    #pragma unroll
    for (int i = 0; i < 4; i++)
        #pragma unroll
        for (int j = 0; j < 4; j++)
            #pragma unroll
            for (int k = 0; k < 4; k++) acc[i][j][k] = 0.f;

    #pragma unroll
    for (int s = 0; s < 2; s++) {
        unsigned off = s * 8192u;
        cpa16(dA + off, Ab + (ASRC == 0 ? s * 1024 : s * 8));
        cpa16(dB + off, Bb + s * 1024);
        CP_COMMIT();
    }

    for (int s = 0; s < NSTAGE; s++) {
        if (s + 1 < NSTAGE) CP_WAIT1(); else CP_WAIT0();
        __syncthreads();
        unsigned buf = (unsigned)(s % 3) * 8192u;
        unsigned af[4][4], bf[4][2];
        ldsm4(bf[0][0], bf[1][0], bf[2][0], bf[3][0], bAddr0 + buf);
        ldsm4(bf[0][1], bf[1][1], bf[2][1], bf[3][1], bAddr1 + buf);
        #pragma unroll
        for (int tm = 0; tm < 4; tm++)
            ldsm4(af[tm][0], af[tm][1], af[tm][2], af[tm][3], aAddr + buf + tm * 512u);
        #pragma unroll
        for (int tm = 0; tm < 4; tm++)
            #pragma unroll
            for (int tn = 0; tn < 4; tn++)
                mma16(acc[tm][tn], af[tm], bf[tn]);
        if (s + 2 < NSTAGE) {
            unsigned off = (unsigned)((s + 2) % 3) * 8192u;
            cpa16(dA + off, Ab + (ASRC == 0 ? (s + 2) * 1024 : (s + 2) * 8));
            cpa16(dB + off, Bb + (s + 2) * 1024);
            CP_COMMIT();
        }
        __syncthreads();
    }

    int m0 = mb * 128, n0 = nb * 128;
    if (EPI == 1) {
        int np = Nd >> 1;
        #pragma unroll
        for (int tm = 0; tm < 4; tm++)
            #pragma unroll
            for (int tn = 0; tn < 4; tn++) {
                int m = m0 + wm * 64 + tm * 16 + g;
                int n = n0 + wn * 32 + tn * 8 + 2 * t;
                Cu[(size_t)m * np + (n >> 1)] = pk(acc[tm][tn][0], acc[tm][tn][1]);
                Cu[(size_t)(m + 8) * np + (n >> 1)] = pk(acc[tm][tn][2], acc[tm][tn][3]);
            }
    } else {
        const float* x1 = (const float*)(g_u + OFF_X1);
        int b = m0 / HW, hw0 = m0 % HW;
        #pragma unroll
        for (int tm = 0; tm < 4; tm++)
            #pragma unroll
            for (int tn = 0; tn < 4; tn++) {
                int mrow = wm * 64 + tm * 16 + g;
                int n = wn * 32 + tn * 8 + 2 * t;
                size_t a0 = ((size_t)b * 128 + n) * HW + hw0 + mrow;
                outp[a0]          = x1[a0] + acc[tm][tn][0];
                outp[a0 + HW]     = x1[a0 + HW] + acc[tm][tn][1];
                outp[a0 + 8]      = x1[a0 + 8] + acc[tm][tn][2];
                outp[a0 + HW + 8] = x1[a0 + HW + 8] + acc[tm][tn][3];
            }
    }
}

// ---------------------------------------------------------------------------
// K3: per-(window,token) channel attention. Q/KV packed bf16 -> AO fp32.
// ---------------------------------------------------------------------------
__global__ void __launch_bounds__(256) k_attn()
{
    __shared__ float outs[32 * 129];
    __shared__ float buf[8 * 640];
    int bid = blockIdx.x;
    int chunk = bid % 61;
    int n = (bid / 61) % 16;
    int b = bid / (61 * 16);
    int ihw0 = chunk * 32;
    const unsigned* Qp  = g_u + OFF_Q;
    const unsigned* KVp = g_u + OFF_KV;
    float* AO = (float*)(g_u + OFF_AO);
    int warp = threadIdx.x >> 5, lane = threadIdx.x & 31;
    float* qs = buf + warp * 640;
    float* ks = qs + 128;
    float* vs = qs + 256;
    float* ds = qs + 384;

    for (int it = 0; it < 4; it++) {
        int g = it * 8 + warp;
        int ihw = ihw0 + g;
        if (ihw < NWIN) {
            int ih = ihw / 44, iw = ihw % 44;
            int h2 = ih * 4 + (n >> 2), w2 = iw * 4 + (n & 3);
            size_t p = (size_t)b * HW + (size_t)h2 * 176 + w2;
            {
                int i = lane;
                float2 vq = bf2f(Qp[p * 64 + i]);
                qs[2 * i] = vq.x; qs[2 * i + 1] = vq.y;
                float2 vq2 = bf2f(Qp[p * 64 + 32 + i]);
                qs[64 + 2 * i] = vq2.x; qs[65 + 2 * i] = vq2.y;
                float2 k1 = bf2f(KVp[p * 128 + i]);
                ks[2 * i] = k1.x; ks[2 * i + 1] = k1.y;
                float2 k2 = bf2f(KVp[p * 128 + 32 + i]);
                ks[64 + 2 * i] = k2.x; ks[65 + 2 * i] = k2.y;
                float2 v1 = bf2f(KVp[p * 128 + 64 + i]);
                vs[2 * i] = v1.x; vs[2 * i + 1] = v1.y;
                float2 v2 = bf2f(KVp[p * 128 + 96 + i]);
                vs[64 + 2 * i] = v2.x; vs[65 + 2 * i] = v2.y;
            }
            __syncwarp();
            for (int e = lane; e < 256; e += 32) {
                int j = e >> 4, kk = e & 15;
                float s = 0.f;
                #pragma unroll
                for (int i = 0; i < 8; i++) s += qs[i * 16 + j] * ks[i * 16 + kk];
                ds[e] = s * 0.25f;
            }
            __syncwarp();
            if (lane < 16) {
                float mx = -1e30f;
                #pragma unroll
                for (int kk = 0; kk < 16; kk++) mx = fmaxf(mx, ds[lane * 16 + kk]);
                float sm = 0.f;
                #pragma unroll
                for (int kk = 0; kk < 16; kk++) {
                    float ev = __expf(ds[lane * 16 + kk] - mx);
                    ds[lane * 16 + kk] = ev; sm += ev;
                }
                float inv = 1.f / sm;
                #pragma unroll
                for (int kk = 0; kk < 16; kk++) ds[lane * 16 + kk] *= inv;
            }
            __syncwarp();
            for (int ch = lane; ch < 128; ch += 32) {
                int i = ch >> 4, j = ch & 15;
                float s = 0.f;
                #pragma unroll
                for (int kk = 0; kk < 16; kk++) s += ds[j * 16 + kk] * vs[i * 16 + kk];
                outs[g * 129 + ch] = s;
            }
        }
    }
    __syncthreads();
    size_t base = ((size_t)b * 2048 + (size_t)n * 128) * 1936 + ihw0;
    for (int e = threadIdx.x; e < 4096; e += 256) {
        int ch = e >> 5, g = e & 31;
        if (ihw0 + g < NWIN)
            AO[base + (size_t)ch * 1936 + g] = outs[g * 129 + ch];
    }
}

// ---------------------------------------------------------------------------
// K4: x1 = x + AO (fp32) + LN2 applied & packed -> tiled X1LN (uint4 stores).
// ---------------------------------------------------------------------------
__global__ void __launch_bounds__(256) k_merge2(
    const float* __restrict__ x, const float* __restrict__ ln2w,
    const float* __restrict__ ln2b)
{
    __shared__ float red[264], red2[264], mu_s[32], rs_s[32];
    __shared__ float w2s[128], b2s[128];
    int p0 = blockIdx.x * 32;
    int b = p0 / HW, hw0 = p0 % HW;
    int px = threadIdx.x & 31, j = threadIdx.x >> 5;
    if (threadIdx.x < 128) { w2s[threadIdx.x] = ln2w[threadIdx.x]; b2s[threadIdx.x] = ln2b[threadIdx.x]; }
    const float* AO = (const float*)(g_u + OFF_AO);
    float* x1 = (float*)(g_u + OFF_X1);
    size_t base = (size_t)b * PB + hw0 + px;
    float v[16];
    float s = 0.f, s2 = 0.f;
    #pragma unroll
    for (int i = 0; i < 16; i++) {
        int c = j * 16 + i;
        size_t idx = base + (size_t)c * HW;
        float val = x[idx] + AO[idx];
        x1[idx] = val; v[i] = val; s += val; s2 += val * val;
    }
    red[j * 33 + px] = s; red2[j * 33 + px] = s2;
    __syncthreads();
    if (threadIdx.x < 32) {
        float ss = 0.f, ss2 = 0.f;
        #pragma unroll
        for (int j2 = 0; j2 < 8; j2++) { ss += red[j2 * 33 + threadIdx.x]; ss2 += red2[j2 * 33 + threadIdx.x]; }
        float mu = ss * (1.f / 128.f);
        float var = ss2 * (1.f / 128.f) - mu * mu;
        mu_s[threadIdx.x] = mu; rs_s[threadIdx.x] = rsqrtf(var + 1e-5f);
    }
    __syncthreads();
    float mu = mu_s[px], rs = rs_s[px];
    int p = p0 + px;
    unsigned qv[8];
    #pragma unroll
    for (int ii = 0; ii < 8; ii++) {
        int c = j * 16 + 2 * ii;
        float a = (v[2 * ii] - mu) * rs * w2s[c] + b2s[c];
        float bb = (v[2 * ii + 1] - mu) * rs * w2s[c + 1] + b2s[c + 1];
        qv[ii] = pk(a, bb);
    }
    uint4* dst = (uint4*)(g_u + OFF_X1LN + (size_t)(p >> 7) * 8192 + (size_t)j * 1024 + (size_t)(p & 127) * 8);
    dst[0] = make_uint4(qv[0], qv[1], qv[2], qv[3]);
    dst[1] = make_uint4(qv[4], qv[5], qv[6], qv[7]);
}

// ---------------------------------------------------------------------------
// K6: depthwise 3x3 + exact GELU gate, h-split x2 for occupancy.
// y_in packed [p][512] -> y_g packed [p][256].
// ---------------------------------------------------------------------------
__device__ __forceinline__ void dw_loadrow(
    const unsigned* __restrict__ yin, int b, int h, int w, int cp,
    float2* a, float2* bb)
{
    #pragma unroll
    for (int dw = 0; dw < 3; dw++) { a[dw] = make_float2(0.f, 0.f); bb[dw] = make_float2(0.f, 0.f); }
    if (h < 0 || h >= 176) return;
    #pragma unroll
    for (int dw = 0; dw < 3; dw++) {
        int ww = w + dw - 1;
        if (ww < 0 || ww >= 176) continue;
        size_t base = ((size_t)b * HW + (size_t)h * 176 + ww) * 512;
        a[dw]  = bf2f(yin[base + cp]);
        bb[dw] = bf2f(yin[base + 256 + cp]);
    }
}

__global__ void __launch_bounds__(256) k_dwconv(const float* __restrict__ wdw)
{
    int cp = threadIdx.x;
    int r = blockIdx.x;
    int hs = r & 1;
    int w = (r >> 1) % 176, b = (r >> 1) / 176;
    int h0 = hs * 88;
    const unsigned* yin = g_u + OFF_YIN;
    unsigned* yg = g_u + OFF_YG;
    int c0 = 2 * cp;
    float wa0[9], wa1[9], wb0[9], wb1[9];
    #pragma unroll
    for (int t = 0; t < 9; t++) {
        wa0[t] = __ldg(&wdw[c0 * 9 + t]);
        wa1[t] = __ldg(&wdw[(c0 + 1) * 9 + t]);
        wb0[t] = __ldg(&wdw[(512 + c0) * 9 + t]);
        wb1[t] = __ldg(&wdw[(513 + c0) * 9 + t]);
    }
    float2 A[3][3], B2[3][3];
    dw_loadrow(yin, b, h0 - 1, w, cp, A[0], B2[0]);
    dw_loadrow(yin, b, h0, w, cp, A[1], B2[1]);
    dw_loadrow(yin, b, h0 + 1, w, cp, A[2], B2[2]);

    for (int h = h0; h < h0 + 88; h++) {
        float a0 = 0.f, a1 = 0.f, g0 = 0.f, g1 = 0.f;
        #pragma unroll
        for (int rr = 0; rr < 3; rr++)
            #pragma unroll
            for (int cc = 0; cc < 3; cc++) {
                int t = rr * 3 + cc;
                a0 += A[rr][cc].x * wa0[t];
                a1 += A[rr][cc].y * wa1[t];
                g0 += B2[rr][cc].x * wb0[t];
                g1 += B2[rr][cc].y * wb1[t];
            }
        float e0 = 0.5f * a0 * (1.f + erff(a0 * 0.70710678118654752f));
        float e1 = 0.5f * a1 * (1.f + erff(a1 * 0.70710678118654752f));
        yg[((size_t)b * HW + (size_t)h * 176 + w) * 256 + cp] = pk(e0 * g0, e1 * g1);
        #pragma unroll
        for (int cc = 0; cc < 3; cc++) {
            A[0][cc] = A[1][cc]; A[1][cc] = A[2][cc];
            B2[0][cc] = B2[1][cc]; B2[1][cc] = B2[2][cc];
        }
        dw_loadrow(yin, b, h + 2, w, cp, A[2], B2[2]);
    }
}

// ---------------------------------------------------------------------------
extern "C" void kernel_launch(void* const* d_in, const int* in_sizes, int n_in,
                              void* d_out, int out_size)
{
    const float* x    = (const float*)d_in[0];
    const float* mask = (const float*)d_in[1];
    const float* edge = (const float*)d_in[2];
    const float* ln1w = (const float*)d_in[3];
    const float* ln1b = (const float*)d_in[4];
    const float* Wq   = (const float*)d_in[5];
    const float* Wk   = (const float*)d_in[6];
    const float* Wv   = (const float*)d_in[7];
    const float* ln2w = (const float*)d_in[8];
    const float* ln2b = (const float*)d_in[9];
    const float* w_in = (const float*)d_in[10];
    const float* w_dw = (const float*)d_in[11];
    const float* w_out= (const float*)d_in[12];
    float* outp = (float*)d_out;

    unsigned* G = nullptr;
    cudaGetSymbolAddress((void**)&G, g_u);

    // K0: weights -> tiled packed bf16x2
    k_wprep<<<(122880 + 255) / 256, 256>>>(Wq, Wk, Wv, w_in, w_out);

    // K1: LN1 + resize -> tiled Aq/Akv
    k_prep<<<PTOT / 32, 256>>>(x, mask, edge, ln1w, ln1b);

    // K2: Q GEMM; fused KV GEMM with swapped grid (x=n-block) for A L2-reuse
    k_mma_t<8, 0, 1, 0><<<dim3(PTOT / 128, 1), 256>>>(G + OFF_AQ,  G + OFF_WB,        G + OFF_Q,  128, nullptr);
    k_mma_t<8, 0, 1, 1><<<dim3(2, PTOT / 128), 256>>>(G + OFF_AKV, G + OFF_WB + 8192, G + OFF_KV, 256, nullptr);

    // K3: channel attention -> AO (merged layout, fp32)
    k_attn<<<4 * 16 * 61, 256>>>();

    // K4: x1 = x + AO, LN2 applied & packed -> tiled X1LN
    k_merge2<<<PTOT / 32, 256>>>(x, ln2w, ln2b);

    // K5: conv1x1 128->1024, swapped grid (x=n-block 8) for A L2-reuse
    k_mma_t<8, 0, 1, 1><<<dim3(8, PTOT / 128), 256>>>(G + OFF_X1LN, G + OFF_WB + 24576, G + OFF_YIN, 1024, nullptr);

    // K6: depthwise 3x3 + GELU gate -> y_g packed rows (h-split x2)
    k_dwconv<<<BATCH * 176 * 2, 256>>>(w_dw);

    // K7: conv1x1 512->128 + residual -> d_out (NCHW), A from rows
    k_mma_t<32, 1, 2, 0><<<dim3(PTOT / 128, 1), 256>>>(G + OFF_YG, G + OFF_WB + 90112, nullptr, 128, outp);
}

// round 8
// speedup vs baseline: 1.2387x; 1.1886x over previous
#include <cuda_runtime.h>
#include <cuda_bf16.h>
#include <math.h>

#define BATCH 4
#define HW    30976            // 176*176
#define PTOT  123904           // BATCH*HW
#define NWIN  1936             // 44*44
#define PB    3964928ULL       // per-batch plane = 128*30976

// uint-unit offsets into the single scratch buffer
#define OFF_AQ    0ULL          // tiled bf16x2, K=128 (8 stages/blk)
#define OFF_AKV   7929856ULL    // tiled bf16x2, K=128
#define OFF_AO    15859712ULL   // fp32 merged-layout attention out
#define OFF_Q     31719424ULL   // packed bf16x2 [p][64]
#define OFF_KV    47579136ULL   // packed bf16x2 [p][128] (K | V)
#define OFF_X1    79298560ULL   // fp32 NCHW residual
#define OFF_X1LN  95158272ULL   // tiled bf16x2, K=128
#define OFF_YIN   103088128ULL  // packed bf16x2 [p][512]
#define OFF_YG    166526976ULL  // packed bf16x2 [p][256]
#define OFF_WB    198246400ULL
#define TOT_U     198369280ULL

__device__ unsigned g_u[TOT_U];

// ---------------------------------------------------------------------------
// helpers
// ---------------------------------------------------------------------------
__device__ __forceinline__ unsigned pk(float lo, float hi) {
    unsigned r;
    asm("cvt.rn.bf16x2.f32 %0, %1, %2;" : "=r"(r) : "f"(hi), "f"(lo));
    return r;
}
__device__ __forceinline__ float2 bf2f(unsigned u) {
    __nv_bfloat162 h = *reinterpret_cast<__nv_bfloat162*>(&u);
    return __bfloat1622float2(h);
}
__device__ __forceinline__ void mma16(float* d, const unsigned* a, const unsigned* b) {
    asm volatile(
        "mma.sync.aligned.m16n8k16.row.col.f32.bf16.bf16.f32 "
        "{%0,%1,%2,%3},{%4,%5,%6,%7},{%8,%9},{%0,%1,%2,%3};"
        : "+f"(d[0]), "+f"(d[1]), "+f"(d[2]), "+f"(d[3])
        : "r"(a[0]), "r"(a[1]), "r"(a[2]), "r"(a[3]), "r"(b[0]), "r"(b[1]));
}
__device__ __forceinline__ void ldsm4(unsigned& r0, unsigned& r1, unsigned& r2, unsigned& r3, unsigned a) {
    asm volatile("ldmatrix.sync.aligned.m8n8.x4.shared.b16 {%0,%1,%2,%3}, [%4];"
        : "=r"(r0), "=r"(r1), "=r"(r2), "=r"(r3) : "r"(a));
}
__device__ __forceinline__ void cpa16(unsigned d, const void* s) {
    asm volatile("cp.async.cg.shared.global [%0], [%1], 16;" :: "r"(d), "l"(s));
}
#define CP_COMMIT() asm volatile("cp.async.commit_group;" ::: "memory")
#define CP_WAIT1()  asm volatile("cp.async.wait_group 1;" ::: "memory")
#define CP_WAIT0()  asm volatile("cp.async.wait_group 0;" ::: "memory")

// ---------------------------------------------------------------------------
// K0: weight prep -> packed bf16x2 in GEMM-tiled layout.
// WB: WqP[8192] | WKVP[16384] | WinP[65536] | WoutP[32768]
// ---------------------------------------------------------------------------
__global__ void k_wprep(const float* __restrict__ Wq, const float* __restrict__ Wk,
                        const float* __restrict__ Wv, const float* __restrict__ win,
                        const float* __restrict__ wout)
{
    int idx = blockIdx.x * 256 + threadIdx.x;
    if (idx >= 122880) return;
    unsigned* WB = g_u + OFF_WB;
    if (idx < 8192) {
        int n = idx >> 6, kp = idx & 63;
        WB[(kp >> 3) * 1024 + n * 8 + (kp & 7)] = pk(Wq[n * 128 + 2 * kp], Wq[n * 128 + 2 * kp + 1]);
    } else if (idx < 24576) {
        int j = idx - 8192; int n2 = j >> 6, kp = j & 63;
        const float* W = (n2 < 128) ? Wk : Wv;
        int n = n2 & 127;
        WB[8192 + (n2 >> 7) * 8192 + (kp >> 3) * 1024 + n * 8 + (kp & 7)]
            = pk(W[n * 128 + 2 * kp], W[n * 128 + 2 * kp + 1]);
    } else if (idx < 90112) {
        int j = idx - 24576; int n = j >> 6, kp = j & 63;
        WB[24576 + (n >> 7) * 8192 + (kp >> 3) * 1024 + (n & 127) * 8 + (kp & 7)]
            = pk(win[n * 128 + 2 * kp], win[n * 128 + 2 * kp + 1]);
    } else {
        int j = idx - 90112; int n = j >> 8, kp = j & 255;
        WB[90112 + (kp >> 3) * 1024 + n * 8 + (kp & 7)]
            = pk(wout[n * 512 + 2 * kp], wout[n * 512 + 2 * kp + 1]);
    }
}

// ---------------------------------------------------------------------------
// K1: LN1(x), bilinear mask/edge upsample -> tiled Aq / Akv (uint4 stores).
// ---------------------------------------------------------------------------
__global__ void __launch_bounds__(256) k_prep(
    const float* __restrict__ x, const float* __restrict__ mask,
    const float* __restrict__ edge, const float* __restrict__ ln1w,
    const float* __restrict__ ln1b)
{
    __shared__ float xs[128 * 33];
    __shared__ float red[264], red2[264];
    __shared__ float ms[32], mu_s[32], rs_s[32];
    __shared__ int   cy0[32], cy1[32], cx0[32], cx1[32];
    __shared__ float cwy[32], cwx[32];
    __shared__ float w1s[128], b1s[128];

    int p0 = blockIdx.x * 32;
    int b = p0 / HW, hw0 = p0 % HW;
    const float* xb = x + (size_t)b * PB;
    if (threadIdx.x < 128) { w1s[threadIdx.x] = ln1w[threadIdx.x]; b1s[threadIdx.x] = ln1b[threadIdx.x]; }

    for (int e = threadIdx.x; e < 4096; e += 256) {
        int c = e >> 5, px = e & 31;
        xs[c * 33 + px] = xb[(size_t)c * HW + hw0 + px];
    }
    if (threadIdx.x < 32) {
        int px = threadIdx.x;
        int hw = hw0 + px;
        int h2 = hw / 176, w2 = hw % 176;
        float fy = 0.25f * h2 - 0.375f; int iy = (int)floorf(fy); float ty = fy - iy;
        float fx = 0.25f * w2 - 0.375f; int ix = (int)floorf(fx); float tx = fx - ix;
        int y0 = iy < 0 ? 0 : iy, y1 = (iy + 1 > 43) ? 43 : iy + 1;
        int x0 = ix < 0 ? 0 : ix, x1 = (ix + 1 > 43) ? 43 : ix + 1;
        cy0[px] = y0; cy1[px] = y1; cx0[px] = x0; cx1[px] = x1;
        cwy[px] = ty; cwx[px] = tx;
        const float* mb = mask + b * NWIN;
        ms[px] = (1.f - ty) * ((1.f - tx) * mb[y0 * 44 + x0] + tx * mb[y0 * 44 + x1])
               +        ty  * ((1.f - tx) * mb[y1 * 44 + x0] + tx * mb[y1 * 44 + x1]);
    }
    __syncthreads();
    {
        int px = threadIdx.x & 31, j = threadIdx.x >> 5;
        float s = 0.f, s2 = 0.f;
        #pragma unroll
        for (int i = 0; i < 16; i++) {
            float v = xs[(j * 16 + i) * 33 + px];
            s += v; s2 += v * v;
        }
        red[j * 33 + px] = s; red2[j * 33 + px] = s2;
    }
    __syncthreads();
    if (threadIdx.x < 32) {
        int px = threadIdx.x; float s = 0.f, s2 = 0.f;
        #pragma unroll
        for (int j = 0; j < 8; j++) { s += red[j * 33 + px]; s2 += red2[j * 33 + px]; }
        float mu = s * (1.f / 128.f);
        float var = s2 * (1.f / 128.f) - mu * mu;
        mu_s[px] = mu; rs_s[px] = rsqrtf(var + 1e-5f);
    }
    __syncthreads();

    int px = threadIdx.x & 31, j = threadIdx.x >> 5;   // j = stage 0..7
    int p = p0 + px;
    size_t tbase = (size_t)(p >> 7) * 8192 + (size_t)j * 1024 + (size_t)(p & 127) * 8;
    {
        float mu = mu_s[px], rs = rs_s[px], m = ms[px];
        unsigned q[8];
        #pragma unroll
        for (int ii = 0; ii < 8; ii++) {
            int c = j * 16 + 2 * ii;
            float v0 = ((xs[c * 33 + px] - mu) * rs * w1s[c] + b1s[c]) * m;
            float v1 = ((xs[(c + 1) * 33 + px] - mu) * rs * w1s[c + 1] + b1s[c + 1]) * m;
            q[ii] = pk(v0, v1);
        }
        uint4* dst = (uint4*)(g_u + OFF_AKV + tbase);
        dst[0] = make_uint4(q[0], q[1], q[2], q[3]);
        dst[1] = make_uint4(q[4], q[5], q[6], q[7]);
    }
    __syncthreads();
    for (int e = threadIdx.x; e < 4096; e += 256) {
        int c = e >> 5, px2 = e & 31;
        const float* eb = edge + ((size_t)b * 128 + c) * NWIN;
        float ty = cwy[px2], tx = cwx[px2];
        float v = (1.f - ty) * ((1.f - tx) * eb[cy0[px2] * 44 + cx0[px2]] + tx * eb[cy0[px2] * 44 + cx1[px2]])
                +        ty  * ((1.f - tx) * eb[cy1[px2] * 44 + cx0[px2]] + tx * eb[cy1[px2] * 44 + cx1[px2]]);
        xs[c * 33 + px2] = v;
    }
    __syncthreads();
    {
        unsigned q[8];
        #pragma unroll
        for (int ii = 0; ii < 8; ii++) {
            int c = j * 16 + 2 * ii;
            q[ii] = pk(xs[c * 33 + px], xs[(c + 1) * 33 + px]);
        }
        uint4* dst = (uint4*)(g_u + OFF_AQ + tbase);
        dst[0] = make_uint4(q[0], q[1], q[2], q[3]);
        dst[1] = make_uint4(q[4], q[5], q[6], q[7]);
    }
}

// ---------------------------------------------------------------------------
// K2: bf16 MMA GEMM, cp.async 3-stage pipeline + ldmatrix (R5-proven core).
// ASRC=0: A tiled.  ASRC=1: A rows [m][256] (K=512).
// EPI=1: packed bf16x2 C [M][Nd/2].  EPI=2: fp32 + residual -> NCHW outp.
// ---------------------------------------------------------------------------
template<int NSTAGE, int ASRC, int EPI>
__global__ void __launch_bounds__(256, 2) k_mma_t(
    const unsigned* __restrict__ At, const unsigned* __restrict__ Bt,
    unsigned* __restrict__ Cu, int Nd, float* __restrict__ outp)
{
    __shared__ unsigned sm[3 * 2048];
    int tid = threadIdx.x, lane = tid & 31, warp = tid >> 5;
    int wm = warp >> 2, wn = warp & 3, t = lane & 3, g = lane >> 2;
    const unsigned* Ab;
    if (ASRC == 0) Ab = At + (size_t)blockIdx.x * (NSTAGE * 1024) + tid * 4;
    else           Ab = At + ((size_t)blockIdx.x * 128 + (tid >> 1)) * 256 + (tid & 1) * 4;
    const unsigned* Bb = Bt + (size_t)blockIdx.y * (NSTAGE * 1024) + tid * 4;
    unsigned smb = (unsigned)__cvta_generic_to_shared(sm);

    // cp.async dst (swizzled 16B rows)
    int m_ = tid >> 1, q = tid & 1;
    unsigned dA = smb + (unsigned)(2 * m_ + (q ^ ((m_ >> 2) & 1))) * 16;
    unsigned dB = dA + 4096;

    // ldmatrix fragment addresses (stage-buffer relative)
    int itemA = wm * 64 + (lane & 15);
    int khA = lane >> 4;
    unsigned aAddr = smb + (unsigned)(2 * itemA + (khA ^ ((itemA >> 2) & 1))) * 16;
    int itemB = wn * 32 + lane;
    int bbit = (itemB >> 2) & 1;
    unsigned bAddr0 = smb + 4096u + (unsigned)(2 * itemB + bbit) * 16;
    unsigned bAddr1 = smb + 4096u + (unsigned)(2 * itemB + (1 ^ bbit)) * 16;

    float acc[4][4][4];
    #pragma unroll
    for (int i = 0; i < 4; i++)
        #pragma unroll
        for (int j = 0; j < 4; j++)
            #pragma unroll
            for (int k = 0; k < 4; k++) acc[i][j][k] = 0.f;

    #pragma unroll
    for (int s = 0; s < 2; s++) {
        unsigned off = s * 8192u;
        cpa16(dA + off, Ab + (ASRC == 0 ? s * 1024 : s * 8));
        cpa16(dB + off, Bb + s * 1024);
        CP_COMMIT();
    }

    for (int s = 0; s < NSTAGE; s++) {
        if (s + 1 < NSTAGE) CP_WAIT1(); else CP_WAIT0();
        __syncthreads();
        unsigned buf = (unsigned)(s % 3) * 8192u;
        unsigned af[4][4], bf[4][2];
        ldsm4(bf[0][0], bf[1][0], bf[2][0], bf[3][0], bAddr0 + buf);
        ldsm4(bf[0][1], bf[1][1], bf[2][1], bf[3][1], bAddr1 + buf);
        #pragma unroll
        for (int tm = 0; tm < 4; tm++)
            ldsm4(af[tm][0], af[tm][1], af[tm][2], af[tm][3], aAddr + buf + tm * 512u);
        #pragma unroll
        for (int tm = 0; tm < 4; tm++)
            #pragma unroll
            for (int tn = 0; tn < 4; tn++)
                mma16(acc[tm][tn], af[tm], bf[tn]);
        if (s + 2 < NSTAGE) {
            unsigned off = (unsigned)((s + 2) % 3) * 8192u;
            cpa16(dA + off, Ab + (ASRC == 0 ? (s + 2) * 1024 : (s + 2) * 8));
            cpa16(dB + off, Bb + (s + 2) * 1024);
            CP_COMMIT();
        }
        __syncthreads();
    }

    int m0 = blockIdx.x * 128, n0 = blockIdx.y * 128;
    if (EPI == 1) {
        int np = Nd >> 1;
        #pragma unroll
        for (int tm = 0; tm < 4; tm++)
            #pragma unroll
            for (int tn = 0; tn < 4; tn++) {
                int m = m0 + wm * 64 + tm * 16 + g;
                int n = n0 + wn * 32 + tn * 8 + 2 * t;
                Cu[(size_t)m * np + (n >> 1)] = pk(acc[tm][tn][0], acc[tm][tn][1]);
                Cu[(size_t)(m + 8) * np + (n >> 1)] = pk(acc[tm][tn][2], acc[tm][tn][3]);
            }
    } else {
        const float* x1 = (const float*)(g_u + OFF_X1);
        int b = m0 / HW, hw0 = m0 % HW;
        #pragma unroll
        for (int tm = 0; tm < 4; tm++)
            #pragma unroll
            for (int tn = 0; tn < 4; tn++) {
                int mrow = wm * 64 + tm * 16 + g;
                int n = wn * 32 + tn * 8 + 2 * t;
                size_t a0 = ((size_t)b * 128 + n) * HW + hw0 + mrow;
                outp[a0]          = x1[a0] + acc[tm][tn][0];
                outp[a0 + HW]     = x1[a0 + HW] + acc[tm][tn][1];
                outp[a0 + 8]      = x1[a0 + 8] + acc[tm][tn][2];
                outp[a0 + HW + 8] = x1[a0 + HW + 8] + acc[tm][tn][3];
            }
    }
}

// ---------------------------------------------------------------------------
// K3: per-(window,token) channel attention. Q/KV packed bf16 -> AO fp32.
// ---------------------------------------------------------------------------
__global__ void __launch_bounds__(256) k_attn()
{
    __shared__ float outs[32 * 129];
    __shared__ float buf[8 * 640];
    int bid = blockIdx.x;
    int chunk = bid % 61;
    int n = (bid / 61) % 16;
    int b = bid / (61 * 16);
    int ihw0 = chunk * 32;
    const unsigned* Qp  = g_u + OFF_Q;
    const unsigned* KVp = g_u + OFF_KV;
    float* AO = (float*)(g_u + OFF_AO);
    int warp = threadIdx.x >> 5, lane = threadIdx.x & 31;
    float* qs = buf + warp * 640;
    float* ks = qs + 128;
    float* vs = qs + 256;
    float* ds = qs + 384;

    for (int it = 0; it < 4; it++) {
        int g = it * 8 + warp;
        int ihw = ihw0 + g;
        if (ihw < NWIN) {
            int ih = ihw / 44, iw = ihw % 44;
            int h2 = ih * 4 + (n >> 2), w2 = iw * 4 + (n & 3);
            size_t p = (size_t)b * HW + (size_t)h2 * 176 + w2;
            {
                int i = lane;
                float2 vq = bf2f(Qp[p * 64 + i]);
                qs[2 * i] = vq.x; qs[2 * i + 1] = vq.y;
                float2 vq2 = bf2f(Qp[p * 64 + 32 + i]);
                qs[64 + 2 * i] = vq2.x; qs[65 + 2 * i] = vq2.y;
                float2 k1 = bf2f(KVp[p * 128 + i]);
                ks[2 * i] = k1.x; ks[2 * i + 1] = k1.y;
                float2 k2 = bf2f(KVp[p * 128 + 32 + i]);
                ks[64 + 2 * i] = k2.x; ks[65 + 2 * i] = k2.y;
                float2 v1 = bf2f(KVp[p * 128 + 64 + i]);
                vs[2 * i] = v1.x; vs[2 * i + 1] = v1.y;
                float2 v2 = bf2f(KVp[p * 128 + 96 + i]);
                vs[64 + 2 * i] = v2.x; vs[65 + 2 * i] = v2.y;
            }
            __syncwarp();
            for (int e = lane; e < 256; e += 32) {
                int j = e >> 4, kk = e & 15;
                float s = 0.f;
                #pragma unroll
                for (int i = 0; i < 8; i++) s += qs[i * 16 + j] * ks[i * 16 + kk];
                ds[e] = s * 0.25f;
            }
            __syncwarp();
            if (lane < 16) {
                float mx = -1e30f;
                #pragma unroll
                for (int kk = 0; kk < 16; kk++) mx = fmaxf(mx, ds[lane * 16 + kk]);
                float sm = 0.f;
                #pragma unroll
                for (int kk = 0; kk < 16; kk++) {
                    float ev = __expf(ds[lane * 16 + kk] - mx);
                    ds[lane * 16 + kk] = ev; sm += ev;
                }
                float inv = 1.f / sm;
                #pragma unroll
                for (int kk = 0; kk < 16; kk++) ds[lane * 16 + kk] *= inv;
            }
            __syncwarp();
            for (int ch = lane; ch < 128; ch += 32) {
                int i = ch >> 4, j = ch & 15;
                float s = 0.f;
                #pragma unroll
                for (int kk = 0; kk < 16; kk++) s += ds[j * 16 + kk] * vs[i * 16 + kk];
                outs[g * 129 + ch] = s;
            }
        }
    }
    __syncthreads();
    size_t base = ((size_t)b * 2048 + (size_t)n * 128) * 1936 + ihw0;
    for (int e = threadIdx.x; e < 4096; e += 256) {
        int ch = e >> 5, g = e & 31;
        if (ihw0 + g < NWIN)
            AO[base + (size_t)ch * 1936 + g] = outs[g * 129 + ch];
    }
}

// ---------------------------------------------------------------------------
// K4: x1 = x + AO (fp32) + LN2 applied & packed -> tiled X1LN (uint4 stores).
// ---------------------------------------------------------------------------
__global__ void __launch_bounds__(256) k_merge2(
    const float* __restrict__ x, const float* __restrict__ ln2w,
    const float* __restrict__ ln2b)
{
    __shared__ float red[264], red2[264], mu_s[32], rs_s[32];
    __shared__ float w2s[128], b2s[128];
    int p0 = blockIdx.x * 32;
    int b = p0 / HW, hw0 = p0 % HW;
    int px = threadIdx.x & 31, j = threadIdx.x >> 5;
    if (threadIdx.x < 128) { w2s[threadIdx.x] = ln2w[threadIdx.x]; b2s[threadIdx.x] = ln2b[threadIdx.x]; }
    const float* AO = (const float*)(g_u + OFF_AO);
    float* x1 = (float*)(g_u + OFF_X1);
    size_t base = (size_t)b * PB + hw0 + px;
    float v[16];
    float s = 0.f, s2 = 0.f;
    #pragma unroll
    for (int i = 0; i < 16; i++) {
        int c = j * 16 + i;
        size_t idx = base + (size_t)c * HW;
        float val = x[idx] + AO[idx];
        x1[idx] = val; v[i] = val; s += val; s2 += val * val;
    }
    red[j * 33 + px] = s; red2[j * 33 + px] = s2;
    __syncthreads();
    if (threadIdx.x < 32) {
        float ss = 0.f, ss2 = 0.f;
        #pragma unroll
        for (int j2 = 0; j2 < 8; j2++) { ss += red[j2 * 33 + threadIdx.x]; ss2 += red2[j2 * 33 + threadIdx.x]; }
        float mu = ss * (1.f / 128.f);
        float var = ss2 * (1.f / 128.f) - mu * mu;
        mu_s[threadIdx.x] = mu; rs_s[threadIdx.x] = rsqrtf(var + 1e-5f);
    }
    __syncthreads();
    float mu = mu_s[px], rs = rs_s[px];
    int p = p0 + px;
    unsigned qv[8];
    #pragma unroll
    for (int ii = 0; ii < 8; ii++) {
        int c = j * 16 + 2 * ii;
        float a = (v[2 * ii] - mu) * rs * w2s[c] + b2s[c];
        float bb = (v[2 * ii + 1] - mu) * rs * w2s[c + 1] + b2s[c + 1];
        qv[ii] = pk(a, bb);
    }
    uint4* dst = (uint4*)(g_u + OFF_X1LN + (size_t)(p >> 7) * 8192 + (size_t)j * 1024 + (size_t)(p & 127) * 8);
    dst[0] = make_uint4(qv[0], qv[1], qv[2], qv[3]);
    dst[1] = make_uint4(qv[4], qv[5], qv[6], qv[7]);
}

// ---------------------------------------------------------------------------
// K6: depthwise 3x3 + exact GELU gate. 4 w-columns/thread, packed-uint
// register window (rows h-1,h,h+1 x 6 cols), h-strip of 22 rows.
// y_in packed [p][512] -> y_g packed [p][256].
// ---------------------------------------------------------------------------
__device__ __forceinline__ void dw_row6(
    const unsigned* __restrict__ yin, int b, int h, int w0, int cp,
    unsigned* U, unsigned* V)
{
    #pragma unroll
    for (int dw = 0; dw < 6; dw++) { U[dw] = 0u; V[dw] = 0u; }
    if (h < 0 || h >= 176) return;
    #pragma unroll
    for (int dw = 0; dw < 6; dw++) {
        int ww = w0 - 1 + dw;
        if (ww < 0 || ww >= 176) continue;
        size_t base = ((size_t)b * HW + (size_t)h * 176 + ww) * 512;
        U[dw] = yin[base + cp];
        V[dw] = yin[base + 256 + cp];
    }
}

__global__ void __launch_bounds__(256) k_dwconv(const float* __restrict__ wdw)
{
    int cp = threadIdx.x;                 // 0..255 (channel pair)
    int blk = blockIdx.x;                 // (b*8 + hs)*44 + wg
    int wg = blk % 44;
    int hs = (blk / 44) % 8;
    int b  = blk / (44 * 8);
    int w0 = wg * 4;
    int h0 = hs * 22;
    const unsigned* yin = g_u + OFF_YIN;
    unsigned* yg = g_u + OFF_YG;
    int c0 = 2 * cp;
    float wa0[9], wa1[9], wb0[9], wb1[9];
    #pragma unroll
    for (int t = 0; t < 9; t++) {
        wa0[t] = __ldg(&wdw[c0 * 9 + t]);
        wa1[t] = __ldg(&wdw[(c0 + 1) * 9 + t]);
        wb0[t] = __ldg(&wdw[(512 + c0) * 9 + t]);
        wb1[t] = __ldg(&wdw[(513 + c0) * 9 + t]);
    }
    unsigned U[3][6], V[3][6];
    dw_row6(yin, b, h0 - 1, w0, cp, U[0], V[0]);
    dw_row6(yin, b, h0,     w0, cp, U[1], V[1]);
    dw_row6(yin, b, h0 + 1, w0, cp, U[2], V[2]);

    for (int h = h0; h < h0 + 22; h++) {
        float accA[4][2], accB[4][2];
        #pragma unroll
        for (int o = 0; o < 4; o++) {
            accA[o][0] = 0.f; accA[o][1] = 0.f;
            accB[o][0] = 0.f; accB[o][1] = 0.f;
        }
        #pragma unroll
        for (int dw = 0; dw < 6; dw++) {
            #pragma unroll
            for (int rr = 0; rr < 3; rr++) {
                float2 ua = bf2f(U[rr][dw]);
                float2 vb = bf2f(V[rr][dw]);
                #pragma unroll
                for (int o = 0; o < 4; o++) {
                    int cc = dw - o;
                    if (cc >= 0 && cc < 3) {
                        int tt = rr * 3 + cc;
                        accA[o][0] += ua.x * wa0[tt];
                        accA[o][1] += ua.y * wa1[tt];
                        accB[o][0] += vb.x * wb0[tt];
                        accB[o][1] += vb.y * wb1[tt];
                    }
                }
            }
        }
        #pragma unroll
        for (int o = 0; o < 4; o++) {
            float a0 = accA[o][0], a1 = accA[o][1];
            float e0 = 0.5f * a0 * (1.f + erff(a0 * 0.70710678118654752f));
            float e1 = 0.5f * a1 * (1.f + erff(a1 * 0.70710678118654752f));
            int p = b * HW + h * 176 + w0 + o;
            yg[(size_t)p * 256 + cp] = pk(e0 * accB[o][0], e1 * accB[o][1]);
        }
        #pragma unroll
        for (int dw = 0; dw < 6; dw++) {
            U[0][dw] = U[1][dw]; U[1][dw] = U[2][dw];
            V[0][dw] = V[1][dw]; V[1][dw] = V[2][dw];
        }
        dw_row6(yin, b, h + 2, w0, cp, U[2], V[2]);
    }
}

// ---------------------------------------------------------------------------
extern "C" void kernel_launch(void* const* d_in, const int* in_sizes, int n_in,
                              void* d_out, int out_size)
{
    const float* x    = (const float*)d_in[0];
    const float* mask = (const float*)d_in[1];
    const float* edge = (const float*)d_in[2];
    const float* ln1w = (const float*)d_in[3];
    const float* ln1b = (const float*)d_in[4];
    const float* Wq   = (const float*)d_in[5];
    const float* Wk   = (const float*)d_in[6];
    const float* Wv   = (const float*)d_in[7];
    const float* ln2w = (const float*)d_in[8];
    const float* ln2b = (const float*)d_in[9];
    const float* w_in = (const float*)d_in[10];
    const float* w_dw = (const float*)d_in[11];
    const float* w_out= (const float*)d_in[12];
    float* outp = (float*)d_out;

    unsigned* G = nullptr;
    cudaGetSymbolAddress((void**)&G, g_u);

    // K0: weights -> tiled packed bf16x2
    k_wprep<<<(122880 + 255) / 256, 256>>>(Wq, Wk, Wv, w_in, w_out);

    // K1: LN1 + resize -> tiled Aq/Akv
    k_prep<<<PTOT / 32, 256>>>(x, mask, edge, ln1w, ln1b);

    // K2: Q and fused KV bf16 GEMMs (R5 config)
    k_mma_t<8, 0, 1><<<dim3(PTOT / 128, 1), 256>>>(G + OFF_AQ,  G + OFF_WB,        G + OFF_Q,  128, nullptr);
    k_mma_t<8, 0, 1><<<dim3(PTOT / 128, 2), 256>>>(G + OFF_AKV, G + OFF_WB + 8192, G + OFF_KV, 256, nullptr);

    // K3: channel attention -> AO (merged layout, fp32)
    k_attn<<<4 * 16 * 61, 256>>>();

    // K4: x1 = x + AO, LN2 applied & packed -> tiled X1LN
    k_merge2<<<PTOT / 32, 256>>>(x, ln2w, ln2b);

    // K5: conv1x1 128->1024 -> y_in packed bf16 (R5 config)
    k_mma_t<8, 0, 1><<<dim3(PTOT / 128, 8), 256>>>(G + OFF_X1LN, G + OFF_WB + 24576, G + OFF_YIN, 1024, nullptr);

    // K6: depthwise 3x3 + GELU gate -> y_g packed rows (4 w/thread, hs x8)
    k_dwconv<<<BATCH * 44 * 8, 256>>>(w_dw);

    // K7: conv1x1 512->128 + residual -> d_out (NCHW), A from rows
    k_mma_t<32, 1, 2><<<dim3(PTOT / 128, 1), 256>>>(G + OFF_YG, G + OFF_WB + 90112, nullptr, 128, outp);
}

// round 9
// speedup vs baseline: 1.2722x; 1.0271x over previous
#include <cuda_runtime.h>
#include <cuda_bf16.h>
#include <math.h>

#define BATCH 4
#define HW    30976            // 176*176
#define PTOT  123904           // BATCH*HW
#define NWIN  1936             // 44*44
#define PB    3964928ULL       // per-batch plane = 128*30976

// uint-unit offsets into the single scratch buffer
#define OFF_AQ    0ULL          // tiled bf16x2, K=128 (8 stages/blk)
#define OFF_AKV   7929856ULL    // tiled bf16x2, K=128
#define OFF_AO    15859712ULL   // (unused after fusion)
#define OFF_Q     31719424ULL   // packed bf16x2 [p][64]
#define OFF_KV    47579136ULL   // packed bf16x2 [p][128] (K | V)
#define OFF_X1    79298560ULL   // fp32 NCHW residual (written by k_attn)
#define OFF_X1LN  95158272ULL   // tiled bf16x2, K=128
#define OFF_YIN   103088128ULL  // packed bf16x2 [p][512]
#define OFF_YG    166526976ULL  // packed bf16x2 [p][256]
#define OFF_WB    198246400ULL
#define TOT_U     198369280ULL

__device__ unsigned g_u[TOT_U];

// ---------------------------------------------------------------------------
// helpers
// ---------------------------------------------------------------------------
__device__ __forceinline__ unsigned pk(float lo, float hi) {
    unsigned r;
    asm("cvt.rn.bf16x2.f32 %0, %1, %2;" : "=r"(r) : "f"(hi), "f"(lo));
    return r;
}
__device__ __forceinline__ float2 bf2f(unsigned u) {
    __nv_bfloat162 h = *reinterpret_cast<__nv_bfloat162*>(&u);
    return __bfloat1622float2(h);
}
__device__ __forceinline__ void mma16(float* d, const unsigned* a, const unsigned* b) {
    asm volatile(
        "mma.sync.aligned.m16n8k16.row.col.f32.bf16.bf16.f32 "
        "{%0,%1,%2,%3},{%4,%5,%6,%7},{%8,%9},{%0,%1,%2,%3};"
        : "+f"(d[0]), "+f"(d[1]), "+f"(d[2]), "+f"(d[3])
        : "r"(a[0]), "r"(a[1]), "r"(a[2]), "r"(a[3]), "r"(b[0]), "r"(b[1]));
}
__device__ __forceinline__ void ldsm4(unsigned& r0, unsigned& r1, unsigned& r2, unsigned& r3, unsigned a) {
    asm volatile("ldmatrix.sync.aligned.m8n8.x4.shared.b16 {%0,%1,%2,%3}, [%4];"
        : "=r"(r0), "=r"(r1), "=r"(r2), "=r"(r3) : "r"(a));
}
__device__ __forceinline__ void cpa16(unsigned d, const void* s) {
    asm volatile("cp.async.cg.shared.global [%0], [%1], 16;" :: "r"(d), "l"(s));
}
__device__ __forceinline__ void stg_cs(unsigned* p, unsigned v) {
    asm volatile("st.global.cs.u32 [%0], %1;" :: "l"(p), "r"(v));
}
#define CP_COMMIT() asm volatile("cp.async.commit_group;" ::: "memory")
#define CP_WAIT1()  asm volatile("cp.async.wait_group 1;" ::: "memory")
#define CP_WAIT0()  asm volatile("cp.async.wait_group 0;" ::: "memory")

// ---------------------------------------------------------------------------
// K0: weight prep -> packed bf16x2 in GEMM-tiled layout.
// WB: WqP[8192] | WKVP[16384] | WinP[65536] | WoutP[32768]
// ---------------------------------------------------------------------------
__global__ void k_wprep(const float* __restrict__ Wq, const float* __restrict__ Wk,
                        const float* __restrict__ Wv, const float* __restrict__ win,
                        const float* __restrict__ wout)
{
    int idx = blockIdx.x * 256 + threadIdx.x;
    if (idx >= 122880) return;
    unsigned* WB = g_u + OFF_WB;
    if (idx < 8192) {
        int n = idx >> 6, kp = idx & 63;
        WB[(kp >> 3) * 1024 + n * 8 + (kp & 7)] = pk(Wq[n * 128 + 2 * kp], Wq[n * 128 + 2 * kp + 1]);
    } else if (idx < 24576) {
        int j = idx - 8192; int n2 = j >> 6, kp = j & 63;
        const float* W = (n2 < 128) ? Wk : Wv;
        int n = n2 & 127;
        WB[8192 + (n2 >> 7) * 8192 + (kp >> 3) * 1024 + n * 8 + (kp & 7)]
            = pk(W[n * 128 + 2 * kp], W[n * 128 + 2 * kp + 1]);
    } else if (idx < 90112) {
        int j = idx - 24576; int n = j >> 6, kp = j & 63;
        WB[24576 + (n >> 7) * 8192 + (kp >> 3) * 1024 + (n & 127) * 8 + (kp & 7)]
            = pk(win[n * 128 + 2 * kp], win[n * 128 + 2 * kp + 1]);
    } else {
        int j = idx - 90112; int n = j >> 8, kp = j & 255;
        WB[90112 + (kp >> 3) * 1024 + n * 8 + (kp & 7)]
            = pk(wout[n * 512 + 2 * kp], wout[n * 512 + 2 * kp + 1]);
    }
}

// ---------------------------------------------------------------------------
// K1: LN1(x), bilinear mask/edge upsample -> tiled Aq / Akv (uint4 stores).
// ---------------------------------------------------------------------------
__global__ void __launch_bounds__(256) k_prep(
    const float* __restrict__ x, const float* __restrict__ mask,
    const float* __restrict__ edge, const float* __restrict__ ln1w,
    const float* __restrict__ ln1b)
{
    __shared__ float xs[128 * 33];
    __shared__ float red[264], red2[264];
    __shared__ float ms[32], mu_s[32], rs_s[32];
    __shared__ int   cy0[32], cy1[32], cx0[32], cx1[32];
    __shared__ float cwy[32], cwx[32];
    __shared__ float w1s[128], b1s[128];

    int p0 = blockIdx.x * 32;
    int b = p0 / HW, hw0 = p0 % HW;
    const float* xb = x + (size_t)b * PB;
    if (threadIdx.x < 128) { w1s[threadIdx.x] = ln1w[threadIdx.x]; b1s[threadIdx.x] = ln1b[threadIdx.x]; }

    for (int e = threadIdx.x; e < 4096; e += 256) {
        int c = e >> 5, px = e & 31;
        xs[c * 33 + px] = xb[(size_t)c * HW + hw0 + px];
    }
    if (threadIdx.x < 32) {
        int px = threadIdx.x;
        int hw = hw0 + px;
        int h2 = hw / 176, w2 = hw % 176;
        float fy = 0.25f * h2 - 0.375f; int iy = (int)floorf(fy); float ty = fy - iy;
        float fx = 0.25f * w2 - 0.375f; int ix = (int)floorf(fx); float tx = fx - ix;
        int y0 = iy < 0 ? 0 : iy, y1 = (iy + 1 > 43) ? 43 : iy + 1;
        int x0 = ix < 0 ? 0 : ix, x1 = (ix + 1 > 43) ? 43 : ix + 1;
        cy0[px] = y0; cy1[px] = y1; cx0[px] = x0; cx1[px] = x1;
        cwy[px] = ty; cwx[px] = tx;
        const float* mb = mask + b * NWIN;
        ms[px] = (1.f - ty) * ((1.f - tx) * mb[y0 * 44 + x0] + tx * mb[y0 * 44 + x1])
               +        ty  * ((1.f - tx) * mb[y1 * 44 + x0] + tx * mb[y1 * 44 + x1]);
    }
    __syncthreads();
    {
        int px = threadIdx.x & 31, j = threadIdx.x >> 5;
        float s = 0.f, s2 = 0.f;
        #pragma unroll
        for (int i = 0; i < 16; i++) {
            float v = xs[(j * 16 + i) * 33 + px];
            s += v; s2 += v * v;
        }
        red[j * 33 + px] = s; red2[j * 33 + px] = s2;
    }
    __syncthreads();
    if (threadIdx.x < 32) {
        int px = threadIdx.x; float s = 0.f, s2 = 0.f;
        #pragma unroll
        for (int j = 0; j < 8; j++) { s += red[j * 33 + px]; s2 += red2[j * 33 + px]; }
        float mu = s * (1.f / 128.f);
        float var = s2 * (1.f / 128.f) - mu * mu;
        mu_s[px] = mu; rs_s[px] = rsqrtf(var + 1e-5f);
    }
    __syncthreads();

    int px = threadIdx.x & 31, j = threadIdx.x >> 5;   // j = stage 0..7
    int p = p0 + px;
    size_t tbase = (size_t)(p >> 7) * 8192 + (size_t)j * 1024 + (size_t)(p & 127) * 8;
    {
        float mu = mu_s[px], rs = rs_s[px], m = ms[px];
        unsigned q[8];
        #pragma unroll
        for (int ii = 0; ii < 8; ii++) {
            int c = j * 16 + 2 * ii;
            float v0 = ((xs[c * 33 + px] - mu) * rs * w1s[c] + b1s[c]) * m;
            float v1 = ((xs[(c + 1) * 33 + px] - mu) * rs * w1s[c + 1] + b1s[c + 1]) * m;
            q[ii] = pk(v0, v1);
        }
        uint4* dst = (uint4*)(g_u + OFF_AKV + tbase);
        dst[0] = make_uint4(q[0], q[1], q[2], q[3]);
        dst[1] = make_uint4(q[4], q[5], q[6], q[7]);
    }
    __syncthreads();
    for (int e = threadIdx.x; e < 4096; e += 256) {
        int c = e >> 5, px2 = e & 31;
        const float* eb = edge + ((size_t)b * 128 + c) * NWIN;
        float ty = cwy[px2], tx = cwx[px2];
        float v = (1.f - ty) * ((1.f - tx) * eb[cy0[px2] * 44 + cx0[px2]] + tx * eb[cy0[px2] * 44 + cx1[px2]])
                +        ty  * ((1.f - tx) * eb[cy1[px2] * 44 + cx0[px2]] + tx * eb[cy1[px2] * 44 + cx1[px2]]);
        xs[c * 33 + px2] = v;
    }
    __syncthreads();
    {
        unsigned q[8];
        #pragma unroll
        for (int ii = 0; ii < 8; ii++) {
            int c = j * 16 + 2 * ii;
            q[ii] = pk(xs[c * 33 + px], xs[(c + 1) * 33 + px]);
        }
        uint4* dst = (uint4*)(g_u + OFF_AQ + tbase);
        dst[0] = make_uint4(q[0], q[1], q[2], q[3]);
        dst[1] = make_uint4(q[4], q[5], q[6], q[7]);
    }
}

// ---------------------------------------------------------------------------
// K2: bf16 MMA GEMM, cp.async 3-stage pipeline + ldmatrix (R5-proven core).
// ASRC=0: A tiled.  ASRC=1: A rows [m][256] (K=512).
// EPI=1: packed bf16x2 C [M][Nd/2] (CS=1 -> evict-first stores).
// EPI=2: fp32 + residual -> NCHW outp.
// ---------------------------------------------------------------------------
template<int NSTAGE, int ASRC, int EPI, int CS>
__global__ void __launch_bounds__(256, 2) k_mma_t(
    const unsigned* __restrict__ At, const unsigned* __restrict__ Bt,
    unsigned* __restrict__ Cu, int Nd, float* __restrict__ outp)
{
    __shared__ unsigned sm[3 * 2048];
    int tid = threadIdx.x, lane = tid & 31, warp = tid >> 5;
    int wm = warp >> 2, wn = warp & 3, t = lane & 3, g = lane >> 2;
    const unsigned* Ab;
    if (ASRC == 0) Ab = At + (size_t)blockIdx.x * (NSTAGE * 1024) + tid * 4;
    else           Ab = At + ((size_t)blockIdx.x * 128 + (tid >> 1)) * 256 + (tid & 1) * 4;
    const unsigned* Bb = Bt + (size_t)blockIdx.y * (NSTAGE * 1024) + tid * 4;
    unsigned smb = (unsigned)__cvta_generic_to_shared(sm);

    // cp.async dst (swizzled 16B rows)
    int m_ = tid >> 1, q = tid & 1;
    unsigned dA = smb + (unsigned)(2 * m_ + (q ^ ((m_ >> 2) & 1))) * 16;
    unsigned dB = dA + 4096;

    // ldmatrix fragment addresses (stage-buffer relative)
    int itemA = wm * 64 + (lane & 15);
    int khA = lane >> 4;
    unsigned aAddr = smb + (unsigned)(2 * itemA + (khA ^ ((itemA >> 2) & 1))) * 16;
    int itemB = wn * 32 + lane;
    int bbit = (itemB >> 2) & 1;
    unsigned bAddr0 = smb + 4096u + (unsigned)(2 * itemB + bbit) * 16;
    unsigned bAddr1 = smb + 4096u + (unsigned)(2 * itemB + (1 ^ bbit)) * 16;

    float acc[4][4][4];
    #pragma unroll
    for (int i = 0; i < 4; i++)
        #pragma unroll
        for (int j = 0; j < 4; j++)
            #pragma unroll
            for (int k = 0; k < 4; k++) acc[i][j][k] = 0.f;

    #pragma unroll
    for (int s = 0; s < 2; s++) {
        unsigned off = s * 8192u;
        cpa16(dA + off, Ab + (ASRC == 0 ? s * 1024 : s * 8));
        cpa16(dB + off, Bb + s * 1024);
        CP_COMMIT();
    }

    for (int s = 0; s < NSTAGE; s++) {
        if (s + 1 < NSTAGE) CP_WAIT1(); else CP_WAIT0();
        __syncthreads();
        unsigned buf = (unsigned)(s % 3) * 8192u;
        unsigned af[4][4], bf[4][2];
        ldsm4(bf[0][0], bf[1][0], bf[2][0], bf[3][0], bAddr0 + buf);
        ldsm4(bf[0][1], bf[1][1], bf[2][1], bf[3][1], bAddr1 + buf);
        #pragma unroll
        for (int tm = 0; tm < 4; tm++)
            ldsm4(af[tm][0], af[tm][1], af[tm][2], af[tm][3], aAddr + buf + tm * 512u);
        #pragma unroll
        for (int tm = 0; tm < 4; tm++)
            #pragma unroll
            for (int tn = 0; tn < 4; tn++)
                mma16(acc[tm][tn], af[tm], bf[tn]);
        if (s + 2 < NSTAGE) {
            unsigned off = (unsigned)((s + 2) % 3) * 8192u;
            cpa16(dA + off, Ab + (ASRC == 0 ? (s + 2) * 1024 : (s + 2) * 8));
            cpa16(dB + off, Bb + (s + 2) * 1024);
            CP_COMMIT();
        }
        __syncthreads();
    }

    int m0 = blockIdx.x * 128, n0 = blockIdx.y * 128;
    if (EPI == 1) {
        int np = Nd >> 1;
        #pragma unroll
        for (int tm = 0; tm < 4; tm++)
            #pragma unroll
            for (int tn = 0; tn < 4; tn++) {
                int m = m0 + wm * 64 + tm * 16 + g;
                int n = n0 + wn * 32 + tn * 8 + 2 * t;
                unsigned v0 = pk(acc[tm][tn][0], acc[tm][tn][1]);
                unsigned v1 = pk(acc[tm][tn][2], acc[tm][tn][3]);
                if (CS) {
                    stg_cs(Cu + (size_t)m * np + (n >> 1), v0);
                    stg_cs(Cu + (size_t)(m + 8) * np + (n >> 1), v1);
                } else {
                    Cu[(size_t)m * np + (n >> 1)] = v0;
                    Cu[(size_t)(m + 8) * np + (n >> 1)] = v1;
                }
            }
    } else {
        const float* x1 = (const float*)(g_u + OFF_X1);
        int b = m0 / HW, hw0 = m0 % HW;
        #pragma unroll
        for (int tm = 0; tm < 4; tm++)
            #pragma unroll
            for (int tn = 0; tn < 4; tn++) {
                int mrow = wm * 64 + tm * 16 + g;
                int n = wn * 32 + tn * 8 + 2 * t;
                size_t a0 = ((size_t)b * 128 + n) * HW + hw0 + mrow;
                outp[a0]          = x1[a0] + acc[tm][tn][0];
                outp[a0 + HW]     = x1[a0 + HW] + acc[tm][tn][1];
                outp[a0 + 8]      = x1[a0 + 8] + acc[tm][tn][2];
                outp[a0 + HW + 8] = x1[a0 + HW + 8] + acc[tm][tn][3];
            }
    }
}

// ---------------------------------------------------------------------------
// K3: per-(window,token) channel attention + FUSED residual:
// x1 = x + attn_out (merged layout == flat NCHW identity).
// ---------------------------------------------------------------------------
__global__ void __launch_bounds__(256) k_attn(const float* __restrict__ x)
{
    __shared__ float outs[32 * 129];
    __shared__ float buf[8 * 640];
    int bid = blockIdx.x;
    int chunk = bid % 61;
    int n = (bid / 61) % 16;
    int b = bid / (61 * 16);
    int ihw0 = chunk * 32;
    const unsigned* Qp  = g_u + OFF_Q;
    const unsigned* KVp = g_u + OFF_KV;
    float* x1 = (float*)(g_u + OFF_X1);
    int warp = threadIdx.x >> 5, lane = threadIdx.x & 31;
    float* qs = buf + warp * 640;
    float* ks = qs + 128;
    float* vs = qs + 256;
    float* ds = qs + 384;

    for (int it = 0; it < 4; it++) {
        int g = it * 8 + warp;
        int ihw = ihw0 + g;
        if (ihw < NWIN) {
            int ih = ihw / 44, iw = ihw % 44;
            int h2 = ih * 4 + (n >> 2), w2 = iw * 4 + (n & 3);
            size_t p = (size_t)b * HW + (size_t)h2 * 176 + w2;
            {
                int i = lane;
                float2 vq = bf2f(Qp[p * 64 + i]);
                qs[2 * i] = vq.x; qs[2 * i + 1] = vq.y;
                float2 vq2 = bf2f(Qp[p * 64 + 32 + i]);
                qs[64 + 2 * i] = vq2.x; qs[65 + 2 * i] = vq2.y;
                float2 k1 = bf2f(KVp[p * 128 + i]);
                ks[2 * i] = k1.x; ks[2 * i + 1] = k1.y;
                float2 k2 = bf2f(KVp[p * 128 + 32 + i]);
                ks[64 + 2 * i] = k2.x; ks[65 + 2 * i] = k2.y;
                float2 v1 = bf2f(KVp[p * 128 + 64 + i]);
                vs[2 * i] = v1.x; vs[2 * i + 1] = v1.y;
                float2 v2 = bf2f(KVp[p * 128 + 96 + i]);
                vs[64 + 2 * i] = v2.x; vs[65 + 2 * i] = v2.y;
            }
            __syncwarp();
            for (int e = lane; e < 256; e += 32) {
                int j = e >> 4, kk = e & 15;
                float s = 0.f;
                #pragma unroll
                for (int i = 0; i < 8; i++) s += qs[i * 16 + j] * ks[i * 16 + kk];
                ds[e] = s * 0.25f;
            }
            __syncwarp();
            if (lane < 16) {
                float mx = -1e30f;
                #pragma unroll
                for (int kk = 0; kk < 16; kk++) mx = fmaxf(mx, ds[lane * 16 + kk]);
                float sm = 0.f;
                #pragma unroll
                for (int kk = 0; kk < 16; kk++) {
                    float ev = __expf(ds[lane * 16 + kk] - mx);
                    ds[lane * 16 + kk] = ev; sm += ev;
                }
                float inv = 1.f / sm;
                #pragma unroll
                for (int kk = 0; kk < 16; kk++) ds[lane * 16 + kk] *= inv;
            }
            __syncwarp();
            for (int ch = lane; ch < 128; ch += 32) {
                int i = ch >> 4, j = ch & 15;
                float s = 0.f;
                #pragma unroll
                for (int kk = 0; kk < 16; kk++) s += ds[j * 16 + kk] * vs[i * 16 + kk];
                outs[g * 129 + ch] = s;
            }
        }
    }
    __syncthreads();
    size_t base = ((size_t)b * 2048 + (size_t)n * 128) * 1936 + ihw0;
    for (int e = threadIdx.x; e < 4096; e += 256) {
        int ch = e >> 5, g = e & 31;
        if (ihw0 + g < NWIN) {
            size_t idx = base + (size_t)ch * 1936 + g;
            x1[idx] = x[idx] + outs[g * 129 + ch];
        }
    }
}

// ---------------------------------------------------------------------------
// K4: LN2 over x1 (read-only) -> tiled X1LN packed bf16 (uint4 stores).
// ---------------------------------------------------------------------------
__global__ void __launch_bounds__(256) k_merge2(
    const float* __restrict__ ln2w, const float* __restrict__ ln2b)
{
    __shared__ float red[264], red2[264], mu_s[32], rs_s[32];
    __shared__ float w2s[128], b2s[128];
    int p0 = blockIdx.x * 32;
    int b = p0 / HW, hw0 = p0 % HW;
    int px = threadIdx.x & 31, j = threadIdx.x >> 5;
    if (threadIdx.x < 128) { w2s[threadIdx.x] = ln2w[threadIdx.x]; b2s[threadIdx.x] = ln2b[threadIdx.x]; }
    const float* x1 = (const float*)(g_u + OFF_X1);
    size_t base = (size_t)b * PB + hw0 + px;
    float v[16];
    float s = 0.f, s2 = 0.f;
    #pragma unroll
    for (int i = 0; i < 16; i++) {
        int c = j * 16 + i;
        float val = x1[base + (size_t)c * HW];
        v[i] = val; s += val; s2 += val * val;
    }
    red[j * 33 + px] = s; red2[j * 33 + px] = s2;
    __syncthreads();
    if (threadIdx.x < 32) {
        float ss = 0.f, ss2 = 0.f;
        #pragma unroll
        for (int j2 = 0; j2 < 8; j2++) { ss += red[j2 * 33 + threadIdx.x]; ss2 += red2[j2 * 33 + threadIdx.x]; }
        float mu = ss * (1.f / 128.f);
        float var = ss2 * (1.f / 128.f) - mu * mu;
        mu_s[threadIdx.x] = mu; rs_s[threadIdx.x] = rsqrtf(var + 1e-5f);
    }
    __syncthreads();
    float mu = mu_s[px], rs = rs_s[px];
    int p = p0 + px;
    unsigned qv[8];
    #pragma unroll
    for (int ii = 0; ii < 8; ii++) {
        int c = j * 16 + 2 * ii;
        float a = (v[2 * ii] - mu) * rs * w2s[c] + b2s[c];
        float bb = (v[2 * ii + 1] - mu) * rs * w2s[c + 1] + b2s[c + 1];
        qv[ii] = pk(a, bb);
    }
    uint4* dst = (uint4*)(g_u + OFF_X1LN + (size_t)(p >> 7) * 8192 + (size_t)j * 1024 + (size_t)(p & 127) * 8);
    dst[0] = make_uint4(qv[0], qv[1], qv[2], qv[3]);
    dst[1] = make_uint4(qv[4], qv[5], qv[6], qv[7]);
}

// ---------------------------------------------------------------------------
// K6: depthwise 3x3 + exact GELU gate. 4 w-columns/thread, packed-uint
// register window (rows h-1,h,h+1 x 6 cols), h-strip of 22 rows.
// ---------------------------------------------------------------------------
__device__ __forceinline__ void dw_row6(
    const unsigned* __restrict__ yin, int b, int h, int w0, int cp,
    unsigned* U, unsigned* V)
{
    #pragma unroll
    for (int dw = 0; dw < 6; dw++) { U[dw] = 0u; V[dw] = 0u; }
    if (h < 0 || h >= 176) return;
    #pragma unroll
    for (int dw = 0; dw < 6; dw++) {
        int ww = w0 - 1 + dw;
        if (ww < 0 || ww >= 176) continue;
        size_t base = ((size_t)b * HW + (size_t)h * 176 + ww) * 512;
        U[dw] = yin[base + cp];
        V[dw] = yin[base + 256 + cp];
    }
}

__global__ void __launch_bounds__(256) k_dwconv(const float* __restrict__ wdw)
{
    int cp = threadIdx.x;                 // 0..255 (channel pair)
    int blk = blockIdx.x;                 // (b*8 + hs)*44 + wg
    int wg = blk % 44;
    int hs = (blk / 44) % 8;
    int b  = blk / (44 * 8);
    int w0 = wg * 4;
    int h0 = hs * 22;
    const unsigned* yin = g_u + OFF_YIN;
    unsigned* yg = g_u + OFF_YG;
    int c0 = 2 * cp;
    float wa0[9], wa1[9], wb0[9], wb1[9];
    #pragma unroll
    for (int t = 0; t < 9; t++) {
        wa0[t] = __ldg(&wdw[c0 * 9 + t]);
        wa1[t] = __ldg(&wdw[(c0 + 1) * 9 + t]);
        wb0[t] = __ldg(&wdw[(512 + c0) * 9 + t]);
        wb1[t] = __ldg(&wdw[(513 + c0) * 9 + t]);
    }
    unsigned U[3][6], V[3][6];
    dw_row6(yin, b, h0 - 1, w0, cp, U[0], V[0]);
    dw_row6(yin, b, h0,     w0, cp, U[1], V[1]);
    dw_row6(yin, b, h0 + 1, w0, cp, U[2], V[2]);

    for (int h = h0; h < h0 + 22; h++) {
        float accA[4][2], accB[4][2];
        #pragma unroll
        for (int o = 0; o < 4; o++) {
            accA[o][0] = 0.f; accA[o][1] = 0.f;
            accB[o][0] = 0.f; accB[o][1] = 0.f;
        }
        #pragma unroll
        for (int dw = 0; dw < 6; dw++) {
            #pragma unroll
            for (int rr = 0; rr < 3; rr++) {
                float2 ua = bf2f(U[rr][dw]);
                float2 vb = bf2f(V[rr][dw]);
                #pragma unroll
                for (int o = 0; o < 4; o++) {
                    int cc = dw - o;
                    if (cc >= 0 && cc < 3) {
                        int tt = rr * 3 + cc;
                        accA[o][0] += ua.x * wa0[tt];
                        accA[o][1] += ua.y * wa1[tt];
                        accB[o][0] += vb.x * wb0[tt];
                        accB[o][1] += vb.y * wb1[tt];
                    }
                }
            }
        }
        #pragma unroll
        for (int o = 0; o < 4; o++) {
            float a0 = accA[o][0], a1 = accA[o][1];
            float e0 = 0.5f * a0 * (1.f + erff(a0 * 0.70710678118654752f));
            float e1 = 0.5f * a1 * (1.f + erff(a1 * 0.70710678118654752f));
            int p = b * HW + h * 176 + w0 + o;
            yg[(size_t)p * 256 + cp] = pk(e0 * accB[o][0], e1 * accB[o][1]);
        }
        #pragma unroll
        for (int dw = 0; dw < 6; dw++) {
            U[0][dw] = U[1][dw]; U[1][dw] = U[2][dw];
            V[0][dw] = V[1][dw]; V[1][dw] = V[2][dw];
        }
        dw_row6(yin, b, h + 2, w0, cp, U[2], V[2]);
    }
}

// ---------------------------------------------------------------------------
extern "C" void kernel_launch(void* const* d_in, const int* in_sizes, int n_in,
                              void* d_out, int out_size)
{
    const float* x    = (const float*)d_in[0];
    const float* mask = (const float*)d_in[1];
    const float* edge = (const float*)d_in[2];
    const float* ln1w = (const float*)d_in[3];
    const float* ln1b = (const float*)d_in[4];
    const float* Wq   = (const float*)d_in[5];
    const float* Wk   = (const float*)d_in[6];
    const float* Wv   = (const float*)d_in[7];
    const float* ln2w = (const float*)d_in[8];
    const float* ln2b = (const float*)d_in[9];
    const float* w_in = (const float*)d_in[10];
    const float* w_dw = (const float*)d_in[11];
    const float* w_out= (const float*)d_in[12];
    float* outp = (float*)d_out;

    unsigned* G = nullptr;
    cudaGetSymbolAddress((void**)&G, g_u);

    // K0: weights -> tiled packed bf16x2
    k_wprep<<<(122880 + 255) / 256, 256>>>(Wq, Wk, Wv, w_in, w_out);

    // K1: LN1 + resize -> tiled Aq/Akv
    k_prep<<<PTOT / 32, 256>>>(x, mask, edge, ln1w, ln1b);

    // K2: Q and fused KV bf16 GEMMs (R5 config)
    k_mma_t<8, 0, 1, 0><<<dim3(PTOT / 128, 1), 256>>>(G + OFF_AQ,  G + OFF_WB,        G + OFF_Q,  128, nullptr);
    k_mma_t<8, 0, 1, 0><<<dim3(PTOT / 128, 2), 256>>>(G + OFF_AKV, G + OFF_WB + 8192, G + OFF_KV, 256, nullptr);

    // K3: channel attention + fused residual -> x1 (fp32 NCHW)
    k_attn<<<4 * 16 * 61, 256>>>(x);

    // K4: LN2(x1) -> tiled X1LN
    k_merge2<<<PTOT / 32, 256>>>(ln2w, ln2b);

    // K5: conv1x1 128->1024 -> y_in packed bf16 (evict-first C stores)
    k_mma_t<8, 0, 1, 1><<<dim3(PTOT / 128, 8), 256>>>(G + OFF_X1LN, G + OFF_WB + 24576, G + OFF_YIN, 1024, nullptr);

    // K6: depthwise 3x3 + GELU gate -> y_g packed rows (4 w/thread, hs x8)
    k_dwconv<<<BATCH * 44 * 8, 256>>>(w_dw);

    // K7: conv1x1 512->128 + residual -> d_out (NCHW), A from rows
    k_mma_t<32, 1, 2, 0><<<dim3(PTOT / 128, 1), 256>>>(G + OFF_YG, G + OFF_WB + 90112, nullptr, 128, outp);
}

// round 10
// speedup vs baseline: 1.3096x; 1.0293x over previous
#include <cuda_runtime.h>
#include <cuda_bf16.h>
#include <math.h>

#define BATCH 4
#define HW    30976            // 176*176
#define PTOT  123904           // BATCH*HW
#define NWIN  1936             // 44*44
#define PB    3964928ULL       // per-batch plane = 128*30976

// uint-unit offsets into the single scratch buffer
#define OFF_AQ    0ULL          // tiled bf16x2, K=128 (8 stages/blk)
#define OFF_AKV   7929856ULL    // tiled bf16x2, K=128
#define OFF_AO    15859712ULL   // (unused after fusion)
#define OFF_Q     31719424ULL   // packed bf16x2 [p][64]
#define OFF_KV    47579136ULL   // packed bf16x2 [p][128] (K | V)
#define OFF_X1    79298560ULL   // fp32 NCHW residual (written by k_attn)
#define OFF_X1LN  95158272ULL   // tiled bf16x2, K=128
#define OFF_YIN   103088128ULL  // packed bf16x2 [p][512]
#define OFF_YG    166526976ULL  // packed bf16x2 [p][256]
#define OFF_WB    198246400ULL
#define TOT_U     198369280ULL

__device__ unsigned g_u[TOT_U];

// ---------------------------------------------------------------------------
// helpers
// ---------------------------------------------------------------------------
__device__ __forceinline__ unsigned pk(float lo, float hi) {
    unsigned r;
    asm("cvt.rn.bf16x2.f32 %0, %1, %2;" : "=r"(r) : "f"(hi), "f"(lo));
    return r;
}
__device__ __forceinline__ float2 bf2f(unsigned u) {
    __nv_bfloat162 h = *reinterpret_cast<__nv_bfloat162*>(&u);
    return __bfloat1622float2(h);
}
__device__ __forceinline__ void mma16(float* d, const unsigned* a, const unsigned* b) {
    asm volatile(
        "mma.sync.aligned.m16n8k16.row.col.f32.bf16.bf16.f32 "
        "{%0,%1,%2,%3},{%4,%5,%6,%7},{%8,%9},{%0,%1,%2,%3};"
        : "+f"(d[0]), "+f"(d[1]), "+f"(d[2]), "+f"(d[3])
        : "r"(a[0]), "r"(a[1]), "r"(a[2]), "r"(a[3]), "r"(b[0]), "r"(b[1]));
}
__device__ __forceinline__ void ldsm4(unsigned& r0, unsigned& r1, unsigned& r2, unsigned& r3, unsigned a) {
    asm volatile("ldmatrix.sync.aligned.m8n8.x4.shared.b16 {%0,%1,%2,%3}, [%4];"
        : "=r"(r0), "=r"(r1), "=r"(r2), "=r"(r3) : "r"(a));
}
__device__ __forceinline__ void cpa16(unsigned d, const void* s) {
    asm volatile("cp.async.cg.shared.global [%0], [%1], 16;" :: "r"(d), "l"(s));
}
__device__ __forceinline__ void stg_cs(unsigned* p, unsigned v) {
    asm volatile("st.global.cs.u32 [%0], %1;" :: "l"(p), "r"(v));
}
#define CP_COMMIT() asm volatile("cp.async.commit_group;" ::: "memory")
#define CP_WAIT2()  asm volatile("cp.async.wait_group 2;" ::: "memory")
#define CP_WAIT1()  asm volatile("cp.async.wait_group 1;" ::: "memory")
#define CP_WAIT0()  asm volatile("cp.async.wait_group 0;" ::: "memory")

// ---------------------------------------------------------------------------
// K0: weight prep -> packed bf16x2 in GEMM-tiled layout.
// WB: WqP[8192] | WKVP[16384] | WinP[65536] | WoutP[32768]
// ---------------------------------------------------------------------------
__global__ void k_wprep(const float* __restrict__ Wq, const float* __restrict__ Wk,
                        const float* __restrict__ Wv, const float* __restrict__ win,
                        const float* __restrict__ wout)
{
    int idx = blockIdx.x * 256 + threadIdx.x;
    if (idx >= 122880) return;
    unsigned* WB = g_u + OFF_WB;
    if (idx < 8192) {
        int n = idx >> 6, kp = idx & 63;
        WB[(kp >> 3) * 1024 + n * 8 + (kp & 7)] = pk(Wq[n * 128 + 2 * kp], Wq[n * 128 + 2 * kp + 1]);
    } else if (idx < 24576) {
        int j = idx - 8192; int n2 = j >> 6, kp = j & 63;
        const float* W = (n2 < 128) ? Wk : Wv;
        int n = n2 & 127;
        WB[8192 + (n2 >> 7) * 8192 + (kp >> 3) * 1024 + n * 8 + (kp & 7)]
            = pk(W[n * 128 + 2 * kp], W[n * 128 + 2 * kp + 1]);
    } else if (idx < 90112) {
        int j = idx - 24576; int n = j >> 6, kp = j & 63;
        WB[24576 + (n >> 7) * 8192 + (kp >> 3) * 1024 + (n & 127) * 8 + (kp & 7)]
            = pk(win[n * 128 + 2 * kp], win[n * 128 + 2 * kp + 1]);
    } else {
        int j = idx - 90112; int n = j >> 8, kp = j & 255;
        WB[90112 + (kp >> 3) * 1024 + n * 8 + (kp & 7)]
            = pk(wout[n * 512 + 2 * kp], wout[n * 512 + 2 * kp + 1]);
    }
}

// ---------------------------------------------------------------------------
// K1: LN1(x), bilinear mask/edge upsample -> tiled Aq / Akv (uint4 stores).
// ---------------------------------------------------------------------------
__global__ void __launch_bounds__(256) k_prep(
    const float* __restrict__ x, const float* __restrict__ mask,
    const float* __restrict__ edge, const float* __restrict__ ln1w,
    const float* __restrict__ ln1b)
{
    __shared__ float xs[128 * 33];
    __shared__ float red[264], red2[264];
    __shared__ float ms[32], mu_s[32], rs_s[32];
    __shared__ int   cy0[32], cy1[32], cx0[32], cx1[32];
    __shared__ float cwy[32], cwx[32];
    __shared__ float w1s[128], b1s[128];

    int p0 = blockIdx.x * 32;
    int b = p0 / HW, hw0 = p0 % HW;
    const float* xb = x + (size_t)b * PB;
    if (threadIdx.x < 128) { w1s[threadIdx.x] = ln1w[threadIdx.x]; b1s[threadIdx.x] = ln1b[threadIdx.x]; }

    for (int e = threadIdx.x; e < 4096; e += 256) {
        int c = e >> 5, px = e & 31;
        xs[c * 33 + px] = xb[(size_t)c * HW + hw0 + px];
    }
    if (threadIdx.x < 32) {
        int px = threadIdx.x;
        int hw = hw0 + px;
        int h2 = hw / 176, w2 = hw % 176;
        float fy = 0.25f * h2 - 0.375f; int iy = (int)floorf(fy); float ty = fy - iy;
        float fx = 0.25f * w2 - 0.375f; int ix = (int)floorf(fx); float tx = fx - ix;
        int y0 = iy < 0 ? 0 : iy, y1 = (iy + 1 > 43) ? 43 : iy + 1;
        int x0 = ix < 0 ? 0 : ix, x1 = (ix + 1 > 43) ? 43 : ix + 1;
        cy0[px] = y0; cy1[px] = y1; cx0[px] = x0; cx1[px] = x1;
        cwy[px] = ty; cwx[px] = tx;
        const float* mb = mask + b * NWIN;
        ms[px] = (1.f - ty) * ((1.f - tx) * mb[y0 * 44 + x0] + tx * mb[y0 * 44 + x1])
               +        ty  * ((1.f - tx) * mb[y1 * 44 + x0] + tx * mb[y1 * 44 + x1]);
    }
    __syncthreads();
    {
        int px = threadIdx.x & 31, j = threadIdx.x >> 5;
        float s = 0.f, s2 = 0.f;
        #pragma unroll
        for (int i = 0; i < 16; i++) {
            float v = xs[(j * 16 + i) * 33 + px];
            s += v; s2 += v * v;
        }
        red[j * 33 + px] = s; red2[j * 33 + px] = s2;
    }
    __syncthreads();
    if (threadIdx.x < 32) {
        int px = threadIdx.x; float s = 0.f, s2 = 0.f;
        #pragma unroll
        for (int j = 0; j < 8; j++) { s += red[j * 33 + px]; s2 += red2[j * 33 + px]; }
        float mu = s * (1.f / 128.f);
        float var = s2 * (1.f / 128.f) - mu * mu;
        mu_s[px] = mu; rs_s[px] = rsqrtf(var + 1e-5f);
    }
    __syncthreads();

    int px = threadIdx.x & 31, j = threadIdx.x >> 5;   // j = stage 0..7
    int p = p0 + px;
    size_t tbase = (size_t)(p >> 7) * 8192 + (size_t)j * 1024 + (size_t)(p & 127) * 8;
    {
        float mu = mu_s[px], rs = rs_s[px], m = ms[px];
        unsigned q[8];
        #pragma unroll
        for (int ii = 0; ii < 8; ii++) {
            int c = j * 16 + 2 * ii;
            float v0 = ((xs[c * 33 + px] - mu) * rs * w1s[c] + b1s[c]) * m;
            float v1 = ((xs[(c + 1) * 33 + px] - mu) * rs * w1s[c + 1] + b1s[c + 1]) * m;
            q[ii] = pk(v0, v1);
        }
        uint4* dst = (uint4*)(g_u + OFF_AKV + tbase);
        dst[0] = make_uint4(q[0], q[1], q[2], q[3]);
        dst[1] = make_uint4(q[4], q[5], q[6], q[7]);
    }
    __syncthreads();
    for (int e = threadIdx.x; e < 4096; e += 256) {
        int c = e >> 5, px2 = e & 31;
        const float* eb = edge + ((size_t)b * 128 + c) * NWIN;
        float ty = cwy[px2], tx = cwx[px2];
        float v = (1.f - ty) * ((1.f - tx) * eb[cy0[px2] * 44 + cx0[px2]] + tx * eb[cy0[px2] * 44 + cx1[px2]])
                +        ty  * ((1.f - tx) * eb[cy1[px2] * 44 + cx0[px2]] + tx * eb[cy1[px2] * 44 + cx1[px2]]);
        xs[c * 33 + px2] = v;
    }
    __syncthreads();
    {
        unsigned q[8];
        #pragma unroll
        for (int ii = 0; ii < 8; ii++) {
            int c = j * 16 + 2 * ii;
            q[ii] = pk(xs[c * 33 + px], xs[(c + 1) * 33 + px]);
        }
        uint4* dst = (uint4*)(g_u + OFF_AQ + tbase);
        dst[0] = make_uint4(q[0], q[1], q[2], q[3]);
        dst[1] = make_uint4(q[4], q[5], q[6], q[7]);
    }
}

// ---------------------------------------------------------------------------
// K2: bf16 MMA GEMM, 4-buffer cp.async pipeline (3 in flight) + ldmatrix,
// ONE barrier per stage. Correct tail waits (R6 bug fixed).
// ASRC=0: A tiled.  ASRC=1: A rows [m][256] (K=512).
// EPI=1: packed bf16x2 C [M][Nd/2] (CS=1 -> evict-first stores).
// EPI=2: fp32 + residual -> NCHW outp.
// ---------------------------------------------------------------------------
template<int NSTAGE, int ASRC, int EPI, int CS>
__global__ void __launch_bounds__(256, 2) k_mma_t(
    const unsigned* __restrict__ At, const unsigned* __restrict__ Bt,
    unsigned* __restrict__ Cu, int Nd, float* __restrict__ outp)
{
    __shared__ unsigned sm[4 * 2048];
    int tid = threadIdx.x, lane = tid & 31, warp = tid >> 5;
    int wm = warp >> 2, wn = warp & 3, t = lane & 3, g = lane >> 2;
    const unsigned* Ab;
    if (ASRC == 0) Ab = At + (size_t)blockIdx.x * (NSTAGE * 1024) + tid * 4;
    else           Ab = At + ((size_t)blockIdx.x * 128 + (tid >> 1)) * 256 + (tid & 1) * 4;
    const unsigned* Bb = Bt + (size_t)blockIdx.y * (NSTAGE * 1024) + tid * 4;
    unsigned smb = (unsigned)__cvta_generic_to_shared(sm);

    // cp.async dst (swizzled 16B rows)
    int m_ = tid >> 1, q = tid & 1;
    unsigned dA = smb + (unsigned)(2 * m_ + (q ^ ((m_ >> 2) & 1))) * 16;
    unsigned dB = dA + 4096;

    // ldmatrix fragment addresses (stage-buffer relative)
    int itemA = wm * 64 + (lane & 15);
    int khA = lane >> 4;
    unsigned aAddr = smb + (unsigned)(2 * itemA + (khA ^ ((itemA >> 2) & 1))) * 16;
    int itemB = wn * 32 + lane;
    int bbit = (itemB >> 2) & 1;
    unsigned bAddr0 = smb + 4096u + (unsigned)(2 * itemB + bbit) * 16;
    unsigned bAddr1 = smb + 4096u + (unsigned)(2 * itemB + (1 ^ bbit)) * 16;

    float acc[4][4][4];
    #pragma unroll
    for (int i = 0; i < 4; i++)
        #pragma unroll
        for (int j = 0; j < 4; j++)
            #pragma unroll
            for (int k = 0; k < 4; k++) acc[i][j][k] = 0.f;

    // prologue: stages 0..2 (3 in flight)
    #pragma unroll
    for (int s = 0; s < 3; s++) {
        if (s < NSTAGE) {
            unsigned off = s * 8192u;
            cpa16(dA + off, Ab + (ASRC == 0 ? s * 1024 : s * 8));
            cpa16(dB + off, Bb + s * 1024);
        }
        CP_COMMIT();
    }

    for (int s = 0; s < NSTAGE; s++) {
        // commits so far = min(s+3, NSTAGE); need group #s complete.
        if (s + 3 <= NSTAGE) CP_WAIT2();
        else if (s + 2 == NSTAGE) CP_WAIT1();
        else CP_WAIT0();
        __syncthreads();
        unsigned buf = (unsigned)(s & 3) * 8192u;
        unsigned af[4][4], bf[4][2];
        ldsm4(bf[0][0], bf[1][0], bf[2][0], bf[3][0], bAddr0 + buf);
        ldsm4(bf[0][1], bf[1][1], bf[2][1], bf[3][1], bAddr1 + buf);
        #pragma unroll
        for (int tm = 0; tm < 4; tm++)
            ldsm4(af[tm][0], af[tm][1], af[tm][2], af[tm][3], aAddr + buf + tm * 512u);
        #pragma unroll
        for (int tm = 0; tm < 4; tm++)
            #pragma unroll
            for (int tn = 0; tn < 4; tn++)
                mma16(acc[tm][tn], af[tm], bf[tn]);
        if (s + 3 < NSTAGE) {
            unsigned off = (unsigned)((s + 3) & 3) * 8192u;
            cpa16(dA + off, Ab + (ASRC == 0 ? (s + 3) * 1024 : (s + 3) * 8));
            cpa16(dB + off, Bb + (s + 3) * 1024);
        }
        CP_COMMIT();
    }

    int m0 = blockIdx.x * 128, n0 = blockIdx.y * 128;
    if (EPI == 1) {
        int np = Nd >> 1;
        #pragma unroll
        for (int tm = 0; tm < 4; tm++)
            #pragma unroll
            for (int tn = 0; tn < 4; tn++) {
                int m = m0 + wm * 64 + tm * 16 + g;
                int n = n0 + wn * 32 + tn * 8 + 2 * t;
                unsigned v0 = pk(acc[tm][tn][0], acc[tm][tn][1]);
                unsigned v1 = pk(acc[tm][tn][2], acc[tm][tn][3]);
                if (CS) {
                    stg_cs(Cu + (size_t)m * np + (n >> 1), v0);
                    stg_cs(Cu + (size_t)(m + 8) * np + (n >> 1), v1);
                } else {
                    Cu[(size_t)m * np + (n >> 1)] = v0;
                    Cu[(size_t)(m + 8) * np + (n >> 1)] = v1;
                }
            }
    } else {
        const float* x1 = (const float*)(g_u + OFF_X1);
        int b = m0 / HW, hw0 = m0 % HW;
        #pragma unroll
        for (int tm = 0; tm < 4; tm++)
            #pragma unroll
            for (int tn = 0; tn < 4; tn++) {
                int mrow = wm * 64 + tm * 16 + g;
                int n = wn * 32 + tn * 8 + 2 * t;
                size_t a0 = ((size_t)b * 128 + n) * HW + hw0 + mrow;
                outp[a0]          = x1[a0] + acc[tm][tn][0];
                outp[a0 + HW]     = x1[a0 + HW] + acc[tm][tn][1];
                outp[a0 + 8]      = x1[a0 + 8] + acc[tm][tn][2];
                outp[a0 + HW + 8] = x1[a0 + HW + 8] + acc[tm][tn][3];
            }
    }
}

// ---------------------------------------------------------------------------
// K3: per-(window,token) channel attention + FUSED residual:
// x1 = x + attn_out (merged layout == flat NCHW identity).
// ---------------------------------------------------------------------------
__global__ void __launch_bounds__(256) k_attn(const float* __restrict__ x)
{
    __shared__ float outs[32 * 129];
    __shared__ float buf[8 * 640];
    int bid = blockIdx.x;
    int chunk = bid % 61;
    int n = (bid / 61) % 16;
    int b = bid / (61 * 16);
    int ihw0 = chunk * 32;
    const unsigned* Qp  = g_u + OFF_Q;
    const unsigned* KVp = g_u + OFF_KV;
    float* x1 = (float*)(g_u + OFF_X1);
    int warp = threadIdx.x >> 5, lane = threadIdx.x & 31;
    float* qs = buf + warp * 640;
    float* ks = qs + 128;
    float* vs = qs + 256;
    float* ds = qs + 384;

    for (int it = 0; it < 4; it++) {
        int g = it * 8 + warp;
        int ihw = ihw0 + g;
        if (ihw < NWIN) {
            int ih = ihw / 44, iw = ihw % 44;
            int h2 = ih * 4 + (n >> 2), w2 = iw * 4 + (n & 3);
            size_t p = (size_t)b * HW + (size_t)h2 * 176 + w2;
            {
                int i = lane;
                float2 vq = bf2f(Qp[p * 64 + i]);
                qs[2 * i] = vq.x; qs[2 * i + 1] = vq.y;
                float2 vq2 = bf2f(Qp[p * 64 + 32 + i]);
                qs[64 + 2 * i] = vq2.x; qs[65 + 2 * i] = vq2.y;
                float2 k1 = bf2f(KVp[p * 128 + i]);
                ks[2 * i] = k1.x; ks[2 * i + 1] = k1.y;
                float2 k2 = bf2f(KVp[p * 128 + 32 + i]);
                ks[64 + 2 * i] = k2.x; ks[65 + 2 * i] = k2.y;
                float2 v1 = bf2f(KVp[p * 128 + 64 + i]);
                vs[2 * i] = v1.x; vs[2 * i + 1] = v1.y;
                float2 v2 = bf2f(KVp[p * 128 + 96 + i]);
                vs[64 + 2 * i] = v2.x; vs[65 + 2 * i] = v2.y;
            }
            __syncwarp();
            for (int e = lane; e < 256; e += 32) {
                int j = e >> 4, kk = e & 15;
                float s = 0.f;
                #pragma unroll
                for (int i = 0; i < 8; i++) s += qs[i * 16 + j] * ks[i * 16 + kk];
                ds[e] = s * 0.25f;
            }
            __syncwarp();
            if (lane < 16) {
                float mx = -1e30f;
                #pragma unroll
                for (int kk = 0; kk < 16; kk++) mx = fmaxf(mx, ds[lane * 16 + kk]);
                float sm = 0.f;
                #pragma unroll
                for (int kk = 0; kk < 16; kk++) {
                    float ev = __expf(ds[lane * 16 + kk] - mx);
                    ds[lane * 16 + kk] = ev; sm += ev;
                }
                float inv = 1.f / sm;
                #pragma unroll
                for (int kk = 0; kk < 16; kk++) ds[lane * 16 + kk] *= inv;
            }
            __syncwarp();
            for (int ch = lane; ch < 128; ch += 32) {
                int i = ch >> 4, j = ch & 15;
                float s = 0.f;
                #pragma unroll
                for (int kk = 0; kk < 16; kk++) s += ds[j * 16 + kk] * vs[i * 16 + kk];
                outs[g * 129 + ch] = s;
            }
        }
    }
    __syncthreads();
    size_t base = ((size_t)b * 2048 + (size_t)n * 128) * 1936 + ihw0;
    for (int e = threadIdx.x; e < 4096; e += 256) {
        int ch = e >> 5, g = e & 31;
        if (ihw0 + g < NWIN) {
            size_t idx = base + (size_t)ch * 1936 + g;
            x1[idx] = x[idx] + outs[g * 129 + ch];
        }
    }
}

// ---------------------------------------------------------------------------
// K4: LN2 over x1 (read-only) -> tiled X1LN packed bf16 (uint4 stores).
// ---------------------------------------------------------------------------
__global__ void __launch_bounds__(256) k_merge2(
    const float* __restrict__ ln2w, const float* __restrict__ ln2b)
{
    __shared__ float red[264], red2[264], mu_s[32], rs_s[32];
    __shared__ float w2s[128], b2s[128];
    int p0 = blockIdx.x * 32;
    int b = p0 / HW, hw0 = p0 % HW;
    int px = threadIdx.x & 31, j = threadIdx.x >> 5;
    if (threadIdx.x < 128) { w2s[threadIdx.x] = ln2w[threadIdx.x]; b2s[threadIdx.x] = ln2b[threadIdx.x]; }
    const float* x1 = (const float*)(g_u + OFF_X1);
    size_t base = (size_t)b * PB + hw0 + px;
    float v[16];
    float s = 0.f, s2 = 0.f;
    #pragma unroll
    for (int i = 0; i < 16; i++) {
        int c = j * 16 + i;
        float val = x1[base + (size_t)c * HW];
        v[i] = val; s += val; s2 += val * val;
    }
    red[j * 33 + px] = s; red2[j * 33 + px] = s2;
    __syncthreads();
    if (threadIdx.x < 32) {
        float ss = 0.f, ss2 = 0.f;
        #pragma unroll
        for (int j2 = 0; j2 < 8; j2++) { ss += red[j2 * 33 + threadIdx.x]; ss2 += red2[j2 * 33 + threadIdx.x]; }
        float mu = ss * (1.f / 128.f);
        float var = ss2 * (1.f / 128.f) - mu * mu;
        mu_s[threadIdx.x] = mu; rs_s[threadIdx.x] = rsqrtf(var + 1e-5f);
    }
    __syncthreads();
    float mu = mu_s[px], rs = rs_s[px];
    int p = p0 + px;
    unsigned qv[8];
    #pragma unroll
    for (int ii = 0; ii < 8; ii++) {
        int c = j * 16 + 2 * ii;
        float a = (v[2 * ii] - mu) * rs * w2s[c] + b2s[c];
        float bb = (v[2 * ii + 1] - mu) * rs * w2s[c + 1] + b2s[c + 1];
        qv[ii] = pk(a, bb);
    }
    uint4* dst = (uint4*)(g_u + OFF_X1LN + (size_t)(p >> 7) * 8192 + (size_t)j * 1024 + (size_t)(p & 127) * 8);
    dst[0] = make_uint4(qv[0], qv[1], qv[2], qv[3]);
    dst[1] = make_uint4(qv[4], qv[5], qv[6], qv[7]);
}

// ---------------------------------------------------------------------------
// K6: depthwise 3x3 + exact GELU gate. 4 w-columns/thread, packed-uint
// register window (rows h-1,h,h+1 x 6 cols), h-strip of 22 rows.
// ---------------------------------------------------------------------------
__device__ __forceinline__ void dw_row6(
    const unsigned* __restrict__ yin, int b, int h, int w0, int cp,
    unsigned* U, unsigned* V)
{
    #pragma unroll
    for (int dw = 0; dw < 6; dw++) { U[dw] = 0u; V[dw] = 0u; }
    if (h < 0 || h >= 176) return;
    #pragma unroll
    for (int dw = 0; dw < 6; dw++) {
        int ww = w0 - 1 + dw;
        if (ww < 0 || ww >= 176) continue;
        size_t base = ((size_t)b * HW + (size_t)h * 176 + ww) * 512;
        U[dw] = yin[base + cp];
        V[dw] = yin[base + 256 + cp];
    }
}

__global__ void __launch_bounds__(256) k_dwconv(const float* __restrict__ wdw)
{
    int cp = threadIdx.x;                 // 0..255 (channel pair)
    int blk = blockIdx.x;                 // (b*8 + hs)*44 + wg
    int wg = blk % 44;
    int hs = (blk / 44) % 8;
    int b  = blk / (44 * 8);
    int w0 = wg * 4;
    int h0 = hs * 22;
    const unsigned* yin = g_u + OFF_YIN;
    unsigned* yg = g_u + OFF_YG;
    int c0 = 2 * cp;
    float wa0[9], wa1[9], wb0[9], wb1[9];
    #pragma unroll
    for (int t = 0; t < 9; t++) {
        wa0[t] = __ldg(&wdw[c0 * 9 + t]);
        wa1[t] = __ldg(&wdw[(c0 + 1) * 9 + t]);
        wb0[t] = __ldg(&wdw[(512 + c0) * 9 + t]);
        wb1[t] = __ldg(&wdw[(513 + c0) * 9 + t]);
    }
    unsigned U[3][6], V[3][6];
    dw_row6(yin, b, h0 - 1, w0, cp, U[0], V[0]);
    dw_row6(yin, b, h0,     w0, cp, U[1], V[1]);
    dw_row6(yin, b, h0 + 1, w0, cp, U[2], V[2]);

    for (int h = h0; h < h0 + 22; h++) {
        float accA[4][2], accB[4][2];
        #pragma unroll
        for (int o = 0; o < 4; o++) {
            accA[o][0] = 0.f; accA[o][1] = 0.f;
            accB[o][0] = 0.f; accB[o][1] = 0.f;
        }
        #pragma unroll
        for (int dw = 0; dw < 6; dw++) {
            #pragma unroll
            for (int rr = 0; rr < 3; rr++) {
                float2 ua = bf2f(U[rr][dw]);
                float2 vb = bf2f(V[rr][dw]);
                #pragma unroll
                for (int o = 0; o < 4; o++) {
                    int cc = dw - o;
                    if (cc >= 0 && cc < 3) {
                        int tt = rr * 3 + cc;
                        accA[o][0] += ua.x * wa0[tt];
                        accA[o][1] += ua.y * wa1[tt];
                        accB[o][0] += vb.x * wb0[tt];
                        accB[o][1] += vb.y * wb1[tt];
                    }
                }
            }
        }
        #pragma unroll
        for (int o = 0; o < 4; o++) {
            float a0 = accA[o][0], a1 = accA[o][1];
            float e0 = 0.5f * a0 * (1.f + erff(a0 * 0.70710678118654752f));
            float e1 = 0.5f * a1 * (1.f + erff(a1 * 0.70710678118654752f));
            int p = b * HW + h * 176 + w0 + o;
            yg[(size_t)p * 256 + cp] = pk(e0 * accB[o][0], e1 * accB[o][1]);
        }
        #pragma unroll
        for (int dw = 0; dw < 6; dw++) {
            U[0][dw] = U[1][dw]; U[1][dw] = U[2][dw];
            V[0][dw] = V[1][dw]; V[1][dw] = V[2][dw];
        }
        dw_row6(yin, b, h + 2, w0, cp, U[2], V[2]);
    }
}

// ---------------------------------------------------------------------------
extern "C" void kernel_launch(void* const* d_in, const int* in_sizes, int n_in,
                              void* d_out, int out_size)
{
    const float* x    = (const float*)d_in[0];
    const float* mask = (const float*)d_in[1];
    const float* edge = (const float*)d_in[2];
    const float* ln1w = (const float*)d_in[3];
    const float* ln1b = (const float*)d_in[4];
    const float* Wq   = (const float*)d_in[5];
    const float* Wk   = (const float*)d_in[6];
    const float* Wv   = (const float*)d_in[7];
    const float* ln2w = (const float*)d_in[8];
    const float* ln2b = (const float*)d_in[9];
    const float* w_in = (const float*)d_in[10];
    const float* w_dw = (const float*)d_in[11];
    const float* w_out= (const float*)d_in[12];
    float* outp = (float*)d_out;

    unsigned* G = nullptr;
    cudaGetSymbolAddress((void**)&G, g_u);

    // K0: weights -> tiled packed bf16x2
    k_wprep<<<(122880 + 255) / 256, 256>>>(Wq, Wk, Wv, w_in, w_out);

    // K1: LN1 + resize -> tiled Aq/Akv
    k_prep<<<PTOT / 32, 256>>>(x, mask, edge, ln1w, ln1b);

    // K2: Q and fused KV bf16 GEMMs
    k_mma_t<8, 0, 1, 0><<<dim3(PTOT / 128, 1), 256>>>(G + OFF_AQ,  G + OFF_WB,        G + OFF_Q,  128, nullptr);
    k_mma_t<8, 0, 1, 0><<<dim3(PTOT / 128, 2), 256>>>(G + OFF_AKV, G + OFF_WB + 8192, G + OFF_KV, 256, nullptr);

    // K3: channel attention + fused residual -> x1 (fp32 NCHW)
    k_attn<<<4 * 16 * 61, 256>>>(x);

    // K4: LN2(x1) -> tiled X1LN
    k_merge2<<<PTOT / 32, 256>>>(ln2w, ln2b);

    // K5: conv1x1 128->1024 -> y_in packed bf16 (evict-first C stores)
    k_mma_t<8, 0, 1, 1><<<dim3(PTOT / 128, 8), 256>>>(G + OFF_X1LN, G + OFF_WB + 24576, G + OFF_YIN, 1024, nullptr);

    // K6: depthwise 3x3 + GELU gate -> y_g packed rows (4 w/thread, hs x8)
    k_dwconv<<<BATCH * 44 * 8, 256>>>(w_dw);

    // K7: conv1x1 512->128 + residual -> d_out (NCHW), A from rows
    k_mma_t<32, 1, 2, 0><<<dim3(PTOT / 128, 1), 256>>>(G + OFF_YG, G + OFF_WB + 90112, nullptr, 128, outp);
}

// round 12
// speedup vs baseline: 1.3296x; 1.0153x over previous
#include <cuda_runtime.h>
#include <cuda_bf16.h>
#include <math.h>

#define BATCH 4
#define HW    30976            // 176*176
#define PTOT  123904           // BATCH*HW
#define NWIN  1936             // 44*44
#define PB    3964928ULL       // per-batch plane = 128*30976

// uint-unit offsets into the single scratch buffer
#define OFF_AQ    0ULL          // tiled bf16x2, K=128 (8 stages/blk)
#define OFF_AKV   7929856ULL    // tiled bf16x2, K=128
#define OFF_Q     31719424ULL   // packed bf16x2 [p][64]
#define OFF_KV    47579136ULL   // packed bf16x2 [p][128] (K | V)
#define OFF_X1    79298560ULL   // fp32 NCHW residual (written by k_attn)
#define OFF_X1LN  95158272ULL   // tiled bf16x2, K=128
#define OFF_YIN   103088128ULL  // packed bf16x2 [p][512]
#define OFF_YG    166526976ULL  // packed bf16x2 [p][256]
#define OFF_WB    198246400ULL
#define TOT_U     198369280ULL

__device__ unsigned g_u[TOT_U];

// ---------------------------------------------------------------------------
// helpers
// ---------------------------------------------------------------------------
__device__ __forceinline__ unsigned pk(float lo, float hi) {
    unsigned r;
    asm("cvt.rn.bf16x2.f32 %0, %1, %2;" : "=r"(r) : "f"(hi), "f"(lo));
    return r;
}
__device__ __forceinline__ float2 bf2f(unsigned u) {
    __nv_bfloat162 h = *reinterpret_cast<__nv_bfloat162*>(&u);
    return __bfloat1622float2(h);
}
__device__ __forceinline__ void mma16(float* d, const unsigned* a, const unsigned* b) {
    asm volatile(
        "mma.sync.aligned.m16n8k16.row.col.f32.bf16.bf16.f32 "
        "{%0,%1,%2,%3},{%4,%5,%6,%7},{%8,%9},{%0,%1,%2,%3};"
        : "+f"(d[0]), "+f"(d[1]), "+f"(d[2]), "+f"(d[3])
        : "r"(a[0]), "r"(a[1]), "r"(a[2]), "r"(a[3]), "r"(b[0]), "r"(b[1]));
}
__device__ __forceinline__ void ldsm4(unsigned& r0, unsigned& r1, unsigned& r2, unsigned& r3, unsigned a) {
    asm volatile("ldmatrix.sync.aligned.m8n8.x4.shared.b16 {%0,%1,%2,%3}, [%4];"
        : "=r"(r0), "=r"(r1), "=r"(r2), "=r"(r3) : "r"(a));
}
__device__ __forceinline__ void cpa16(unsigned d, const void* s) {
    asm volatile("cp.async.cg.shared.global [%0], [%1], 16;" :: "r"(d), "l"(s));
}
__device__ __forceinline__ void stg_cs(unsigned* p, unsigned v) {
    asm volatile("st.global.cs.u32 [%0], %1;" :: "l"(p), "r"(v));
}
#define CP_COMMIT() asm volatile("cp.async.commit_group;" ::: "memory")
#define CP_WAIT2()  asm volatile("cp.async.wait_group 2;" ::: "memory")
#define CP_WAIT1()  asm volatile("cp.async.wait_group 1;" ::: "memory")
#define CP_WAIT0()  asm volatile("cp.async.wait_group 0;" ::: "memory")

// packed f32x2 helpers (sm_100-family PTX, not arch-accelerated)
__device__ __forceinline__ unsigned long long u2f2(unsigned u) {
    unsigned lo = u << 16, hi = u & 0xFFFF0000u;
    unsigned long long r;
    asm("mov.b64 %0, {%1,%2};" : "=l"(r) : "r"(lo), "r"(hi));
    return r;
}
__device__ __forceinline__ unsigned long long pkf2(float lo, float hi) {
    unsigned long long r;
    asm("mov.b64 %0, {%1,%2};" : "=l"(r) : "f"(lo), "f"(hi));
    return r;
}
__device__ __forceinline__ unsigned long long ffma2(
    unsigned long long a, unsigned long long b, unsigned long long c) {
    unsigned long long d;
    asm("fma.rn.f32x2 %0, %1, %2, %3;" : "=l"(d) : "l"(a), "l"(b), "l"(c));
    return d;
}
__device__ __forceinline__ void unf2(unsigned long long v, float& lo, float& hi) {
    asm("mov.b64 {%0,%1}, %2;" : "=f"(lo), "=f"(hi) : "l"(v));
}

// ---------------------------------------------------------------------------
// K0: weight prep -> packed bf16x2 in GEMM-tiled layout.
// WB: WqP[8192] | WKVP[16384] | WinP[65536] | WoutP[32768]
// ---------------------------------------------------------------------------
__global__ void k_wprep(const float* __restrict__ Wq, const float* __restrict__ Wk,
                        const float* __restrict__ Wv, const float* __restrict__ win,
                        const float* __restrict__ wout)
{
    int idx = blockIdx.x * 256 + threadIdx.x;
    if (idx >= 122880) return;
    unsigned* WB = g_u + OFF_WB;
    if (idx < 8192) {
        int n = idx >> 6, kp = idx & 63;
        WB[(kp >> 3) * 1024 + n * 8 + (kp & 7)] = pk(Wq[n * 128 + 2 * kp], Wq[n * 128 + 2 * kp + 1]);
    } else if (idx < 24576) {
        int j = idx - 8192; int n2 = j >> 6, kp = j & 63;
        const float* W = (n2 < 128) ? Wk : Wv;
        int n = n2 & 127;
        WB[8192 + (n2 >> 7) * 8192 + (kp >> 3) * 1024 + n * 8 + (kp & 7)]
            = pk(W[n * 128 + 2 * kp], W[n * 128 + 2 * kp + 1]);
    } else if (idx < 90112) {
        int j = idx - 24576; int n = j >> 6, kp = j & 63;
        WB[24576 + (n >> 7) * 8192 + (kp >> 3) * 1024 + (n & 127) * 8 + (kp & 7)]
            = pk(win[n * 128 + 2 * kp], win[n * 128 + 2 * kp + 1]);
    } else {
        int j = idx - 90112; int n = j >> 8, kp = j & 255;
        WB[90112 + (kp >> 3) * 1024 + n * 8 + (kp & 7)]
            = pk(wout[n * 512 + 2 * kp], wout[n * 512 + 2 * kp + 1]);
    }
}

// ---------------------------------------------------------------------------
// K1: LN1(x), bilinear mask/edge upsample -> tiled Aq / Akv (uint4 stores).
// ---------------------------------------------------------------------------
__global__ void __launch_bounds__(256) k_prep(
    const float* __restrict__ x, const float* __restrict__ mask,
    const float* __restrict__ edge, const float* __restrict__ ln1w,
    const float* __restrict__ ln1b)
{
    __shared__ float xs[128 * 33];
    __shared__ float red[264], red2[264];
    __shared__ float ms[32], mu_s[32], rs_s[32];
    __shared__ int   cy0[32], cy1[32], cx0[32], cx1[32];
    __shared__ float cwy[32], cwx[32];
    __shared__ float w1s[128], b1s[128];

    int p0 = blockIdx.x * 32;
    int b = p0 / HW, hw0 = p0 % HW;
    const float* xb = x + (size_t)b * PB;
    if (threadIdx.x < 128) { w1s[threadIdx.x] = ln1w[threadIdx.x]; b1s[threadIdx.x] = ln1b[threadIdx.x]; }

    for (int e = threadIdx.x; e < 4096; e += 256) {
        int c = e >> 5, px = e & 31;
        xs[c * 33 + px] = xb[(size_t)c * HW + hw0 + px];
    }
    if (threadIdx.x < 32) {
        int px = threadIdx.x;
        int hw = hw0 + px;
        int h2 = hw / 176, w2 = hw % 176;
        float fy = 0.25f * h2 - 0.375f; int iy = (int)floorf(fy); float ty = fy - iy;
        float fx = 0.25f * w2 - 0.375f; int ix = (int)floorf(fx); float tx = fx - ix;
        int y0 = iy < 0 ? 0 : iy, y1 = (iy + 1 > 43) ? 43 : iy + 1;
        int x0 = ix < 0 ? 0 : ix, x1 = (ix + 1 > 43) ? 43 : ix + 1;
        cy0[px] = y0; cy1[px] = y1; cx0[px] = x0; cx1[px] = x1;
        cwy[px] = ty; cwx[px] = tx;
        const float* mb = mask + b * NWIN;
        ms[px] = (1.f - ty) * ((1.f - tx) * mb[y0 * 44 + x0] + tx * mb[y0 * 44 + x1])
               +        ty  * ((1.f - tx) * mb[y1 * 44 + x0] + tx * mb[y1 * 44 + x1]);
    }
    __syncthreads();
    {
        int px = threadIdx.x & 31, j = threadIdx.x >> 5;
        float s = 0.f, s2 = 0.f;
        #pragma unroll
        for (int i = 0; i < 16; i++) {
            float v = xs[(j * 16 + i) * 33 + px];
            s += v; s2 += v * v;
        }
        red[j * 33 + px] = s; red2[j * 33 + px] = s2;
    }
    __syncthreads();
    if (threadIdx.x < 32) {
        int px = threadIdx.x; float s = 0.f, s2 = 0.f;
        #pragma unroll
        for (int j = 0; j < 8; j++) { s += red[j * 33 + px]; s2 += red2[j * 33 + px]; }
        float mu = s * (1.f / 128.f);
        float var = s2 * (1.f / 128.f) - mu * mu;
        mu_s[px] = mu; rs_s[px] = rsqrtf(var + 1e-5f);
    }
    __syncthreads();

    int px = threadIdx.x & 31, j = threadIdx.x >> 5;   // j = stage 0..7
    int p = p0 + px;
    size_t tbase = (size_t)(p >> 7) * 8192 + (size_t)j * 1024 + (size_t)(p & 127) * 8;
    {
        float mu = mu_s[px], rs = rs_s[px], m = ms[px];
        unsigned q[8];
        #pragma unroll
        for (int ii = 0; ii < 8; ii++) {
            int c = j * 16 + 2 * ii;
            float v0 = ((xs[c * 33 + px] - mu) * rs * w1s[c] + b1s[c]) * m;
            float v1 = ((xs[(c + 1) * 33 + px] - mu) * rs * w1s[c + 1] + b1s[c + 1]) * m;
            q[ii] = pk(v0, v1);
        }
        uint4* dst = (uint4*)(g_u + OFF_AKV + tbase);
        dst[0] = make_uint4(q[0], q[1], q[2], q[3]);
        dst[1] = make_uint4(q[4], q[5], q[6], q[7]);
    }
    __syncthreads();
    for (int e = threadIdx.x; e < 4096; e += 256) {
        int c = e >> 5, px2 = e & 31;
        const float* eb = edge + ((size_t)b * 128 + c) * NWIN;
        float ty = cwy[px2], tx = cwx[px2];
        float v = (1.f - ty) * ((1.f - tx) * eb[cy0[px2] * 44 + cx0[px2]] + tx * eb[cy0[px2] * 44 + cx1[px2]])
                +        ty  * ((1.f - tx) * eb[cy1[px2] * 44 + cx0[px2]] + tx * eb[cy1[px2] * 44 + cx1[px2]]);
        xs[c * 33 + px2] = v;
    }
    __syncthreads();
    {
        unsigned q[8];
        #pragma unroll
        for (int ii = 0; ii < 8; ii++) {
            int c = j * 16 + 2 * ii;
            q[ii] = pk(xs[c * 33 + px], xs[(c + 1) * 33 + px]);
        }
        uint4* dst = (uint4*)(g_u + OFF_AQ + tbase);
        dst[0] = make_uint4(q[0], q[1], q[2], q[3]);
        dst[1] = make_uint4(q[4], q[5], q[6], q[7]);
    }
}

// ---------------------------------------------------------------------------
// Shared GEMM mainloop pieces (R10-proven: 4-buffer, 3 in flight, 1 bar/stage)
// ---------------------------------------------------------------------------
#define GEMM_PREAMBLE() \
    int tid = threadIdx.x, lane = tid & 31, warp = tid >> 5; \
    int wm = warp >> 2, wn = warp & 3, t = lane & 3, g = lane >> 2; \
    unsigned smb = (unsigned)__cvta_generic_to_shared(sm); \
    int m_ = tid >> 1, q_ = tid & 1; \
    unsigned dA = smb + (unsigned)(2 * m_ + (q_ ^ ((m_ >> 2) & 1))) * 16; \
    unsigned dB = dA + 4096; \
    int itemA = wm * 64 + (lane & 15); \
    int khA = lane >> 4; \
    unsigned aAddr = smb + (unsigned)(2 * itemA + (khA ^ ((itemA >> 2) & 1))) * 16; \
    int itemB = wn * 32 + lane; \
    int bbit = (itemB >> 2) & 1; \
    unsigned bAddr0 = smb + 4096u + (unsigned)(2 * itemB + bbit) * 16; \
    unsigned bAddr1 = smb + 4096u + (unsigned)(2 * itemB + (1 ^ bbit)) * 16; \
    float acc[4][4][4]; \
    _Pragma("unroll") \
    for (int i = 0; i < 4; i++) \
        _Pragma("unroll") \
        for (int j = 0; j < 4; j++) \
            _Pragma("unroll") \
            for (int k = 0; k < 4; k++) acc[i][j][k] = 0.f;

#define GEMM_STAGE_BODY() \
    unsigned buf = (unsigned)(s & 3) * 8192u; \
    unsigned af[4][4], bf[4][2]; \
    ldsm4(bf[0][0], bf[1][0], bf[2][0], bf[3][0], bAddr0 + buf); \
    ldsm4(bf[0][1], bf[1][1], bf[2][1], bf[3][1], bAddr1 + buf); \
    _Pragma("unroll") \
    for (int tm = 0; tm < 4; tm++) \
        ldsm4(af[tm][0], af[tm][1], af[tm][2], af[tm][3], aAddr + buf + tm * 512u); \
    _Pragma("unroll") \
    for (int tm = 0; tm < 4; tm++) \
        _Pragma("unroll") \
        for (int tn = 0; tn < 4; tn++) \
            mma16(acc[tm][tn], af[tm], bf[tn]);

// ---------------------------------------------------------------------------
// K2a: fused Q/K/V GEMM. grid (PTOT/128, 3). y=0->Q, y=1->K half, y=2->V half.
// ---------------------------------------------------------------------------
__global__ void __launch_bounds__(256, 2) k_mma_qkv()
{
    __shared__ unsigned sm[4 * 2048];
    GEMM_PREAMBLE();
    int y = blockIdx.y;
    const unsigned* Ab = g_u + (y == 0 ? OFF_AQ : OFF_AKV)
                       + (size_t)blockIdx.x * 8192 + tid * 4;
    const unsigned* Bb = g_u + OFF_WB + (size_t)y * 8192 + tid * 4;

    #pragma unroll
    for (int s = 0; s < 3; s++) {
        unsigned off = s * 8192u;
        cpa16(dA + off, Ab + s * 1024);
        cpa16(dB + off, Bb + s * 1024);
        CP_COMMIT();
    }
    for (int s = 0; s < 8; s++) {
        if (s + 3 <= 8) CP_WAIT2();
        else if (s + 2 == 8) CP_WAIT1();
        else CP_WAIT0();
        __syncthreads();
        GEMM_STAGE_BODY();
        if (s + 3 < 8) {
            unsigned off = (unsigned)((s + 3) & 3) * 8192u;
            cpa16(dA + off, Ab + (s + 3) * 1024);
            cpa16(dB + off, Bb + (s + 3) * 1024);
        }
        CP_COMMIT();
    }

    int m0 = blockIdx.x * 128;
    unsigned* Cu = g_u + (y == 0 ? OFF_Q : OFF_KV);
    int np = (y == 0) ? 64 : 128;
    int nc0 = (y == 0) ? 0 : (y - 1) * 64;
    #pragma unroll
    for (int tm = 0; tm < 4; tm++)
        #pragma unroll
        for (int tn = 0; tn < 4; tn++) {
            int m = m0 + wm * 64 + tm * 16 + g;
            int n = wn * 32 + tn * 8 + 2 * t;
            Cu[(size_t)m * np + nc0 + (n >> 1)] = pk(acc[tm][tn][0], acc[tm][tn][1]);
            Cu[(size_t)(m + 8) * np + nc0 + (n >> 1)] = pk(acc[tm][tn][2], acc[tm][tn][3]);
        }
}

// ---------------------------------------------------------------------------
// K2b: generic GEMM (conv_in EPI=1/CS, conv_out EPI=2) — R10-proven.
// ---------------------------------------------------------------------------
template<int NSTAGE, int ASRC, int EPI, int CS>
__global__ void __launch_bounds__(256, 2) k_mma_t(
    const unsigned* __restrict__ At, const unsigned* __restrict__ Bt,
    unsigned* __restrict__ Cu, int Nd, float* __restrict__ outp)
{
    __shared__ unsigned sm[4 * 2048];
    GEMM_PREAMBLE();
    const unsigned* Ab;
    if (ASRC == 0) Ab = At + (size_t)blockIdx.x * (NSTAGE * 1024) + tid * 4;
    else           Ab = At + ((size_t)blockIdx.x * 128 + (tid >> 1)) * 256 + (tid & 1) * 4;
    const unsigned* Bb = Bt + (size_t)blockIdx.y * (NSTAGE * 1024) + tid * 4;

    #pragma unroll
    for (int s = 0; s < 3; s++) {
        if (s < NSTAGE) {
            unsigned off = s * 8192u;
            cpa16(dA + off, Ab + (ASRC == 0 ? s * 1024 : s * 8));
            cpa16(dB + off, Bb + s * 1024);
        }
        CP_COMMIT();
    }
    for (int s = 0; s < NSTAGE; s++) {
        if (s + 3 <= NSTAGE) CP_WAIT2();
        else if (s + 2 == NSTAGE) CP_WAIT1();
        else CP_WAIT0();
        __syncthreads();
        GEMM_STAGE_BODY();
        if (s + 3 < NSTAGE) {
            unsigned off = (unsigned)((s + 3) & 3) * 8192u;
            cpa16(dA + off, Ab + (ASRC == 0 ? (s + 3) * 1024 : (s + 3) * 8));
            cpa16(dB + off, Bb + (s + 3) * 1024);
        }
        CP_COMMIT();
    }

    int m0 = blockIdx.x * 128, n0 = blockIdx.y * 128;
    if (EPI == 1) {
        int np = Nd >> 1;
        #pragma unroll
        for (int tm = 0; tm < 4; tm++)
            #pragma unroll
            for (int tn = 0; tn < 4; tn++) {
                int m = m0 + wm * 64 + tm * 16 + g;
                int n = n0 + wn * 32 + tn * 8 + 2 * t;
                unsigned v0 = pk(acc[tm][tn][0], acc[tm][tn][1]);
                unsigned v1 = pk(acc[tm][tn][2], acc[tm][tn][3]);
                if (CS) {
                    stg_cs(Cu + (size_t)m * np + (n >> 1), v0);
                    stg_cs(Cu + (size_t)(m + 8) * np + (n >> 1), v1);
                } else {
                    Cu[(size_t)m * np + (n >> 1)] = v0;
                    Cu[(size_t)(m + 8) * np + (n >> 1)] = v1;
                }
            }
    } else {
        const float* x1 = (const float*)(g_u + OFF_X1);
        int b = m0 / HW, hw0 = m0 % HW;
        #pragma unroll
        for (int tm = 0; tm < 4; tm++)
            #pragma unroll
            for (int tn = 0; tn < 4; tn++) {
                int mrow = wm * 64 + tm * 16 + g;
                int n = wn * 32 + tn * 8 + 2 * t;
                size_t a0 = ((size_t)b * 128 + n) * HW + hw0 + mrow;
                outp[a0]          = x1[a0] + acc[tm][tn][0];
                outp[a0 + HW]     = x1[a0 + HW] + acc[tm][tn][1];
                outp[a0 + 8]      = x1[a0 + 8] + acc[tm][tn][2];
                outp[a0 + HW + 8] = x1[a0 + HW + 8] + acc[tm][tn][3];
            }
    }
}

// ---------------------------------------------------------------------------
// K3: per-(window,token) channel attention + FUSED residual -> x1.
// ---------------------------------------------------------------------------
__global__ void __launch_bounds__(256) k_attn(const float* __restrict__ x)
{
    __shared__ float outs[32 * 129];
    __shared__ float buf[8 * 640];
    int bid = blockIdx.x;
    int chunk = bid % 61;
    int n = (bid / 61) % 16;
    int b = bid / (61 * 16);
    int ihw0 = chunk * 32;
    const unsigned* Qp  = g_u + OFF_Q;
    const unsigned* KVp = g_u + OFF_KV;
    float* x1 = (float*)(g_u + OFF_X1);
    int warp = threadIdx.x >> 5, lane = threadIdx.x & 31;
    float* qs = buf + warp * 640;
    float* ks = qs + 128;
    float* vs = qs + 256;
    float* ds = qs + 384;

    for (int it = 0; it < 4; it++) {
        int g = it * 8 + warp;
        int ihw = ihw0 + g;
        if (ihw < NWIN) {
            int ih = ihw / 44, iw = ihw % 44;
            int h2 = ih * 4 + (n >> 2), w2 = iw * 4 + (n & 3);
            size_t p = (size_t)b * HW + (size_t)h2 * 176 + w2;
            {
                int i = lane;
                float2 vq = bf2f(Qp[p * 64 + i]);
                qs[2 * i] = vq.x; qs[2 * i + 1] = vq.y;
                float2 vq2 = bf2f(Qp[p * 64 + 32 + i]);
                qs[64 + 2 * i] = vq2.x; qs[65 + 2 * i] = vq2.y;
                float2 k1 = bf2f(KVp[p * 128 + i]);
                ks[2 * i] = k1.x; ks[2 * i + 1] = k1.y;
                float2 k2 = bf2f(KVp[p * 128 + 32 + i]);
                ks[64 + 2 * i] = k2.x; ks[65 + 2 * i] = k2.y;
                float2 v1 = bf2f(KVp[p * 128 + 64 + i]);
                vs[2 * i] = v1.x; vs[2 * i + 1] = v1.y;
                float2 v2 = bf2f(KVp[p * 128 + 96 + i]);
                vs[64 + 2 * i] = v2.x; vs[65 + 2 * i] = v2.y;
            }
            __syncwarp();
            for (int e = lane; e < 256; e += 32) {
                int j = e >> 4, kk = e & 15;
                float s = 0.f;
                #pragma unroll
                for (int i = 0; i < 8; i++) s += qs[i * 16 + j] * ks[i * 16 + kk];
                ds[e] = s * 0.25f;
            }
            __syncwarp();
            if (lane < 16) {
                float mx = -1e30f;
                #pragma unroll
                for (int kk = 0; kk < 16; kk++) mx = fmaxf(mx, ds[lane * 16 + kk]);
                float sm = 0.f;
                #pragma unroll
                for (int kk = 0; kk < 16; kk++) {
                    float ev = __expf(ds[lane * 16 + kk] - mx);
                    ds[lane * 16 + kk] = ev; sm += ev;
                }
                float inv = 1.f / sm;
                #pragma unroll
                for (int kk = 0; kk < 16; kk++) ds[lane * 16 + kk] *= inv;
            }
            __syncwarp();
            for (int ch = lane; ch < 128; ch += 32) {
                int i = ch >> 4, j = ch & 15;
                float s = 0.f;
                #pragma unroll
                for (int kk = 0; kk < 16; kk++) s += ds[j * 16 + kk] * vs[i * 16 + kk];
                outs[g * 129 + ch] = s;
            }
        }
    }
    __syncthreads();
    size_t base = ((size_t)b * 2048 + (size_t)n * 128) * 1936 + ihw0;
    for (int e = threadIdx.x; e < 4096; e += 256) {
        int ch = e >> 5, g = e & 31;
        if (ihw0 + g < NWIN) {
            size_t idx = base + (size_t)ch * 1936 + g;
            x1[idx] = x[idx] + outs[g * 129 + ch];
        }
    }
}

// ---------------------------------------------------------------------------
// K4: LN2 over x1 (read-only) -> tiled X1LN packed bf16 (uint4 stores).
// ---------------------------------------------------------------------------
__global__ void __launch_bounds__(256) k_merge2(
    const float* __restrict__ ln2w, const float* __restrict__ ln2b)
{
    __shared__ float red[264], red2[264], mu_s[32], rs_s[32];
    __shared__ float w2s[128], b2s[128];
    int p0 = blockIdx.x * 32;
    int b = p0 / HW, hw0 = p0 % HW;
    int px = threadIdx.x & 31, j = threadIdx.x >> 5;
    if (threadIdx.x < 128) { w2s[threadIdx.x] = ln2w[threadIdx.x]; b2s[threadIdx.x] = ln2b[threadIdx.x]; }
    const float* x1 = (const float*)(g_u + OFF_X1);
    size_t base = (size_t)b * PB + hw0 + px;
    float v[16];
    float s = 0.f, s2 = 0.f;
    #pragma unroll
    for (int i = 0; i < 16; i++) {
        int c = j * 16 + i;
        float val = x1[base + (size_t)c * HW];
        v[i] = val; s += val; s2 += val * val;
    }
    red[j * 33 + px] = s; red2[j * 33 + px] = s2;
    __syncthreads();
    if (threadIdx.x < 32) {
        float ss = 0.f, ss2 = 0.f;
        #pragma unroll
        for (int j2 = 0; j2 < 8; j2++) { ss += red[j2 * 33 + threadIdx.x]; ss2 += red2[j2 * 33 + threadIdx.x]; }
        float mu = ss * (1.f / 128.f);
        float var = ss2 * (1.f / 128.f) - mu * mu;
        mu_s[threadIdx.x] = mu; rs_s[threadIdx.x] = rsqrtf(var + 1e-5f);
    }
    __syncthreads();
    float mu = mu_s[px], rs = rs_s[px];
    int p = p0 + px;
    unsigned qv[8];
    #pragma unroll
    for (int ii = 0; ii < 8; ii++) {
        int c = j * 16 + 2 * ii;
        float a = (v[2 * ii] - mu) * rs * w2s[c] + b2s[c];
        float bb = (v[2 * ii + 1] - mu) * rs * w2s[c + 1] + b2s[c + 1];
        qv[ii] = pk(a, bb);
    }
    uint4* dst = (uint4*)(g_u + OFF_X1LN + (size_t)(p >> 7) * 8192 + (size_t)j * 1024 + (size_t)(p & 127) * 8);
    dst[0] = make_uint4(qv[0], qv[1], qv[2], qv[3]);
    dst[1] = make_uint4(qv[4], qv[5], qv[6], qv[7]);
}

// ---------------------------------------------------------------------------
// K6: depthwise 3x3 + exact GELU gate, packed f32x2 accumulation.
// 4 w-columns/thread, rows window h-1..h+1 x 6 cols, h-strip of 22.
// ---------------------------------------------------------------------------
__device__ __forceinline__ void dw_row6(
    const unsigned* __restrict__ yin, int b, int h, int w0, int cp,
    unsigned* U, unsigned* V)
{
    #pragma unroll
    for (int dw = 0; dw < 6; dw++) { U[dw] = 0u; V[dw] = 0u; }
    if (h < 0 || h >= 176) return;
    #pragma unroll
    for (int dw = 0; dw < 6; dw++) {
        int ww = w0 - 1 + dw;
        if (ww < 0 || ww >= 176) continue;
        size_t base = ((size_t)b * HW + (size_t)h * 176 + ww) * 512;
        U[dw] = yin[base + cp];
        V[dw] = yin[base + 256 + cp];
    }
}

__global__ void __launch_bounds__(256) k_dwconv(const float* __restrict__ wdw)
{
    int cp = threadIdx.x;
    int blk = blockIdx.x;
    int wg = blk % 44;
    int hs = (blk / 44) % 8;
    int b  = blk / (44 * 8);
    int w0 = wg * 4;
    int h0 = hs * 22;
    const unsigned* yin = g_u + OFF_YIN;
    unsigned* yg = g_u + OFF_YG;
    int c0 = 2 * cp;
    unsigned long long wpA[9], wpB[9];
    #pragma unroll
    for (int t = 0; t < 9; t++) {
        wpA[t] = pkf2(__ldg(&wdw[c0 * 9 + t]), __ldg(&wdw[(c0 + 1) * 9 + t]));
        wpB[t] = pkf2(__ldg(&wdw[(512 + c0) * 9 + t]), __ldg(&wdw[(513 + c0) * 9 + t]));
    }
    unsigned U[3][6], V[3][6];
    dw_row6(yin, b, h0 - 1, w0, cp, U[0], V[0]);
    dw_row6(yin, b, h0,     w0, cp, U[1], V[1]);
    dw_row6(yin, b, h0 + 1, w0, cp, U[2], V[2]);

    for (int h = h0; h < h0 + 22; h++) {
        unsigned long long accA[4], accB[4];
        #pragma unroll
        for (int o = 0; o < 4; o++) { accA[o] = 0ULL; accB[o] = 0ULL; }
        #pragma unroll
        for (int dw = 0; dw < 6; dw++) {
            #pragma unroll
            for (int rr = 0; rr < 3; rr++) {
                unsigned long long ua = u2f2(U[rr][dw]);
                unsigned long long vb = u2f2(V[rr][dw]);
                #pragma unroll
                for (int o = 0; o < 4; o++) {
                    int cc = dw - o;
                    if (cc >= 0 && cc < 3) {
                        int tt = rr * 3 + cc;
                        accA[o] = ffma2(ua, wpA[tt], accA[o]);
                        accB[o] = ffma2(vb, wpB[tt], accB[o]);
                    }
                }
            }
        }
        #pragma unroll
        for (int o = 0; o < 4; o++) {
            float a0, a1, g0, g1;
            unf2(accA[o], a0, a1);
            unf2(accB[o], g0, g1);
            float e0 = 0.5f * a0 * (1.f + erff(a0 * 0.70710678118654752f));
            float e1 = 0.5f * a1 * (1.f + erff(a1 * 0.70710678118654752f));
            int p = b * HW + h * 176 + w0 + o;
            yg[(size_t)p * 256 + cp] = pk(e0 * g0, e1 * g1);
        }
        #pragma unroll
        for (int dw = 0; dw < 6; dw++) {
            U[0][dw] = U[1][dw]; U[1][dw] = U[2][dw];
            V[0][dw] = V[1][dw]; V[1][dw] = V[2][dw];
        }
        dw_row6(yin, b, h + 2, w0, cp, U[2], V[2]);
    }
}

// ---------------------------------------------------------------------------
extern "C" void kernel_launch(void* const* d_in, const int* in_sizes, int n_in,
                              void* d_out, int out_size)
{
    const float* x    = (const float*)d_in[0];
    const float* mask = (const float*)d_in[1];
    const float* edge = (const float*)d_in[2];
    const float* ln1w = (const float*)d_in[3];
    const float* ln1b = (const float*)d_in[4];
    const float* Wq   = (const float*)d_in[5];
    const float* Wk   = (const float*)d_in[6];
    const float* Wv   = (const float*)d_in[7];
    const float* ln2w = (const float*)d_in[8];
    const float* ln2b = (const float*)d_in[9];
    const float* w_in = (const float*)d_in[10];
    const float* w_dw = (const float*)d_in[11];
    const float* w_out= (const float*)d_in[12];
    float* outp = (float*)d_out;

    unsigned* G = nullptr;
    cudaGetSymbolAddress((void**)&G, g_u);

    // K0: weights -> tiled packed bf16x2
    k_wprep<<<(122880 + 255) / 256, 256>>>(Wq, Wk, Wv, w_in, w_out);

    // K1: LN1 + resize -> tiled Aq/Akv
    k_prep<<<PTOT / 32, 256>>>(x, mask, edge, ln1w, ln1b);

    // K2a: fused Q/K/V GEMM (one launch, grid.y = 3)
    k_mma_qkv<<<dim3(PTOT / 128, 3), 256>>>();

    // K3: channel attention + fused residual -> x1 (fp32 NCHW)
    k_attn<<<4 * 16 * 61, 256>>>(x);

    // K4: LN2(x1) -> tiled X1LN
    k_merge2<<<PTOT / 32, 256>>>(ln2w, ln2b);

    // K5: conv1x1 128->1024 -> y_in packed bf16 (evict-first C stores)
    k_mma_t<8, 0, 1, 1><<<dim3(PTOT / 128, 8), 256>>>(G + OFF_X1LN, G + OFF_WB + 24576, G + OFF_YIN, 1024, nullptr);

    // K6: depthwise 3x3 + GELU gate -> y_g packed rows (f32x2 math)
    k_dwconv<<<BATCH * 44 * 8, 256>>>(w_dw);

    // K7: conv1x1 512->128 + residual -> d_out (NCHW), A from rows
    k_mma_t<32, 1, 2, 0><<<dim3(PTOT / 128, 1), 256>>>(G + OFF_YG, G + OFF_WB + 90112, nullptr, 128, outp);
}

// round 13
// speedup vs baseline: 1.4350x; 1.0792x over previous
#include <cuda_runtime.h>
#include <cuda_bf16.h>
#include <math.h>

#define BATCH 4
#define HW    30976            // 176*176
#define PTOT  123904           // BATCH*HW
#define NWIN  1936             // 44*44
#define PB    3964928ULL       // per-batch plane = 128*30976

// uint-unit offsets into the single scratch buffer
#define OFF_AQ    0ULL          // tiled bf16x2, K=128 (8 stages/blk)
#define OFF_AKV   7929856ULL    // tiled bf16x2, K=128
#define OFF_Q     31719424ULL   // packed bf16x2 [p][64]
#define OFF_KV    47579136ULL   // packed bf16x2 [p][128] (K | V)
#define OFF_X1    79298560ULL   // fp32 NCHW residual (written by k_attn)
#define OFF_X1LN  95158272ULL   // tiled bf16x2, K=128
#define OFF_YIN   103088128ULL  // packed bf16x2 [p][512]
#define OFF_YG    166526976ULL  // packed bf16x2 [p][256]
#define OFF_WB    198246400ULL
#define TOT_U     198369280ULL

__device__ unsigned g_u[TOT_U];

// ---------------------------------------------------------------------------
// helpers
// ---------------------------------------------------------------------------
__device__ __forceinline__ unsigned pk(float lo, float hi) {
    unsigned r;
    asm("cvt.rn.bf16x2.f32 %0, %1, %2;" : "=r"(r) : "f"(hi), "f"(lo));
    return r;
}
__device__ __forceinline__ float2 bf2f(unsigned u) {
    __nv_bfloat162 h = *reinterpret_cast<__nv_bfloat162*>(&u);
    return __bfloat1622float2(h);
}
__device__ __forceinline__ void mma16(float* d, const unsigned* a, const unsigned* b) {
    asm volatile(
        "mma.sync.aligned.m16n8k16.row.col.f32.bf16.bf16.f32 "
        "{%0,%1,%2,%3},{%4,%5,%6,%7},{%8,%9},{%0,%1,%2,%3};"
        : "+f"(d[0]), "+f"(d[1]), "+f"(d[2]), "+f"(d[3])
        : "r"(a[0]), "r"(a[1]), "r"(a[2]), "r"(a[3]), "r"(b[0]), "r"(b[1]));
}
__device__ __forceinline__ void ldsm4(unsigned& r0, unsigned& r1, unsigned& r2, unsigned& r3, unsigned a) {
    asm volatile("ldmatrix.sync.aligned.m8n8.x4.shared.b16 {%0,%1,%2,%3}, [%4];"
        : "=r"(r0), "=r"(r1), "=r"(r2), "=r"(r3) : "r"(a));
}
__device__ __forceinline__ void cpa16(unsigned d, const void* s) {
    asm volatile("cp.async.cg.shared.global [%0], [%1], 16;" :: "r"(d), "l"(s));
}
__device__ __forceinline__ void stg_cs(unsigned* p, unsigned v) {
    asm volatile("st.global.cs.u32 [%0], %1;" :: "l"(p), "r"(v));
}
#define CP_COMMIT() asm volatile("cp.async.commit_group;" ::: "memory")
#define CP_WAIT2()  asm volatile("cp.async.wait_group 2;" ::: "memory")
#define CP_WAIT1()  asm volatile("cp.async.wait_group 1;" ::: "memory")
#define CP_WAIT0()  asm volatile("cp.async.wait_group 0;" ::: "memory")

// packed f32x2 helpers (sm_100-family PTX, not arch-accelerated)
__device__ __forceinline__ unsigned long long u2f2(unsigned u) {
    unsigned lo = u << 16, hi = u & 0xFFFF0000u;
    unsigned long long r;
    asm("mov.b64 %0, {%1,%2};" : "=l"(r) : "r"(lo), "r"(hi));
    return r;
}
__device__ __forceinline__ unsigned long long pkf2(float lo, float hi) {
    unsigned long long r;
    asm("mov.b64 %0, {%1,%2};" : "=l"(r) : "f"(lo), "f"(hi));
    return r;
}
__device__ __forceinline__ unsigned long long ffma2(
    unsigned long long a, unsigned long long b, unsigned long long c) {
    unsigned long long d;
    asm("fma.rn.f32x2 %0, %1, %2, %3;" : "=l"(d) : "l"(a), "l"(b), "l"(c));
    return d;
}
__device__ __forceinline__ void unf2(unsigned long long v, float& lo, float& hi) {
    asm("mov.b64 {%0,%1}, %2;" : "=f"(lo), "=f"(hi) : "l"(v));
}

// ---------------------------------------------------------------------------
// K0: weight prep -> packed bf16x2 in GEMM-tiled layout.
// WB: WqP[8192] | WKVP[16384] | WinP[65536] | WoutP[32768]
// ---------------------------------------------------------------------------
__global__ void k_wprep(const float* __restrict__ Wq, const float* __restrict__ Wk,
                        const float* __restrict__ Wv, const float* __restrict__ win,
                        const float* __restrict__ wout)
{
    int idx = blockIdx.x * 256 + threadIdx.x;
    if (idx >= 122880) return;
    unsigned* WB = g_u + OFF_WB;
    if (idx < 8192) {
        int n = idx >> 6, kp = idx & 63;
        WB[(kp >> 3) * 1024 + n * 8 + (kp & 7)] = pk(Wq[n * 128 + 2 * kp], Wq[n * 128 + 2 * kp + 1]);
    } else if (idx < 24576) {
        int j = idx - 8192; int n2 = j >> 6, kp = j & 63;
        const float* W = (n2 < 128) ? Wk : Wv;
        int n = n2 & 127;
        WB[8192 + (n2 >> 7) * 8192 + (kp >> 3) * 1024 + n * 8 + (kp & 7)]
            = pk(W[n * 128 + 2 * kp], W[n * 128 + 2 * kp + 1]);
    } else if (idx < 90112) {
        int j = idx - 24576; int n = j >> 6, kp = j & 63;
        WB[24576 + (n >> 7) * 8192 + (kp >> 3) * 1024 + (n & 127) * 8 + (kp & 7)]
            = pk(win[n * 128 + 2 * kp], win[n * 128 + 2 * kp + 1]);
    } else {
        int j = idx - 90112; int n = j >> 8, kp = j & 255;
        WB[90112 + (kp >> 3) * 1024 + n * 8 + (kp & 7)]
            = pk(wout[n * 512 + 2 * kp], wout[n * 512 + 2 * kp + 1]);
    }
}

// ---------------------------------------------------------------------------
// K1: LN1(x), bilinear mask/edge upsample -> tiled Aq / Akv (uint4 stores).
// ---------------------------------------------------------------------------
__global__ void __launch_bounds__(256) k_prep(
    const float* __restrict__ x, const float* __restrict__ mask,
    const float* __restrict__ edge, const float* __restrict__ ln1w,
    const float* __restrict__ ln1b)
{
    __shared__ float xs[128 * 33];
    __shared__ float red[264], red2[264];
    __shared__ float ms[32], mu_s[32], rs_s[32];
    __shared__ int   cy0[32], cy1[32], cx0[32], cx1[32];
    __shared__ float cwy[32], cwx[32];
    __shared__ float w1s[128], b1s[128];

    int p0 = blockIdx.x * 32;
    int b = p0 / HW, hw0 = p0 % HW;
    const float* xb = x + (size_t)b * PB;
    if (threadIdx.x < 128) { w1s[threadIdx.x] = ln1w[threadIdx.x]; b1s[threadIdx.x] = ln1b[threadIdx.x]; }

    for (int e = threadIdx.x; e < 4096; e += 256) {
        int c = e >> 5, px = e & 31;
        xs[c * 33 + px] = xb[(size_t)c * HW + hw0 + px];
    }
    if (threadIdx.x < 32) {
        int px = threadIdx.x;
        int hw = hw0 + px;
        int h2 = hw / 176, w2 = hw % 176;
        float fy = 0.25f * h2 - 0.375f; int iy = (int)floorf(fy); float ty = fy - iy;
        float fx = 0.25f * w2 - 0.375f; int ix = (int)floorf(fx); float tx = fx - ix;
        int y0 = iy < 0 ? 0 : iy, y1 = (iy + 1 > 43) ? 43 : iy + 1;
        int x0 = ix < 0 ? 0 : ix, x1 = (ix + 1 > 43) ? 43 : ix + 1;
        cy0[px] = y0; cy1[px] = y1; cx0[px] = x0; cx1[px] = x1;
        cwy[px] = ty; cwx[px] = tx;
        const float* mb = mask + b * NWIN;
        ms[px] = (1.f - ty) * ((1.f - tx) * mb[y0 * 44 + x0] + tx * mb[y0 * 44 + x1])
               +        ty  * ((1.f - tx) * mb[y1 * 44 + x0] + tx * mb[y1 * 44 + x1]);
    }
    __syncthreads();
    {
        int px = threadIdx.x & 31, j = threadIdx.x >> 5;
        float s = 0.f, s2 = 0.f;
        #pragma unroll
        for (int i = 0; i < 16; i++) {
            float v = xs[(j * 16 + i) * 33 + px];
            s += v; s2 += v * v;
        }
        red[j * 33 + px] = s; red2[j * 33 + px] = s2;
    }
    __syncthreads();
    if (threadIdx.x < 32) {
        int px = threadIdx.x; float s = 0.f, s2 = 0.f;
        #pragma unroll
        for (int j = 0; j < 8; j++) { s += red[j * 33 + px]; s2 += red2[j * 33 + px]; }
        float mu = s * (1.f / 128.f);
        float var = s2 * (1.f / 128.f) - mu * mu;
        mu_s[px] = mu; rs_s[px] = rsqrtf(var + 1e-5f);
    }
    __syncthreads();

    int px = threadIdx.x & 31, j = threadIdx.x >> 5;   // j = stage 0..7
    int p = p0 + px;
    size_t tbase = (size_t)(p >> 7) * 8192 + (size_t)j * 1024 + (size_t)(p & 127) * 8;
    {
        float mu = mu_s[px], rs = rs_s[px], m = ms[px];
        unsigned q[8];
        #pragma unroll
        for (int ii = 0; ii < 8; ii++) {
            int c = j * 16 + 2 * ii;
            float v0 = ((xs[c * 33 + px] - mu) * rs * w1s[c] + b1s[c]) * m;
            float v1 = ((xs[(c + 1) * 33 + px] - mu) * rs * w1s[c + 1] + b1s[c + 1]) * m;
            q[ii] = pk(v0, v1);
        }
        uint4* dst = (uint4*)(g_u + OFF_AKV + tbase);
        dst[0] = make_uint4(q[0], q[1], q[2], q[3]);
        dst[1] = make_uint4(q[4], q[5], q[6], q[7]);
    }
    __syncthreads();
    for (int e = threadIdx.x; e < 4096; e += 256) {
        int c = e >> 5, px2 = e & 31;
        const float* eb = edge + ((size_t)b * 128 + c) * NWIN;
        float ty = cwy[px2], tx = cwx[px2];
        float v = (1.f - ty) * ((1.f - tx) * eb[cy0[px2] * 44 + cx0[px2]] + tx * eb[cy0[px2] * 44 + cx1[px2]])
                +        ty  * ((1.f - tx) * eb[cy1[px2] * 44 + cx0[px2]] + tx * eb[cy1[px2] * 44 + cx1[px2]]);
        xs[c * 33 + px2] = v;
    }
    __syncthreads();
    {
        unsigned q[8];
        #pragma unroll
        for (int ii = 0; ii < 8; ii++) {
            int c = j * 16 + 2 * ii;
            q[ii] = pk(xs[c * 33 + px], xs[(c + 1) * 33 + px]);
        }
        uint4* dst = (uint4*)(g_u + OFF_AQ + tbase);
        dst[0] = make_uint4(q[0], q[1], q[2], q[3]);
        dst[1] = make_uint4(q[4], q[5], q[6], q[7]);
    }
}

// ---------------------------------------------------------------------------
// Shared GEMM mainloop pieces (R10-proven: 4-buffer, 3 in flight, 1 bar/stage)
// ---------------------------------------------------------------------------
#define GEMM_PREAMBLE() \
    int tid = threadIdx.x, lane = tid & 31, warp = tid >> 5; \
    int wm = warp >> 2, wn = warp & 3, t = lane & 3, g = lane >> 2; \
    unsigned smb = (unsigned)__cvta_generic_to_shared(sm); \
    int m_ = tid >> 1, q_ = tid & 1; \
    unsigned dA = smb + (unsigned)(2 * m_ + (q_ ^ ((m_ >> 2) & 1))) * 16; \
    unsigned dB = dA + 4096; \
    int itemA = wm * 64 + (lane & 15); \
    int khA = lane >> 4; \
    unsigned aAddr = smb + (unsigned)(2 * itemA + (khA ^ ((itemA >> 2) & 1))) * 16; \
    int itemB = wn * 32 + lane; \
    int bbit = (itemB >> 2) & 1; \
    unsigned bAddr0 = smb + 4096u + (unsigned)(2 * itemB + bbit) * 16; \
    unsigned bAddr1 = smb + 4096u + (unsigned)(2 * itemB + (1 ^ bbit)) * 16; \
    float acc[4][4][4]; \
    _Pragma("unroll") \
    for (int i = 0; i < 4; i++) \
        _Pragma("unroll") \
        for (int j = 0; j < 4; j++) \
            _Pragma("unroll") \
            for (int k = 0; k < 4; k++) acc[i][j][k] = 0.f;

#define GEMM_STAGE_BODY() \
    unsigned buf = (unsigned)(s & 3) * 8192u; \
    unsigned af[4][4], bf[4][2]; \
    ldsm4(bf[0][0], bf[1][0], bf[2][0], bf[3][0], bAddr0 + buf); \
    ldsm4(bf[0][1], bf[1][1], bf[2][1], bf[3][1], bAddr1 + buf); \
    _Pragma("unroll") \
    for (int tm = 0; tm < 4; tm++) \
        ldsm4(af[tm][0], af[tm][1], af[tm][2], af[tm][3], aAddr + buf + tm * 512u); \
    _Pragma("unroll") \
    for (int tm = 0; tm < 4; tm++) \
        _Pragma("unroll") \
        for (int tn = 0; tn < 4; tn++) \
            mma16(acc[tm][tn], af[tm], bf[tn]);

// ---------------------------------------------------------------------------
// K2a: fused Q/K/V GEMM. grid (PTOT/128, 3). y=0->Q, y=1->K half, y=2->V half.
// ---------------------------------------------------------------------------
__global__ void __launch_bounds__(256, 2) k_mma_qkv()
{
    __shared__ unsigned sm[4 * 2048];
    GEMM_PREAMBLE();
    int y = blockIdx.y;
    const unsigned* Ab = g_u + (y == 0 ? OFF_AQ : OFF_AKV)
                       + (size_t)blockIdx.x * 8192 + tid * 4;
    const unsigned* Bb = g_u + OFF_WB + (size_t)y * 8192 + tid * 4;

    #pragma unroll
    for (int s = 0; s < 3; s++) {
        unsigned off = s * 8192u;
        cpa16(dA + off, Ab + s * 1024);
        cpa16(dB + off, Bb + s * 1024);
        CP_COMMIT();
    }
    for (int s = 0; s < 8; s++) {
        if (s + 3 <= 8) CP_WAIT2();
        else if (s + 2 == 8) CP_WAIT1();
        else CP_WAIT0();
        __syncthreads();
        GEMM_STAGE_BODY();
        if (s + 3 < 8) {
            unsigned off = (unsigned)((s + 3) & 3) * 8192u;
            cpa16(dA + off, Ab + (s + 3) * 1024);
            cpa16(dB + off, Bb + (s + 3) * 1024);
        }
        CP_COMMIT();
    }

    int m0 = blockIdx.x * 128;
    unsigned* Cu = g_u + (y == 0 ? OFF_Q : OFF_KV);
    int np = (y == 0) ? 64 : 128;
    int nc0 = (y == 0) ? 0 : (y - 1) * 64;
    #pragma unroll
    for (int tm = 0; tm < 4; tm++)
        #pragma unroll
        for (int tn = 0; tn < 4; tn++) {
            int m = m0 + wm * 64 + tm * 16 + g;
            int n = wn * 32 + tn * 8 + 2 * t;
            Cu[(size_t)m * np + nc0 + (n >> 1)] = pk(acc[tm][tn][0], acc[tm][tn][1]);
            Cu[(size_t)(m + 8) * np + nc0 + (n >> 1)] = pk(acc[tm][tn][2], acc[tm][tn][3]);
        }
}

// ---------------------------------------------------------------------------
// K2b: generic GEMM (conv_in EPI=1/CS, conv_out EPI=2) — R10-proven.
// ---------------------------------------------------------------------------
template<int NSTAGE, int ASRC, int EPI, int CS>
__global__ void __launch_bounds__(256, 2) k_mma_t(
    const unsigned* __restrict__ At, const unsigned* __restrict__ Bt,
    unsigned* __restrict__ Cu, int Nd, float* __restrict__ outp)
{
    __shared__ unsigned sm[4 * 2048];
    GEMM_PREAMBLE();
    const unsigned* Ab;
    if (ASRC == 0) Ab = At + (size_t)blockIdx.x * (NSTAGE * 1024) + tid * 4;
    else           Ab = At + ((size_t)blockIdx.x * 128 + (tid >> 1)) * 256 + (tid & 1) * 4;
    const unsigned* Bb = Bt + (size_t)blockIdx.y * (NSTAGE * 1024) + tid * 4;

    #pragma unroll
    for (int s = 0; s < 3; s++) {
        if (s < NSTAGE) {
            unsigned off = s * 8192u;
            cpa16(dA + off, Ab + (ASRC == 0 ? s * 1024 : s * 8));
            cpa16(dB + off, Bb + s * 1024);
        }
        CP_COMMIT();
    }
    for (int s = 0; s < NSTAGE; s++) {
        if (s + 3 <= NSTAGE) CP_WAIT2();
        else if (s + 2 == NSTAGE) CP_WAIT1();
        else CP_WAIT0();
        __syncthreads();
        GEMM_STAGE_BODY();
        if (s + 3 < NSTAGE) {
            unsigned off = (unsigned)((s + 3) & 3) * 8192u;
            cpa16(dA + off, Ab + (ASRC == 0 ? (s + 3) * 1024 : (s + 3) * 8));
            cpa16(dB + off, Bb + (s + 3) * 1024);
        }
        CP_COMMIT();
    }

    int m0 = blockIdx.x * 128, n0 = blockIdx.y * 128;
    if (EPI == 1) {
        int np = Nd >> 1;
        #pragma unroll
        for (int tm = 0; tm < 4; tm++)
            #pragma unroll
            for (int tn = 0; tn < 4; tn++) {
                int m = m0 + wm * 64 + tm * 16 + g;
                int n = n0 + wn * 32 + tn * 8 + 2 * t;
                unsigned v0 = pk(acc[tm][tn][0], acc[tm][tn][1]);
                unsigned v1 = pk(acc[tm][tn][2], acc[tm][tn][3]);
                if (CS) {
                    stg_cs(Cu + (size_t)m * np + (n >> 1), v0);
                    stg_cs(Cu + (size_t)(m + 8) * np + (n >> 1), v1);
                } else {
                    Cu[(size_t)m * np + (n >> 1)] = v0;
                    Cu[(size_t)(m + 8) * np + (n >> 1)] = v1;
                }
            }
    } else {
        const float* x1 = (const float*)(g_u + OFF_X1);
        int b = m0 / HW, hw0 = m0 % HW;
        #pragma unroll
        for (int tm = 0; tm < 4; tm++)
            #pragma unroll
            for (int tn = 0; tn < 4; tn++) {
                int mrow = wm * 64 + tm * 16 + g;
                int n = wn * 32 + tn * 8 + 2 * t;
                size_t a0 = ((size_t)b * 128 + n) * HW + hw0 + mrow;
                outp[a0]          = x1[a0] + acc[tm][tn][0];
                outp[a0 + HW]     = x1[a0 + HW] + acc[tm][tn][1];
                outp[a0 + 8]      = x1[a0 + 8] + acc[tm][tn][2];
                outp[a0 + HW + 8] = x1[a0 + HW + 8] + acc[tm][tn][3];
            }
    }
}

// ---------------------------------------------------------------------------
// K3: channel attention + fused residual, register-cached smem operands.
// ds stored TRANSPOSED with stride 17: ds[kk*17 + j].
// ---------------------------------------------------------------------------
__global__ void __launch_bounds__(256) k_attn(const float* __restrict__ x)
{
    __shared__ float outs[32 * 129];
    __shared__ float buf[8 * 656];
    int bid = blockIdx.x;
    int chunk = bid % 61;
    int n = (bid / 61) % 16;
    int b = bid / (61 * 16);
    int ihw0 = chunk * 32;
    const unsigned* Qp  = g_u + OFF_Q;
    const unsigned* KVp = g_u + OFF_KV;
    float* x1 = (float*)(g_u + OFF_X1);
    int warp = threadIdx.x >> 5, lane = threadIdx.x & 31;
    float* qs = buf + warp * 656;
    float* ks = qs + 128;
    float* vs = qs + 256;
    float* ds = qs + 384;          // 16x16 stored transposed, stride 17
    int kk = lane & 15, hh = lane >> 4;

    for (int it = 0; it < 4; it++) {
        int g = it * 8 + warp;
        int ihw = ihw0 + g;
        if (ihw < NWIN) {
            int ih = ihw / 44, iw = ihw % 44;
            int h2 = ih * 4 + (n >> 2), w2 = iw * 4 + (n & 3);
            size_t p = (size_t)b * HW + (size_t)h2 * 176 + w2;
            {
                int i = lane;
                *(float2*)(qs + 2 * i)      = bf2f(Qp[p * 64 + i]);
                *(float2*)(qs + 64 + 2 * i) = bf2f(Qp[p * 64 + 32 + i]);
                *(float2*)(ks + 2 * i)      = bf2f(KVp[p * 128 + i]);
                *(float2*)(ks + 64 + 2 * i) = bf2f(KVp[p * 128 + 32 + i]);
                *(float2*)(vs + 2 * i)      = bf2f(KVp[p * 128 + 64 + i]);
                *(float2*)(vs + 64 + 2 * i) = bf2f(KVp[p * 128 + 96 + i]);
            }
            __syncwarp();
            // QK^T: lane owns column kk; k-column cached in regs.
            {
                float kreg[8];
                #pragma unroll
                for (int i = 0; i < 8; i++) kreg[i] = ks[i * 16 + kk];
                #pragma unroll
                for (int t2 = 0; t2 < 8; t2++) {
                    int j = hh + 2 * t2;
                    float s = 0.f;
                    #pragma unroll
                    for (int i = 0; i < 8; i++) s += qs[i * 16 + j] * kreg[i];
                    ds[kk * 17 + j] = s * 0.25f;
                }
            }
            __syncwarp();
            if (lane < 16) {   // softmax over kk for row j=lane (stride-17 reads)
                float mx = -1e30f;
                #pragma unroll
                for (int k2 = 0; k2 < 16; k2++) mx = fmaxf(mx, ds[k2 * 17 + lane]);
                float sm = 0.f;
                #pragma unroll
                for (int k2 = 0; k2 < 16; k2++) {
                    float ev = __expf(ds[k2 * 17 + lane] - mx);
                    ds[k2 * 17 + lane] = ev; sm += ev;
                }
                float inv = 1.f / sm;
                #pragma unroll
                for (int k2 = 0; k2 < 16; k2++) ds[k2 * 17 + lane] *= inv;
            }
            __syncwarp();
            // AV: lane owns output column j=kk; attn row cached in regs.
            {
                float dreg[16];
                #pragma unroll
                for (int k2 = 0; k2 < 16; k2++) dreg[k2] = ds[k2 * 17 + kk];
                #pragma unroll
                for (int t2 = 0; t2 < 4; t2++) {
                    int i = hh + 2 * t2;
                    float s = 0.f;
                    #pragma unroll
                    for (int k2 = 0; k2 < 16; k2++) s += dreg[k2] * vs[i * 16 + k2];
                    outs[g * 129 + i * 16 + kk] = s;
                }
            }
        }
    }
    __syncthreads();
    size_t base = ((size_t)b * 2048 + (size_t)n * 128) * 1936 + ihw0;
    for (int e = threadIdx.x; e < 4096; e += 256) {
        int ch = e >> 5, g = e & 31;
        if (ihw0 + g < NWIN) {
            size_t idx = base + (size_t)ch * 1936 + g;
            x1[idx] = x[idx] + outs[g * 129 + ch];
        }
    }
}

// ---------------------------------------------------------------------------
// K4: LN2 over x1 (read-only) -> tiled X1LN packed bf16 (uint4 stores).
// ---------------------------------------------------------------------------
__global__ void __launch_bounds__(256) k_merge2(
    const float* __restrict__ ln2w, const float* __restrict__ ln2b)
{
    __shared__ float red[264], red2[264], mu_s[32], rs_s[32];
    __shared__ float w2s[128], b2s[128];
    int p0 = blockIdx.x * 32;
    int b = p0 / HW, hw0 = p0 % HW;
    int px = threadIdx.x & 31, j = threadIdx.x >> 5;
    if (threadIdx.x < 128) { w2s[threadIdx.x] = ln2w[threadIdx.x]; b2s[threadIdx.x] = ln2b[threadIdx.x]; }
    const float* x1 = (const float*)(g_u + OFF_X1);
    size_t base = (size_t)b * PB + hw0 + px;
    float v[16];
    float s = 0.f, s2 = 0.f;
    #pragma unroll
    for (int i = 0; i < 16; i++) {
        int c = j * 16 + i;
        float val = x1[base + (size_t)c * HW];
        v[i] = val; s += val; s2 += val * val;
    }
    red[j * 33 + px] = s; red2[j * 33 + px] = s2;
    __syncthreads();
    if (threadIdx.x < 32) {
        float ss = 0.f, ss2 = 0.f;
        #pragma unroll
        for (int j2 = 0; j2 < 8; j2++) { ss += red[j2 * 33 + threadIdx.x]; ss2 += red2[j2 * 33 + threadIdx.x]; }
        float mu = ss * (1.f / 128.f);
        float var = ss2 * (1.f / 128.f) - mu * mu;
        mu_s[threadIdx.x] = mu; rs_s[threadIdx.x] = rsqrtf(var + 1e-5f);
    }
    __syncthreads();
    float mu = mu_s[px], rs = rs_s[px];
    int p = p0 + px;
    unsigned qv[8];
    #pragma unroll
    for (int ii = 0; ii < 8; ii++) {
        int c = j * 16 + 2 * ii;
        float a = (v[2 * ii] - mu) * rs * w2s[c] + b2s[c];
        float bb = (v[2 * ii + 1] - mu) * rs * w2s[c + 1] + b2s[c + 1];
        qv[ii] = pk(a, bb);
    }
    uint4* dst = (uint4*)(g_u + OFF_X1LN + (size_t)(p >> 7) * 8192 + (size_t)j * 1024 + (size_t)(p & 127) * 8);
    dst[0] = make_uint4(qv[0], qv[1], qv[2], qv[3]);
    dst[1] = make_uint4(qv[4], qv[5], qv[6], qv[7]);
}

// ---------------------------------------------------------------------------
// K6: depthwise 3x3 + exact GELU gate, packed f32x2 accumulation.
// ---------------------------------------------------------------------------
__device__ __forceinline__ void dw_row6(
    const unsigned* __restrict__ yin, int b, int h, int w0, int cp,
    unsigned* U, unsigned* V)
{
    #pragma unroll
    for (int dw = 0; dw < 6; dw++) { U[dw] = 0u; V[dw] = 0u; }
    if (h < 0 || h >= 176) return;
    #pragma unroll
    for (int dw = 0; dw < 6; dw++) {
        int ww = w0 - 1 + dw;
        if (ww < 0 || ww >= 176) continue;
        size_t base = ((size_t)b * HW + (size_t)h * 176 + ww) * 512;
        U[dw] = yin[base + cp];
        V[dw] = yin[base + 256 + cp];
    }
}

__global__ void __launch_bounds__(256) k_dwconv(const float* __restrict__ wdw)
{
    int cp = threadIdx.x;
    int blk = blockIdx.x;
    int wg = blk % 44;
    int hs = (blk / 44) % 8;
    int b  = blk / (44 * 8);
    int w0 = wg * 4;
    int h0 = hs * 22;
    const unsigned* yin = g_u + OFF_YIN;
    unsigned* yg = g_u + OFF_YG;
    int c0 = 2 * cp;
    unsigned long long wpA[9], wpB[9];
    #pragma unroll
    for (int t = 0; t < 9; t++) {
        wpA[t] = pkf2(__ldg(&wdw[c0 * 9 + t]), __ldg(&wdw[(c0 + 1) * 9 + t]));
        wpB[t] = pkf2(__ldg(&wdw[(512 + c0) * 9 + t]), __ldg(&wdw[(513 + c0) * 9 + t]));
    }
    unsigned U[3][6], V[3][6];
    dw_row6(yin, b, h0 - 1, w0, cp, U[0], V[0]);
    dw_row6(yin, b, h0,     w0, cp, U[1], V[1]);
    dw_row6(yin, b, h0 + 1, w0, cp, U[2], V[2]);

    for (int h = h0; h < h0 + 22; h++) {
        unsigned long long accA[4], accB[4];
        #pragma unroll
        for (int o = 0; o < 4; o++) { accA[o] = 0ULL; accB[o] = 0ULL; }
        #pragma unroll
        for (int dw = 0; dw < 6; dw++) {
            #pragma unroll
            for (int rr = 0; rr < 3; rr++) {
                unsigned long long ua = u2f2(U[rr][dw]);
                unsigned long long vb = u2f2(V[rr][dw]);
                #pragma unroll
                for (int o = 0; o < 4; o++) {
                    int cc = dw - o;
                    if (cc >= 0 && cc < 3) {
                        int tt = rr * 3 + cc;
                        accA[o] = ffma2(ua, wpA[tt], accA[o]);
                        accB[o] = ffma2(vb, wpB[tt], accB[o]);
                    }
                }
            }
        }
        #pragma unroll
        for (int o = 0; o < 4; o++) {
            float a0, a1, g0, g1;
            unf2(accA[o], a0, a1);
            unf2(accB[o], g0, g1);
            float e0 = 0.5f * a0 * (1.f + erff(a0 * 0.70710678118654752f));
            float e1 = 0.5f * a1 * (1.f + erff(a1 * 0.70710678118654752f));
            int p = b * HW + h * 176 + w0 + o;
            yg[(size_t)p * 256 + cp] = pk(e0 * g0, e1 * g1);
        }
        #pragma unroll
        for (int dw = 0; dw < 6; dw++) {
            U[0][dw] = U[1][dw]; U[1][dw] = U[2][dw];
            V[0][dw] = V[1][dw]; V[1][dw] = V[2][dw];
        }
        dw_row6(yin, b, h + 2, w0, cp, U[2], V[2]);
    }
}

// ---------------------------------------------------------------------------
extern "C" void kernel_launch(void* const* d_in, const int* in_sizes, int n_in,
                              void* d_out, int out_size)
{
    const float* x    = (const float*)d_in[0];
    const float* mask = (const float*)d_in[1];
    const float* edge = (const float*)d_in[2];
    const float* ln1w = (const float*)d_in[3];
    const float* ln1b = (const float*)d_in[4];
    const float* Wq   = (const float*)d_in[5];
    const float* Wk   = (const float*)d_in[6];
    const float* Wv   = (const float*)d_in[7];
    const float* ln2w = (const float*)d_in[8];
    const float* ln2b = (const float*)d_in[9];
    const float* w_in = (const float*)d_in[10];
    const float* w_dw = (const float*)d_in[11];
    const float* w_out= (const float*)d_in[12];
    float* outp = (float*)d_out;

    unsigned* G = nullptr;
    cudaGetSymbolAddress((void**)&G, g_u);

    // K0: weights -> tiled packed bf16x2
    k_wprep<<<(122880 + 255) / 256, 256>>>(Wq, Wk, Wv, w_in, w_out);

    // K1: LN1 + resize -> tiled Aq/Akv
    k_prep<<<PTOT / 32, 256>>>(x, mask, edge, ln1w, ln1b);

    // K2a: fused Q/K/V GEMM (one launch, grid.y = 3)
    k_mma_qkv<<<dim3(PTOT / 128, 3), 256>>>();

    // K3: channel attention + fused residual -> x1 (fp32 NCHW)
    k_attn<<<4 * 16 * 61, 256>>>(x);

    // K4: LN2(x1) -> tiled X1LN
    k_merge2<<<PTOT / 32, 256>>>(ln2w, ln2b);

    // K5: conv1x1 128->1024 -> y_in packed bf16 (evict-first C stores)
    k_mma_t<8, 0, 1, 1><<<dim3(PTOT / 128, 8), 256>>>(G + OFF_X1LN, G + OFF_WB + 24576, G + OFF_YIN, 1024, nullptr);

    // K6: depthwise 3x3 + GELU gate -> y_g packed rows (f32x2 math)
    k_dwconv<<<BATCH * 44 * 8, 256>>>(w_dw);

    // K7: conv1x1 512->128 + residual -> d_out (NCHW), A from rows
    k_mma_t<32, 1, 2, 0><<<dim3(PTOT / 128, 1), 256>>>(G + OFF_YG, G + OFF_WB + 90112, nullptr, 128, outp);
}